// round 2
// baseline (speedup 1.0000x reference)
#include <cuda_runtime.h>
#include <cuda_bf16.h>
#include <cstdint>

// ---------------- dims ----------------
#define B_  2
#define S_  1024
#define D_  1024
#define H_  16
#define DH_ 64
#define DFF_ 4096
#define L_  2
#define V_  32000
#define GS_ 128
#define NT_ (B_*S_)   // 2048 tokens

// ---------------- scratch (device globals; no allocations allowed) ----------------
__device__ float g_x[NT_*D_];
__device__ float g_h[NT_*D_];
__device__ float g_q[NT_*D_];
__device__ float g_k[NT_*D_];
__device__ float g_v[NT_*D_];
__device__ float g_o[NT_*D_];
__device__ float g_gate[NT_*DFF_];
__device__ float g_up[NT_*DFF_];
__device__ int   g_wfmt;   // 0=int8, 1=int32, 2=bf16

// ---------------- ternary weight format detector ----------------
__global__ void detect_fmt_kernel(const void* __restrict__ w)
{
    const unsigned* u = (const unsigned*)w;
    bool i32 = true, b16 = true;
    for (int i = 0; i < 64; i++) {
        unsigned x = u[i];
        if (!(x == 0u || x == 1u || x == 0xFFFFFFFFu)) i32 = false;
        unsigned lo = x & 0xFFFFu, hi = x >> 16;
        bool lok = (lo == 0u || lo == 0x3F80u || lo == 0xBF80u);
        bool hok = (hi == 0u || hi == 0x3F80u || hi == 0xBF80u);
        if (!(lok && hok)) b16 = false;
    }
    g_wfmt = i32 ? 1 : (b16 ? 2 : 0);
}

// decode 4 consecutive ternary weights at flat ELEMENT index idx
__device__ __forceinline__ void load_w4(const void* W, size_t idx, int fmt,
                                        float& w0, float& w1, float& w2, float& w3)
{
    if (fmt == 1) {
        int4 wv = *(const int4*)((const int*)W + idx);
        w0 = (float)wv.x; w1 = (float)wv.y; w2 = (float)wv.z; w3 = (float)wv.w;
    } else if (fmt == 2) {
        uint2 v = *(const uint2*)((const __nv_bfloat16*)W + idx);
        w0 = __bfloat162float(__ushort_as_bfloat16((unsigned short)( v.x        & 0xFFFFu)));
        w1 = __bfloat162float(__ushort_as_bfloat16((unsigned short)( v.x >> 16          )));
        w2 = __bfloat162float(__ushort_as_bfloat16((unsigned short)( v.y        & 0xFFFFu)));
        w3 = __bfloat162float(__ushort_as_bfloat16((unsigned short)( v.y >> 16          )));
    } else {
        int wv = *(const int*)((const int8_t*)W + idx);
        w0 = (float)(int8_t)( wv         & 0xff);
        w1 = (float)(int8_t)((wv >> 8 )  & 0xff);
        w2 = (float)(int8_t)((wv >> 16)  & 0xff);
        w3 = (float)(int8_t)( wv >> 24         );
    }
}

// ---------------- embedding gather + dequant ----------------
__global__ void embed_kernel(const int* __restrict__ ids,
                             const void* __restrict__ et,
                             const float* __restrict__ es,
                             float* __restrict__ X)
{
    int token = blockIdx.x;
    int id = ids[token];
    int d0 = threadIdx.x * 4;
    int fmt = g_wfmt;
    float w0, w1, w2, w3;
    load_w4(et, (size_t)id * D_ + d0, fmt, w0, w1, w2, w3);
    float s = es[id * (D_/GS_) + (d0 >> 7)];
    *(float4*)(X + (size_t)token * D_ + d0) = make_float4(w0*s, w1*s, w2*s, w3*s);
}

// ---------------- rmsnorm (row of 1024) ----------------
__global__ void rmsnorm_kernel(const float* __restrict__ X,
                               const float* __restrict__ w,
                               float* __restrict__ Y)
{
    int row = blockIdx.x;
    const float* x = X + (size_t)row * D_;
    float ss = 0.f;
    float vals[4];
#pragma unroll
    for (int j = 0; j < 4; j++) {
        vals[j] = x[threadIdx.x + j*256];
        ss += vals[j]*vals[j];
    }
    __shared__ float red[256];
    red[threadIdx.x] = ss;
    __syncthreads();
    for (int s = 128; s > 0; s >>= 1) {
        if (threadIdx.x < s) red[threadIdx.x] += red[threadIdx.x + s];
        __syncthreads();
    }
    float rs = rsqrtf(red[0] * (1.0f/(float)D_) + 1e-6f);
#pragma unroll
    for (int j = 0; j < 4; j++) {
        int d = threadIdx.x + j*256;
        Y[(size_t)row * D_ + d] = vals[j] * rs * w[d];
    }
}

// ---------------- fused-dequant ternary GEMM ----------------
// C[M,N] (=|+=) A[M,K] @ dequant(W[wbase + n*K + k])^T, scales Sc[n*K/GS + k/GS]
#define BK 64
#define PADS 68
template<int OP>
__global__ void __launch_bounds__(256)
gemm_tern(const float* __restrict__ A, const void* __restrict__ W, size_t wbase,
          const float* __restrict__ Sc, float* __restrict__ C,
          int M, int N, int K)
{
    __shared__ float As[BK][PADS];
    __shared__ float Bs[BK][PADS];
    int tid = threadIdx.x;
    int tx = tid & 15, ty = tid >> 4;
    int m0 = blockIdx.y * 64, n0 = blockIdx.x * 64;
    int ngroups = K >> 7;
    int fmt = g_wfmt;
    float acc[4][4] = {};
    for (int k0 = 0; k0 < K; k0 += BK) {
        int grp = k0 >> 7;
#pragma unroll
        for (int j = 0; j < 4; j++) {
            int i  = tid + j*256;
            int m  = i >> 4;
            int k4 = i & 15;
            float4 v = *(const float4*)(A + (size_t)(m0+m)*K + k0 + k4*4);
            As[k4*4+0][m] = v.x; As[k4*4+1][m] = v.y;
            As[k4*4+2][m] = v.z; As[k4*4+3][m] = v.w;
        }
#pragma unroll
        for (int j = 0; j < 4; j++) {
            int i  = tid + j*256;
            int n  = i >> 4;
            int k4 = i & 15;
            float s = Sc[(size_t)(n0+n)*ngroups + grp];
            float w0, w1, w2, w3;
            load_w4(W, wbase + (size_t)(n0+n)*K + k0 + k4*4, fmt, w0, w1, w2, w3);
            Bs[k4*4+0][n] = w0 * s;
            Bs[k4*4+1][n] = w1 * s;
            Bs[k4*4+2][n] = w2 * s;
            Bs[k4*4+3][n] = w3 * s;
        }
        __syncthreads();
#pragma unroll 8
        for (int k = 0; k < BK; k++) {
            float4 a = *(const float4*)&As[k][ty*4];
            float4 b = *(const float4*)&Bs[k][tx*4];
            float av[4] = {a.x, a.y, a.z, a.w};
            float bv[4] = {b.x, b.y, b.z, b.w};
#pragma unroll
            for (int i = 0; i < 4; i++)
#pragma unroll
                for (int jj = 0; jj < 4; jj++)
                    acc[i][jj] += av[i] * bv[jj];
        }
        __syncthreads();
    }
#pragma unroll
    for (int i = 0; i < 4; i++) {
        float* cp = C + (size_t)(m0 + ty*4 + i) * N + n0 + tx*4;
        float4 r = make_float4(acc[i][0], acc[i][1], acc[i][2], acc[i][3]);
        if (OP == 1) {
            float4 old = *(float4*)cp;
            r.x += old.x; r.y += old.y; r.z += old.z; r.w += old.w;
        }
        *(float4*)cp = r;
    }
}

// ---------------- flash attention + per-head residual ----------------
#define KT 64
__global__ void __launch_bounds__(128)
attn_kernel(const float* __restrict__ Q, const float* __restrict__ K,
            const float* __restrict__ V, const float* __restrict__ Hn,
            const float* __restrict__ alpha, float* __restrict__ O, int layer)
{
    int qt = blockIdx.x, hh = blockIdx.y, b = blockIdx.z;
    int tid = threadIdx.x;
    int qi = qt*128 + tid;
    __shared__ float Ks[KT][64];
    __shared__ float Vs[KT][64];

    const float* qrow = Q + ((size_t)(b*S_ + qi))*D_ + hh*DH_;
    float4 q[16];
#pragma unroll
    for (int j = 0; j < 16; j++) q[j] = *(const float4*)(qrow + j*4);

    float o[64];
#pragma unroll
    for (int d = 0; d < 64; d++) o[d] = 0.f;
    float m = -1e30f, l = 0.f;
    const float scale = 0.125f;

    int tmax = qt*128 + 127;
    for (int t0 = 0; t0 <= tmax; t0 += KT) {
        const float* kb = K + ((size_t)(b*S_ + t0))*D_ + hh*DH_;
        const float* vb = V + ((size_t)(b*S_ + t0))*D_ + hh*DH_;
#pragma unroll
        for (int j = 0; j < 8; j++) {
            int i = tid + j*128;
            int r = i >> 4, c4 = i & 15;
            *(float4*)&Ks[r][c4*4] = *(const float4*)(kb + (size_t)r*D_ + c4*4);
            *(float4*)&Vs[r][c4*4] = *(const float4*)(vb + (size_t)r*D_ + c4*4);
        }
        __syncthreads();
#pragma unroll 1
        for (int sub = 0; sub < 2; sub++) {
            float sc[32];
            float mloc = -1e30f;
#pragma unroll
            for (int i = 0; i < 32; i++) {
                int tt = sub*32 + i;
                int t  = t0 + tt;
                float s = 0.f;
#pragma unroll
                for (int j = 0; j < 16; j++) {
                    float4 kv = *(const float4*)&Ks[tt][j*4];
                    s += q[j].x*kv.x + q[j].y*kv.y + q[j].z*kv.z + q[j].w*kv.w;
                }
                s *= scale;
                sc[i] = (t <= qi) ? s : -1e30f;
                mloc = fmaxf(mloc, sc[i]);
            }
            if (mloc > m) {
                float corr = __expf(m - mloc);
                l *= corr;
#pragma unroll
                for (int d = 0; d < 64; d++) o[d] *= corr;
                m = mloc;
            }
#pragma unroll
            for (int i = 0; i < 32; i++) {
                float p = __expf(sc[i] - m);
                l += p;
                int tt = sub*32 + i;
#pragma unroll
                for (int d = 0; d < 64; d++) o[d] += p * Vs[tt][d];
            }
        }
        __syncthreads();
    }
    float a   = alpha[layer*H_ + hh];
    float inv = 1.f / l;
    float*       orow = O  + ((size_t)(b*S_ + qi))*D_ + hh*DH_;
    const float* hrow = Hn + ((size_t)(b*S_ + qi))*D_ + hh*DH_;
#pragma unroll
    for (int d = 0; d < 64; d++) orow[d] = o[d]*inv + a*hrow[d];
}

// ---------------- silu(gate) * up ----------------
__global__ void silu_mul(const float* __restrict__ G, const float* __restrict__ U,
                         float* __restrict__ Out, int n)
{
    int i = blockIdx.x * blockDim.x + threadIdx.x;
    if (i < n) {
        float g = G[i];
        Out[i] = g / (1.f + __expf(-g)) * U[i];
    }
}

// ---------------- launch ----------------
extern "C" void kernel_launch(void* const* d_in, const int* in_sizes, int n_in,
                              void* d_out, int out_size)
{
    const int*   ids    = (const int*)  d_in[0];
    const void*  emb_t  = d_in[1];
    const float* emb_s  = (const float*)d_in[2];
    const void*  qt_    = d_in[3];
    const float* qs_    = (const float*)d_in[4];
    const void*  kt_    = d_in[5];
    const float* ks_    = (const float*)d_in[6];
    const void*  vt_    = d_in[7];
    const float* vs_    = (const float*)d_in[8];
    const void*  ot_    = d_in[9];
    const float* os_    = (const float*)d_in[10];
    const void*  gatet  = d_in[11];
    const float* gates  = (const float*)d_in[12];
    const void*  upt    = d_in[13];
    const float* ups    = (const float*)d_in[14];
    const void*  downt  = d_in[15];
    const float* downs  = (const float*)d_in[16];
    const float* wa     = (const float*)d_in[17];
    const float* wm     = (const float*)d_in[18];
    const float* alpha  = (const float*)d_in[19];
    const float* wf     = (const float*)d_in[20];
    const void*  headt  = d_in[21];
    const float* heads  = (const float*)d_in[22];
    float* out = (float*)d_out;

    float *x, *h, *q, *k, *v, *o, *g, *u;
    cudaGetSymbolAddress((void**)&x, g_x);
    cudaGetSymbolAddress((void**)&h, g_h);
    cudaGetSymbolAddress((void**)&q, g_q);
    cudaGetSymbolAddress((void**)&k, g_k);
    cudaGetSymbolAddress((void**)&v, g_v);
    cudaGetSymbolAddress((void**)&o, g_o);
    cudaGetSymbolAddress((void**)&g, g_gate);
    cudaGetSymbolAddress((void**)&u, g_up);

    const size_t wDD  = (size_t)D_*D_;
    const size_t sDD  = (size_t)D_*D_/GS_;
    const size_t wFD  = (size_t)DFF_*D_;
    const size_t sFD  = (size_t)DFF_*D_/GS_;

    detect_fmt_kernel<<<1, 1>>>(emb_t);
    embed_kernel<<<NT_, 256>>>(ids, emb_t, emb_s, x);

    dim3 gp(D_/64,   NT_/64);
    dim3 gf(DFF_/64, NT_/64);
    dim3 gh(V_/64,   NT_/64);

    for (int l = 0; l < L_; l++) {
        rmsnorm_kernel<<<NT_, 256>>>(x, wa + (size_t)l*D_, h);
        gemm_tern<0><<<gp, 256>>>(h, qt_,   (size_t)l*wDD, qs_   + l*sDD, q, NT_, D_, D_);
        gemm_tern<0><<<gp, 256>>>(h, kt_,   (size_t)l*wDD, ks_   + l*sDD, k, NT_, D_, D_);
        gemm_tern<0><<<gp, 256>>>(h, vt_,   (size_t)l*wDD, vs_   + l*sDD, v, NT_, D_, D_);
        attn_kernel<<<dim3(S_/128, H_, B_), 128>>>(q, k, v, h, alpha, o, l);
        gemm_tern<1><<<gp, 256>>>(o, ot_,   (size_t)l*wDD, os_   + l*sDD, x, NT_, D_, D_);

        rmsnorm_kernel<<<NT_, 256>>>(x, wm + (size_t)l*D_, h);
        gemm_tern<0><<<gf, 256>>>(h, gatet, (size_t)l*wFD, gates + l*sFD, g, NT_, DFF_, D_);
        gemm_tern<0><<<gf, 256>>>(h, upt,   (size_t)l*wFD, ups   + l*sFD, u, NT_, DFF_, D_);
        silu_mul<<<(NT_*DFF_ + 255)/256, 256>>>(g, u, g, NT_*DFF_);
        gemm_tern<1><<<gp, 256>>>(g, downt, (size_t)l*wFD, downs + l*sFD, x, NT_, D_, DFF_);
    }
    rmsnorm_kernel<<<NT_, 256>>>(x, wf, h);
    gemm_tern<0><<<gh, 256>>>(h, headt, 0, heads, out, NT_, V_, D_);
}

// round 3
// speedup vs baseline: 3.3441x; 3.3441x over previous
#include <cuda_runtime.h>
#include <cuda_fp16.h>
#include <cuda_bf16.h>
#include <cstdint>

// ---------------- dims ----------------
#define B_  2
#define S_  1024
#define D_  1024
#define H_  16
#define DH_ 64
#define DFF_ 4096
#define L_  2
#define V_  32000
#define GS_ 128
#define NT_ (B_*S_)   // 2048 tokens

// ---------------- scratch ----------------
__device__ float g_x[NT_*D_];
__device__ float g_h[NT_*D_];
__device__ float g_q[NT_*D_];
__device__ float g_k[NT_*D_];
__device__ float g_v[NT_*D_];
__device__ float g_o[NT_*D_];
__device__ float g_gate[NT_*DFF_];
__device__ float g_up[NT_*DFF_];
__device__ int   g_wfmt;   // 0=int8, 1=int32, 2=bf16

// ---------------- weight format detector ----------------
__global__ void detect_fmt_kernel(const void* __restrict__ w)
{
    const unsigned* u = (const unsigned*)w;
    bool i32 = true, b16 = true;
    for (int i = 0; i < 64; i++) {
        unsigned x = u[i];
        if (!(x == 0u || x == 1u || x == 0xFFFFFFFFu)) i32 = false;
        unsigned lo = x & 0xFFFFu, hi = x >> 16;
        bool lok = (lo == 0u || lo == 0x3F80u || lo == 0xBF80u);
        bool hok = (hi == 0u || hi == 0x3F80u || hi == 0xBF80u);
        if (!(lok && hok)) b16 = false;
    }
    g_wfmt = i32 ? 1 : (b16 ? 2 : 0);
}

// decode 4 consecutive ternary weights at flat ELEMENT index idx
__device__ __forceinline__ void load_w4(const void* W, size_t idx, int fmt,
                                        float& w0, float& w1, float& w2, float& w3)
{
    if (fmt == 1) {
        int4 wv = *(const int4*)((const int*)W + idx);
        w0 = (float)wv.x; w1 = (float)wv.y; w2 = (float)wv.z; w3 = (float)wv.w;
    } else if (fmt == 2) {
        uint2 v = *(const uint2*)((const __nv_bfloat16*)W + idx);
        w0 = __bfloat162float(__ushort_as_bfloat16((unsigned short)( v.x        & 0xFFFFu)));
        w1 = __bfloat162float(__ushort_as_bfloat16((unsigned short)( v.x >> 16          )));
        w2 = __bfloat162float(__ushort_as_bfloat16((unsigned short)( v.y        & 0xFFFFu)));
        w3 = __bfloat162float(__ushort_as_bfloat16((unsigned short)( v.y >> 16          )));
    } else {
        int wv = *(const int*)((const int8_t*)W + idx);
        w0 = (float)(int8_t)( wv         & 0xff);
        w1 = (float)(int8_t)((wv >> 8 )  & 0xff);
        w2 = (float)(int8_t)((wv >> 16)  & 0xff);
        w3 = (float)(int8_t)( wv >> 24         );
    }
}

// ---------------- embedding gather + dequant ----------------
__global__ void embed_kernel(const int* __restrict__ ids,
                             const void* __restrict__ et,
                             const float* __restrict__ es,
                             float* __restrict__ X)
{
    int token = blockIdx.x;
    int id = ids[token];
    int d0 = threadIdx.x * 4;
    int fmt = g_wfmt;
    float w0, w1, w2, w3;
    load_w4(et, (size_t)id * D_ + d0, fmt, w0, w1, w2, w3);
    float s = es[id * (D_/GS_) + (d0 >> 7)];
    *(float4*)(X + (size_t)token * D_ + d0) = make_float4(w0*s, w1*s, w2*s, w3*s);
}

// ---------------- rmsnorm ----------------
__global__ void rmsnorm_kernel(const float* __restrict__ X,
                               const float* __restrict__ w,
                               float* __restrict__ Y)
{
    int row = blockIdx.x;
    const float* x = X + (size_t)row * D_;
    float ss = 0.f;
    float vals[4];
#pragma unroll
    for (int j = 0; j < 4; j++) {
        vals[j] = x[threadIdx.x + j*256];
        ss += vals[j]*vals[j];
    }
    __shared__ float red[256];
    red[threadIdx.x] = ss;
    __syncthreads();
    for (int s = 128; s > 0; s >>= 1) {
        if (threadIdx.x < s) red[threadIdx.x] += red[threadIdx.x + s];
        __syncthreads();
    }
    float rs = rsqrtf(red[0] * (1.0f/(float)D_) + 1e-6f);
#pragma unroll
    for (int j = 0; j < 4; j++) {
        int d = threadIdx.x + j*256;
        Y[(size_t)row * D_ + d] = vals[j] * rs * w[d];
    }
}

// ---------------- HMMA ternary GEMM ----------------
// C[M,N] (=|+=) A[M,K] @ dequant(W)^T
// fp16 operands: A converted at smem-store; W kept EXACT ternary in fp16.
// Group scale (GS=128) applied to fp32 group accumulators at group boundary.
#define BM 128
#define BN 128
#define BKG 32
#define LDA 40   // BKG + 8 halves padding

__device__ __forceinline__ void mma16816(float* c, const uint32_t* a, const uint32_t* b)
{
    asm volatile(
        "mma.sync.aligned.m16n8k16.row.col.f32.f16.f16.f32 "
        "{%0,%1,%2,%3}, {%4,%5,%6,%7}, {%8,%9}, {%0,%1,%2,%3};\n"
        : "+f"(c[0]), "+f"(c[1]), "+f"(c[2]), "+f"(c[3])
        : "r"(a[0]), "r"(a[1]), "r"(a[2]), "r"(a[3]), "r"(b[0]), "r"(b[1]));
}

template<int OP>
__global__ void __launch_bounds__(256, 1)
gemm_hmma(const float* __restrict__ A, const void* __restrict__ W, size_t wbase,
          const float* __restrict__ Sc, float* __restrict__ C,
          int M, int N, int K)
{
    __shared__ __half As[BM][LDA];
    __shared__ __half Bs[BN][LDA];
    __shared__ float  Ssc[BN];

    const int tid   = threadIdx.x;
    const int lane  = tid & 31;
    const int wid   = tid >> 5;
    const int warp_m = wid >> 2;        // 0..1 -> 64 rows each
    const int warp_n = wid & 3;         // 0..3 -> 32 cols each
    const int m0 = blockIdx.x * BM;
    const int n0 = blockIdx.y * BN;
    const int ngroups = K >> 7;
    const int fmt = g_wfmt;
    const int gid  = lane >> 2;         // 0..7
    const int tig  = lane & 3;          // 0..3

    float acc [4][4][4] = {};
    float accg[4][4][4] = {};

    uint2 aStage[4];
    uint2 bStage[4];

    const int iters = K / BKG;

    // ---- gmem load of one tile into staging regs ----
    auto load_tiles = [&](int k0) {
#pragma unroll
        for (int i = 0; i < 4; i++) {
            int p   = tid + i*256;          // 0..1023
            int row = p >> 3;
            int c4  = p & 7;
            float4 v = *(const float4*)(A + (size_t)(m0+row)*K + k0 + c4*4);
            __half2 h0 = __floats2half2_rn(v.x, v.y);
            __half2 h1 = __floats2half2_rn(v.z, v.w);
            aStage[i] = make_uint2(*(uint32_t*)&h0, *(uint32_t*)&h1);
        }
#pragma unroll
        for (int i = 0; i < 4; i++) {
            int p   = tid + i*256;
            int row = p >> 3;
            int c4  = p & 7;
            float w0, w1, w2, w3;
            load_w4(W, wbase + (size_t)(n0+row)*K + k0 + c4*4, fmt, w0, w1, w2, w3);
            __half2 h0 = __floats2half2_rn(w0, w1);
            __half2 h1 = __floats2half2_rn(w2, w3);
            bStage[i] = make_uint2(*(uint32_t*)&h0, *(uint32_t*)&h1);
        }
    };

    auto store_tiles = [&]() {
#pragma unroll
        for (int i = 0; i < 4; i++) {
            int p   = tid + i*256;
            int row = p >> 3;
            int c4  = p & 7;
            *(uint2*)&As[row][c4*4] = aStage[i];
        }
#pragma unroll
        for (int i = 0; i < 4; i++) {
            int p   = tid + i*256;
            int row = p >> 3;
            int c4  = p & 7;
            *(uint2*)&Bs[row][c4*4] = bStage[i];
        }
    };

    load_tiles(0);

    for (int it = 0; it < iters; it++) {
        int k0 = it * BKG;
        __syncthreads();                 // previous compute done
        store_tiles();
        if ((k0 & 127) == 0 && tid < BN) {
            Ssc[tid] = Sc[(size_t)(n0 + tid)*ngroups + (k0 >> 7)];
        }
        __syncthreads();

        if (it + 1 < iters) load_tiles(k0 + BKG);

        // ---- compute: 2 x k16 steps ----
#pragma unroll
        for (int kk = 0; kk < 2; kk++) {
            int ks = kk * 16;
            uint32_t af[4][4];
#pragma unroll
            for (int mt = 0; mt < 4; mt++) {
                int r = warp_m*64 + mt*16 + gid;
                int c = ks + 2*tig;
                af[mt][0] = *(const uint32_t*)&As[r  ][c  ];
                af[mt][1] = *(const uint32_t*)&As[r+8][c  ];
                af[mt][2] = *(const uint32_t*)&As[r  ][c+8];
                af[mt][3] = *(const uint32_t*)&As[r+8][c+8];
            }
            uint32_t bf[4][2];
#pragma unroll
            for (int nt = 0; nt < 4; nt++) {
                int n = warp_n*32 + nt*8 + gid;
                int c = ks + 2*tig;
                bf[nt][0] = *(const uint32_t*)&Bs[n][c  ];
                bf[nt][1] = *(const uint32_t*)&Bs[n][c+8];
            }
#pragma unroll
            for (int mt = 0; mt < 4; mt++)
#pragma unroll
                for (int nt = 0; nt < 4; nt++)
                    mma16816(accg[mt][nt], af[mt], bf[nt]);
        }

        // ---- group boundary: fold scale into master accumulators ----
        if (((k0 + BKG) & 127) == 0) {
#pragma unroll
            for (int nt = 0; nt < 4; nt++) {
                int nc = warp_n*32 + nt*8 + 2*tig;
                float s0 = Ssc[nc], s1 = Ssc[nc + 1];
#pragma unroll
                for (int mt = 0; mt < 4; mt++) {
                    acc[mt][nt][0] += s0 * accg[mt][nt][0];
                    acc[mt][nt][1] += s1 * accg[mt][nt][1];
                    acc[mt][nt][2] += s0 * accg[mt][nt][2];
                    acc[mt][nt][3] += s1 * accg[mt][nt][3];
                    accg[mt][nt][0] = 0.f; accg[mt][nt][1] = 0.f;
                    accg[mt][nt][2] = 0.f; accg[mt][nt][3] = 0.f;
                }
            }
        }
    }

    // ---- epilogue ----
#pragma unroll
    for (int mt = 0; mt < 4; mt++) {
        int r = m0 + warp_m*64 + mt*16 + gid;
#pragma unroll
        for (int nt = 0; nt < 4; nt++) {
            int c = n0 + warp_n*32 + nt*8 + 2*tig;
            float2 v0 = make_float2(acc[mt][nt][0], acc[mt][nt][1]);
            float2 v1 = make_float2(acc[mt][nt][2], acc[mt][nt][3]);
            float* p0 = C + (size_t)r*N + c;
            float* p1 = C + (size_t)(r+8)*N + c;
            if (OP == 1) {
                float2 o0 = *(float2*)p0, o1 = *(float2*)p1;
                v0.x += o0.x; v0.y += o0.y; v1.x += o1.x; v1.y += o1.y;
            }
            *(float2*)p0 = v0;
            *(float2*)p1 = v1;
        }
    }
}

// ---------------- flash attention + per-head residual ----------------
#define KT 64
__global__ void __launch_bounds__(128)
attn_kernel(const float* __restrict__ Q, const float* __restrict__ K,
            const float* __restrict__ V, const float* __restrict__ Hn,
            const float* __restrict__ alpha, float* __restrict__ O, int layer)
{
    int qt = blockIdx.x, hh = blockIdx.y, b = blockIdx.z;
    int tid = threadIdx.x;
    int qi = qt*128 + tid;
    __shared__ float Ks[KT][64];
    __shared__ float Vs[KT][64];

    const float* qrow = Q + ((size_t)(b*S_ + qi))*D_ + hh*DH_;
    float4 q[16];
#pragma unroll
    for (int j = 0; j < 16; j++) q[j] = *(const float4*)(qrow + j*4);

    float o[64];
#pragma unroll
    for (int d = 0; d < 64; d++) o[d] = 0.f;
    float m = -1e30f, l = 0.f;
    const float scale = 0.125f;

    int tmax = qt*128 + 127;
    for (int t0 = 0; t0 <= tmax; t0 += KT) {
        const float* kb = K + ((size_t)(b*S_ + t0))*D_ + hh*DH_;
        const float* vb = V + ((size_t)(b*S_ + t0))*D_ + hh*DH_;
#pragma unroll
        for (int j = 0; j < 8; j++) {
            int i = tid + j*128;
            int r = i >> 4, c4 = i & 15;
            *(float4*)&Ks[r][c4*4] = *(const float4*)(kb + (size_t)r*D_ + c4*4);
            *(float4*)&Vs[r][c4*4] = *(const float4*)(vb + (size_t)r*D_ + c4*4);
        }
        __syncthreads();
#pragma unroll 1
        for (int sub = 0; sub < 2; sub++) {
            float sc[32];
            float mloc = -1e30f;
#pragma unroll
            for (int i = 0; i < 32; i++) {
                int tt = sub*32 + i;
                int t  = t0 + tt;
                float s = 0.f;
#pragma unroll
                for (int j = 0; j < 16; j++) {
                    float4 kv = *(const float4*)&Ks[tt][j*4];
                    s += q[j].x*kv.x + q[j].y*kv.y + q[j].z*kv.z + q[j].w*kv.w;
                }
                s *= scale;
                sc[i] = (t <= qi) ? s : -1e30f;
                mloc = fmaxf(mloc, sc[i]);
            }
            if (mloc > m) {
                float corr = __expf(m - mloc);
                l *= corr;
#pragma unroll
                for (int d = 0; d < 64; d++) o[d] *= corr;
                m = mloc;
            }
#pragma unroll
            for (int i = 0; i < 32; i++) {
                float p = __expf(sc[i] - m);
                l += p;
                int tt = sub*32 + i;
#pragma unroll
                for (int d = 0; d < 64; d++) o[d] += p * Vs[tt][d];
            }
        }
        __syncthreads();
    }
    float a   = alpha[layer*H_ + hh];
    float inv = 1.f / l;
    float*       orow = O  + ((size_t)(b*S_ + qi))*D_ + hh*DH_;
    const float* hrow = Hn + ((size_t)(b*S_ + qi))*D_ + hh*DH_;
#pragma unroll
    for (int d = 0; d < 64; d++) orow[d] = o[d]*inv + a*hrow[d];
}

// ---------------- silu(gate) * up ----------------
__global__ void silu_mul(const float* __restrict__ G, const float* __restrict__ U,
                         float* __restrict__ Out, int n)
{
    int i = blockIdx.x * blockDim.x + threadIdx.x;
    if (i < n) {
        float g = G[i];
        Out[i] = g / (1.f + __expf(-g)) * U[i];
    }
}

// ---------------- launch ----------------
extern "C" void kernel_launch(void* const* d_in, const int* in_sizes, int n_in,
                              void* d_out, int out_size)
{
    const int*   ids    = (const int*)  d_in[0];
    const void*  emb_t  = d_in[1];
    const float* emb_s  = (const float*)d_in[2];
    const void*  qt_    = d_in[3];
    const float* qs_    = (const float*)d_in[4];
    const void*  kt_    = d_in[5];
    const float* ks_    = (const float*)d_in[6];
    const void*  vt_    = d_in[7];
    const float* vs_    = (const float*)d_in[8];
    const void*  ot_    = d_in[9];
    const float* os_    = (const float*)d_in[10];
    const void*  gatet  = d_in[11];
    const float* gates  = (const float*)d_in[12];
    const void*  upt    = d_in[13];
    const float* ups    = (const float*)d_in[14];
    const void*  downt  = d_in[15];
    const float* downs  = (const float*)d_in[16];
    const float* wa     = (const float*)d_in[17];
    const float* wm     = (const float*)d_in[18];
    const float* alpha  = (const float*)d_in[19];
    const float* wf     = (const float*)d_in[20];
    const void*  headt  = d_in[21];
    const float* heads  = (const float*)d_in[22];
    float* out = (float*)d_out;

    float *x, *h, *q, *k, *v, *o, *g, *u;
    cudaGetSymbolAddress((void**)&x, g_x);
    cudaGetSymbolAddress((void**)&h, g_h);
    cudaGetSymbolAddress((void**)&q, g_q);
    cudaGetSymbolAddress((void**)&k, g_k);
    cudaGetSymbolAddress((void**)&v, g_v);
    cudaGetSymbolAddress((void**)&o, g_o);
    cudaGetSymbolAddress((void**)&g, g_gate);
    cudaGetSymbolAddress((void**)&u, g_up);

    const size_t wDD  = (size_t)D_*D_;
    const size_t sDD  = (size_t)D_*D_/GS_;
    const size_t wFD  = (size_t)DFF_*D_;
    const size_t sFD  = (size_t)DFF_*D_/GS_;

    detect_fmt_kernel<<<1, 1>>>(emb_t);
    embed_kernel<<<NT_, 256>>>(ids, emb_t, emb_s, x);

    // grid: x = m (fast) so concurrent blocks share the same weight panel in L2
    dim3 gp(NT_/BM, D_/BN);     // 16 x 8
    dim3 gf(NT_/BM, DFF_/BN);   // 16 x 32
    dim3 gh(NT_/BM, V_/BN);     // 16 x 250

    for (int l = 0; l < L_; l++) {
        rmsnorm_kernel<<<NT_, 256>>>(x, wa + (size_t)l*D_, h);
        gemm_hmma<0><<<gp, 256>>>(h, qt_,   (size_t)l*wDD, qs_   + l*sDD, q, NT_, D_, D_);
        gemm_hmma<0><<<gp, 256>>>(h, kt_,   (size_t)l*wDD, ks_   + l*sDD, k, NT_, D_, D_);
        gemm_hmma<0><<<gp, 256>>>(h, vt_,   (size_t)l*wDD, vs_   + l*sDD, v, NT_, D_, D_);
        attn_kernel<<<dim3(S_/128, H_, B_), 128>>>(q, k, v, h, alpha, o, l);
        gemm_hmma<1><<<gp, 256>>>(o, ot_,   (size_t)l*wDD, os_   + l*sDD, x, NT_, D_, D_);

        rmsnorm_kernel<<<NT_, 256>>>(x, wm + (size_t)l*D_, h);
        gemm_hmma<0><<<gf, 256>>>(h, gatet, (size_t)l*wFD, gates + l*sFD, g, NT_, DFF_, D_);
        gemm_hmma<0><<<gf, 256>>>(h, upt,   (size_t)l*wFD, ups   + l*sFD, u, NT_, DFF_, D_);
        silu_mul<<<(NT_*DFF_ + 255)/256, 256>>>(g, u, g, NT_*DFF_);
        gemm_hmma<1><<<gp, 256>>>(g, downt, (size_t)l*wFD, downs + l*sFD, x, NT_, D_, DFF_);
    }
    rmsnorm_kernel<<<NT_, 256>>>(x, wf, h);
    gemm_hmma<0><<<gh, 256>>>(h, headt, 0, heads, out, NT_, V_, D_);
}

// round 5
// speedup vs baseline: 4.3970x; 1.3149x over previous
#include <cuda_runtime.h>
#include <cuda_fp16.h>
#include <cuda_bf16.h>
#include <cstdint>

// ---------------- dims ----------------
#define B_  2
#define S_  1024
#define D_  1024
#define H_  16
#define DH_ 64
#define DFF_ 4096
#define L_  2
#define V_  32000
#define GS_ 128
#define NT_ (B_*S_)   // 2048 tokens

// weight regions in g_wh (element offsets, halves)
#define OFF_QKV 0ull                       // 2 layers x 3M
#define OFF_O   (6ull*1024*1024)           // 2 x 1M
#define OFF_GU  (8ull*1024*1024)           // 2 x 8M (gate 4M + up 4M)
#define OFF_DN  (24ull*1024*1024)          // 2 x 4M
#define OFF_HD  (32ull*1024*1024)          // 32M
#define WH_TOT  (64ull*1024*1024)

// ---------------- scratch ----------------
__device__ __align__(16) float  g_x  [NT_*D_];
__device__ __align__(16) float  g_qkv[NT_*3*D_];
__device__ __align__(16) float  g_gu [NT_*2*DFF_];
__device__ __align__(16) __half g_hh [NT_*D_];
__device__ __align__(16) __half g_oh [NT_*D_];
__device__ __align__(16) __half g_gh [NT_*DFF_];
__device__ __align__(16) __half g_wh [WH_TOT];
__device__ float g_scqkv[2*3*8192];
__device__ float g_scgu [2*2*32768];
__device__ int   g_wfmt;   // 0=int8, 1=int32, 2=bf16

// ---------------- weight format detector ----------------
__global__ void detect_fmt_kernel(const void* __restrict__ w)
{
    const unsigned* u = (const unsigned*)w;
    bool i32 = true, b16 = true;
    for (int i = 0; i < 64; i++) {
        unsigned x = u[i];
        if (!(x == 0u || x == 1u || x == 0xFFFFFFFFu)) i32 = false;
        unsigned lo = x & 0xFFFFu, hi = x >> 16;
        bool lok = (lo == 0u || lo == 0x3F80u || lo == 0xBF80u);
        bool hok = (hi == 0u || hi == 0x3F80u || hi == 0xBF80u);
        if (!(lok && hok)) b16 = false;
    }
    g_wfmt = i32 ? 1 : (b16 ? 2 : 0);
}

__device__ __forceinline__ void load_w4(const void* W, size_t idx, int fmt,
                                        float& w0, float& w1, float& w2, float& w3)
{
    if (fmt == 1) {
        int4 wv = *(const int4*)((const int*)W + idx);
        w0 = (float)wv.x; w1 = (float)wv.y; w2 = (float)wv.z; w3 = (float)wv.w;
    } else if (fmt == 2) {
        uint2 v = *(const uint2*)((const __nv_bfloat16*)W + idx);
        w0 = __bfloat162float(__ushort_as_bfloat16((unsigned short)( v.x        & 0xFFFFu)));
        w1 = __bfloat162float(__ushort_as_bfloat16((unsigned short)( v.x >> 16          )));
        w2 = __bfloat162float(__ushort_as_bfloat16((unsigned short)( v.y        & 0xFFFFu)));
        w3 = __bfloat162float(__ushort_as_bfloat16((unsigned short)( v.y >> 16          )));
    } else {
        int wv = *(const int*)((const int8_t*)W + idx);
        w0 = (float)(int8_t)( wv         & 0xff);
        w1 = (float)(int8_t)((wv >> 8 )  & 0xff);
        w2 = (float)(int8_t)((wv >> 16)  & 0xff);
        w3 = (float)(int8_t)( wv >> 24         );
    }
}

// ---------------- weight conversion: ternary -> exact fp16 ----------------
__global__ void convert_w(const void* __restrict__ W, size_t src_base,
                          __half* __restrict__ dst, int nelems)
{
    int i = (blockIdx.x * 256 + threadIdx.x) * 4;
    if (i >= nelems) return;
    int fmt = g_wfmt;
    float w0, w1, w2, w3;
    load_w4(W, src_base + i, fmt, w0, w1, w2, w3);
    __half2 h0 = __floats2half2_rn(w0, w1);
    __half2 h1 = __floats2half2_rn(w2, w3);
    *(uint2*)&dst[i] = make_uint2(*(uint32_t*)&h0, *(uint32_t*)&h1);
}

// ---------------- embedding gather + dequant ----------------
__global__ void embed_kernel(const int* __restrict__ ids,
                             const void* __restrict__ et,
                             const float* __restrict__ es,
                             float* __restrict__ X)
{
    int token = blockIdx.x;
    int id = ids[token];
    int d0 = threadIdx.x * 4;
    int fmt = g_wfmt;
    float w0, w1, w2, w3;
    load_w4(et, (size_t)id * D_ + d0, fmt, w0, w1, w2, w3);
    float s = es[id * (D_/GS_) + (d0 >> 7)];
    *(float4*)(X + (size_t)token * D_ + d0) = make_float4(w0*s, w1*s, w2*s, w3*s);
}

// ---------------- rmsnorm (f32 in, f16 out) ----------------
__global__ void rmsnorm_kernel(const float* __restrict__ X,
                               const float* __restrict__ w,
                               __half* __restrict__ Y)
{
    int row = blockIdx.x;
    const float* x = X + (size_t)row * D_;
    float ss = 0.f;
    float vals[4];
#pragma unroll
    for (int j = 0; j < 4; j++) {
        vals[j] = x[threadIdx.x + j*256];
        ss += vals[j]*vals[j];
    }
    __shared__ float red[256];
    red[threadIdx.x] = ss;
    __syncthreads();
    for (int s = 128; s > 0; s >>= 1) {
        if (threadIdx.x < s) red[threadIdx.x] += red[threadIdx.x + s];
        __syncthreads();
    }
    float rs = rsqrtf(red[0] * (1.0f/(float)D_) + 1e-6f);
#pragma unroll
    for (int j = 0; j < 4; j++) {
        int d = threadIdx.x + j*256;
        Y[(size_t)row * D_ + d] = __float2half(vals[j] * rs * w[d]);
    }
}

// ---------------- async HMMA GEMM ----------------
// C[M,N] (=|+=) A[M,K](f16) @ W[N,K](f16,exact ternary)^T with group scales.
#define BM 128
#define BN 128
#define BKT 32

__device__ __forceinline__ void mma16816(float* c, const uint32_t* a, const uint32_t* b)
{
    asm volatile(
        "mma.sync.aligned.m16n8k16.row.col.f32.f16.f16.f32 "
        "{%0,%1,%2,%3}, {%4,%5,%6,%7}, {%8,%9}, {%0,%1,%2,%3};\n"
        : "+f"(c[0]), "+f"(c[1]), "+f"(c[2]), "+f"(c[3])
        : "r"(a[0]), "r"(a[1]), "r"(a[2]), "r"(a[3]), "r"(b[0]), "r"(b[1]));
}
__device__ __forceinline__ void cp16(uint32_t dst, const void* src)
{
    asm volatile("cp.async.cg.shared.global [%0], [%1], 16;\n" :: "r"(dst), "l"(src));
}
__device__ __forceinline__ void ldm_x4(uint32_t& r0, uint32_t& r1, uint32_t& r2, uint32_t& r3,
                                       uint32_t addr)
{
    asm volatile("ldmatrix.sync.aligned.m8n8.x4.shared.b16 {%0,%1,%2,%3}, [%4];"
                 : "=r"(r0), "=r"(r1), "=r"(r2), "=r"(r3) : "r"(addr));
}

template<int OP>
__global__ void __launch_bounds__(256, 2)
gemm_async(const __half* __restrict__ A, const __half* __restrict__ Wh,
           const float* __restrict__ Sc, float* __restrict__ C,
           int M, int N, int K)
{
    __shared__ __align__(16) __half As[2][BM*BKT];
    __shared__ __align__(16) __half Bs[2][BN*BKT];
    __shared__ float Ssc[32][128];          // [group][n]

    const int tid  = threadIdx.x;
    const int lane = tid & 31;
    const int wid  = tid >> 5;
    const int warp_m = wid >> 2;            // 0..1 (64 rows)
    const int warp_n = wid & 3;             // 0..3 (32 cols)
    const int m0 = blockIdx.x * BM;
    const int n0 = blockIdx.y * BN;
    const int ngroups = K >> 7;
    const int gid = lane >> 2, tig = lane & 3;

    const uint32_t sa = (uint32_t)__cvta_generic_to_shared(&As[0][0]);
    const uint32_t sb = (uint32_t)__cvta_generic_to_shared(&Bs[0][0]);

    // per-lane ldmatrix address components
    const int a_row  = lane & 15;                 // + rbase
    const int a_sel  = lane >> 4;                 // k chunk half
    const int a_xor  = ((lane & 15) >> 1) & 3;
    const int b_roff = ((lane >> 4) << 3) + (lane & 7);
    const int b_sel  = (lane >> 3) & 1;
    const int b_xor  = (b_roff >> 1) & 3;

    float acc[4][4][4] = {};
    float s_cur[4][2];

    // preload ALL group scales for this n-panel
    for (int i = tid; i < 128 * ngroups; i += 256) {
        int n = i & 127, g = i >> 7;
        Ssc[g][n] = Sc[(size_t)(n0 + n) * ngroups + g];
    }

    const int iters = K / BKT;

    auto issue = [&](int stage, int k0) {
        uint32_t ab = sa + stage * (BM*BKT*2);
        uint32_t bb = sb + stage * (BN*BKT*2);
#pragma unroll
        for (int j = 0; j < 2; j++) {
            int c = tid + j*256;                 // 0..511
            int row = c >> 2, ch = c & 3;
            int pch = ch ^ ((row >> 1) & 3);
            cp16(ab + row*64 + pch*16, A  + (size_t)(m0+row)*K + k0 + ch*8);
        }
#pragma unroll
        for (int j = 0; j < 2; j++) {
            int c = tid + j*256;
            int row = c >> 2, ch = c & 3;
            int pch = ch ^ ((row >> 1) & 3);
            cp16(bb + row*64 + pch*16, Wh + (size_t)(n0+row)*K + k0 + ch*8);
        }
        asm volatile("cp.async.commit_group;\n");
    };

    issue(0, 0);

    for (int it = 0; it < iters; it++) {
        if (it + 1 < iters) {
            issue((it + 1) & 1, (it + 1) * BKT);
            asm volatile("cp.async.wait_group 1;\n");
        } else {
            asm volatile("cp.async.wait_group 0;\n");
        }
        __syncthreads();

        // group boundary: rescale accumulators (acc in units of 1/s_cur)
        if ((it & 3) == 0) {
            int g = it >> 2;
#pragma unroll
            for (int nt = 0; nt < 4; nt++) {
                int nc = warp_n*32 + nt*8 + 2*tig;
                float s0 = Ssc[g][nc], s1 = Ssc[g][nc + 1];
                if (it) {
                    float r0 = __fdividef(s_cur[nt][0], s0);
                    float r1 = __fdividef(s_cur[nt][1], s1);
#pragma unroll
                    for (int mt = 0; mt < 4; mt++) {
                        acc[mt][nt][0] *= r0; acc[mt][nt][1] *= r1;
                        acc[mt][nt][2] *= r0; acc[mt][nt][3] *= r1;
                    }
                }
                s_cur[nt][0] = s0; s_cur[nt][1] = s1;
            }
        }

        const int stage = it & 1;
        const uint32_t ab = sa + stage * (BM*BKT*2);
        const uint32_t bb = sb + stage * (BN*BKT*2);
#pragma unroll
        for (int kk = 0; kk < 2; kk++) {
            uint32_t af[4][4];
#pragma unroll
            for (int mt = 0; mt < 4; mt++) {
                int row = warp_m*64 + mt*16 + a_row;
                int pch = (kk*2 + a_sel) ^ a_xor;
                ldm_x4(af[mt][0], af[mt][1], af[mt][2], af[mt][3],
                       ab + row*64 + pch*16);
            }
            uint32_t bf[4][2];
#pragma unroll
            for (int p = 0; p < 2; p++) {
                int row = warp_n*32 + p*16 + b_roff;
                int pch = (kk*2 + b_sel) ^ b_xor;
                uint32_t r0, r1, r2, r3;
                ldm_x4(r0, r1, r2, r3, bb + row*64 + pch*16);
                bf[2*p  ][0] = r0; bf[2*p  ][1] = r1;
                bf[2*p+1][0] = r2; bf[2*p+1][1] = r3;
            }
#pragma unroll
            for (int mt = 0; mt < 4; mt++)
#pragma unroll
                for (int nt = 0; nt < 4; nt++)
                    mma16816(acc[mt][nt], af[mt], bf[nt]);
        }
        __syncthreads();
    }

    // epilogue: apply last group scale, write/accumulate f32
#pragma unroll
    for (int mt = 0; mt < 4; mt++) {
        int r = m0 + warp_m*64 + mt*16 + gid;
#pragma unroll
        for (int nt = 0; nt < 4; nt++) {
            int c = n0 + warp_n*32 + nt*8 + 2*tig;
            float s0 = s_cur[nt][0], s1 = s_cur[nt][1];
            float2 v0 = make_float2(acc[mt][nt][0]*s0, acc[mt][nt][1]*s1);
            float2 v1 = make_float2(acc[mt][nt][2]*s0, acc[mt][nt][3]*s1);
            float* p0 = C + (size_t)r*N + c;
            float* p1 = C + (size_t)(r+8)*N + c;
            if (OP == 1) {
                float2 o0 = *(float2*)p0, o1 = *(float2*)p1;
                v0.x += o0.x; v0.y += o0.y; v1.x += o1.x; v1.y += o1.y;
            }
            *(float2*)p0 = v0;
            *(float2*)p1 = v1;
        }
    }
}

// ---------------- flash attention + per-head residual ----------------
// QKV fused buffer [NT, 3072]: q at col 0, k at 1024, v at 2048.
#define KT 64
#define QKVS (3*D_)
__global__ void __launch_bounds__(128)
attn_kernel(const float* __restrict__ QKV, const __half* __restrict__ Hn,
            const float* __restrict__ alpha, __half* __restrict__ O, int layer)
{
    int qt = blockIdx.x, hh = blockIdx.y, b = blockIdx.z;
    int tid = threadIdx.x;
    int qi = qt*128 + tid;
    __shared__ float Ks[KT][64];
    __shared__ float Vs[KT][64];

    const float* qrow = QKV + ((size_t)(b*S_ + qi))*QKVS + hh*DH_;
    float4 q[16];
#pragma unroll
    for (int j = 0; j < 16; j++) q[j] = *(const float4*)(qrow + j*4);

    float o[64];
#pragma unroll
    for (int d = 0; d < 64; d++) o[d] = 0.f;
    float m = -1e30f, l = 0.f;
    const float scale = 0.125f;

    int tmax = qt*128 + 127;
    for (int t0 = 0; t0 <= tmax; t0 += KT) {
        const float* kb = QKV + ((size_t)(b*S_ + t0))*QKVS + D_   + hh*DH_;
        const float* vb = QKV + ((size_t)(b*S_ + t0))*QKVS + 2*D_ + hh*DH_;
#pragma unroll
        for (int j = 0; j < 8; j++) {
            int i = tid + j*128;
            int r = i >> 4, c4 = i & 15;
            *(float4*)&Ks[r][c4*4] = *(const float4*)(kb + (size_t)r*QKVS + c4*4);
            *(float4*)&Vs[r][c4*4] = *(const float4*)(vb + (size_t)r*QKVS + c4*4);
        }
        __syncthreads();
#pragma unroll 1
        for (int sub = 0; sub < 2; sub++) {
            float sc[32];
            float mloc = -1e30f;
#pragma unroll
            for (int i = 0; i < 32; i++) {
                int tt = sub*32 + i;
                int t  = t0 + tt;
                float s = 0.f;
#pragma unroll
                for (int j = 0; j < 16; j++) {
                    float4 kv = *(const float4*)&Ks[tt][j*4];
                    s += q[j].x*kv.x + q[j].y*kv.y + q[j].z*kv.z + q[j].w*kv.w;
                }
                s *= scale;
                sc[i] = (t <= qi) ? s : -1e30f;
                mloc = fmaxf(mloc, sc[i]);
            }
            if (mloc > m) {
                float corr = __expf(m - mloc);
                l *= corr;
#pragma unroll
                for (int d = 0; d < 64; d++) o[d] *= corr;
                m = mloc;
            }
#pragma unroll
            for (int i = 0; i < 32; i++) {
                float p = __expf(sc[i] - m);
                l += p;
                int tt = sub*32 + i;
#pragma unroll
                for (int d = 0; d < 64; d++) o[d] += p * Vs[tt][d];
            }
        }
        __syncthreads();
    }
    float a   = alpha[layer*H_ + hh];
    float inv = 1.f / l;
    __half*       orow = O  + ((size_t)(b*S_ + qi))*D_ + hh*DH_;
    const __half* hrow = Hn + ((size_t)(b*S_ + qi))*D_ + hh*DH_;
#pragma unroll
    for (int d = 0; d < 64; d++)
        orow[d] = __float2half(o[d]*inv + a*__half2float(hrow[d]));
}

// ---------------- silu(gate) * up (from fused gu buffer) ----------------
__global__ void silu_mul(const float* __restrict__ GU, __half* __restrict__ Out)
{
    int i = blockIdx.x * blockDim.x + threadIdx.x;   // over NT*DFF
    int row = i >> 12, col = i & 4095;
    float g = GU[(size_t)row*(2*DFF_) + col];
    float u = GU[(size_t)row*(2*DFF_) + DFF_ + col];
    Out[i] = __float2half(g / (1.f + __expf(-g)) * u);
}

// ---------------- launch ----------------
extern "C" void kernel_launch(void* const* d_in, const int* in_sizes, int n_in,
                              void* d_out, int out_size)
{
    const int*   ids    = (const int*)  d_in[0];
    const void*  emb_t  = d_in[1];
    const float* emb_s  = (const float*)d_in[2];
    const void*  qt_    = d_in[3];
    const float* qs_    = (const float*)d_in[4];
    const void*  kt_    = d_in[5];
    const float* ks_    = (const float*)d_in[6];
    const void*  vt_    = d_in[7];
    const float* vs_    = (const float*)d_in[8];
    const void*  ot_    = d_in[9];
    const float* os_    = (const float*)d_in[10];
    const void*  gatet  = d_in[11];
    const float* gates  = (const float*)d_in[12];
    const void*  upt    = d_in[13];
    const float* ups    = (const float*)d_in[14];
    const void*  downt  = d_in[15];
    const float* downs  = (const float*)d_in[16];
    const float* wa     = (const float*)d_in[17];
    const float* wm     = (const float*)d_in[18];
    const float* alpha  = (const float*)d_in[19];
    const float* wf     = (const float*)d_in[20];
    const void*  headt  = d_in[21];
    const float* heads  = (const float*)d_in[22];
    float* out = (float*)d_out;

    float *x, *qkv, *gu, *scqkv, *scgu;
    __half *hh, *oh, *gh, *wh;
    cudaGetSymbolAddress((void**)&x,    g_x);
    cudaGetSymbolAddress((void**)&qkv,  g_qkv);
    cudaGetSymbolAddress((void**)&gu,   g_gu);
    cudaGetSymbolAddress((void**)&hh,   g_hh);
    cudaGetSymbolAddress((void**)&oh,   g_oh);
    cudaGetSymbolAddress((void**)&gh,   g_gh);
    cudaGetSymbolAddress((void**)&wh,   g_wh);
    cudaGetSymbolAddress((void**)&scqkv,g_scqkv);
    cudaGetSymbolAddress((void**)&scgu, g_scgu);

    const size_t wDD = (size_t)D_*D_;          // 1M
    const size_t wFD = (size_t)DFF_*D_;        // 4M
    const size_t sDD = wDD/GS_;                // 8192
    const size_t sFD = wFD/GS_;                // 32768

    detect_fmt_kernel<<<1, 1>>>(emb_t);

    // ---- weight conversion (exact ternary fp16) ----
    const int CB = 256;
    for (int l = 0; l < L_; l++) {
        convert_w<<<wDD/1024, CB>>>(qt_,   l*wDD, wh + OFF_QKV + l*3*wDD,          (int)wDD);
        convert_w<<<wDD/1024, CB>>>(kt_,   l*wDD, wh + OFF_QKV + l*3*wDD + wDD,    (int)wDD);
        convert_w<<<wDD/1024, CB>>>(vt_,   l*wDD, wh + OFF_QKV + l*3*wDD + 2*wDD,  (int)wDD);
        convert_w<<<wDD/1024, CB>>>(ot_,   l*wDD, wh + OFF_O   + l*wDD,            (int)wDD);
        convert_w<<<wFD/1024, CB>>>(gatet, l*wFD, wh + OFF_GU  + l*2*wFD,          (int)wFD);
        convert_w<<<wFD/1024, CB>>>(upt,   l*wFD, wh + OFF_GU  + l*2*wFD + wFD,    (int)wFD);
        convert_w<<<wFD/1024, CB>>>(downt, l*wFD, wh + OFF_DN  + l*wFD,            (int)wFD);
        // concatenated scales
        cudaMemcpyAsync(scqkv + l*3*sDD,         qs_   + l*sDD, sDD*4, cudaMemcpyDeviceToDevice, 0);
        cudaMemcpyAsync(scqkv + l*3*sDD +   sDD, ks_   + l*sDD, sDD*4, cudaMemcpyDeviceToDevice, 0);
        cudaMemcpyAsync(scqkv + l*3*sDD + 2*sDD, vs_   + l*sDD, sDD*4, cudaMemcpyDeviceToDevice, 0);
        cudaMemcpyAsync(scgu  + l*2*sFD,         gates + l*sFD, sFD*4, cudaMemcpyDeviceToDevice, 0);
        cudaMemcpyAsync(scgu  + l*2*sFD +   sFD, ups   + l*sFD, sFD*4, cudaMemcpyDeviceToDevice, 0);
    }
    convert_w<<<(V_*(size_t)D_)/1024, CB>>>(headt, 0, wh + OFF_HD, V_*D_);

    embed_kernel<<<NT_, 256>>>(ids, emb_t, emb_s, x);

    dim3 g_qkvp(NT_/BM, 3*D_/BN);    // 16 x 24
    dim3 g_op  (NT_/BM, D_/BN);      // 16 x 8
    dim3 g_gup (NT_/BM, 2*DFF_/BN);  // 16 x 64
    dim3 g_dn  (NT_/BM, D_/BN);      // 16 x 8
    dim3 g_hd  (NT_/BM, V_/BN);      // 16 x 250

    for (int l = 0; l < L_; l++) {
        rmsnorm_kernel<<<NT_, 256>>>(x, wa + (size_t)l*D_, hh);
        gemm_async<0><<<g_qkvp, 256>>>(hh, wh + OFF_QKV + l*3*wDD, scqkv + l*3*sDD,
                                       qkv, NT_, 3*D_, D_);
        attn_kernel<<<dim3(S_/128, H_, B_), 128>>>(qkv, hh, alpha, oh, l);
        gemm_async<1><<<g_op, 256>>>(oh, wh + OFF_O + l*wDD, os_ + l*sDD,
                                     x, NT_, D_, D_);

        rmsnorm_kernel<<<NT_, 256>>>(x, wm + (size_t)l*D_, hh);
        gemm_async<0><<<g_gup, 256>>>(hh, wh + OFF_GU + l*2*wFD, scgu + l*2*sFD,
                                      gu, NT_, 2*DFF_, D_);
        silu_mul<<<(NT_*DFF_)/256, 256>>>(gu, gh);
        gemm_async<1><<<g_dn, 256>>>(gh, wh + OFF_DN + l*wFD, downs + l*sFD,
                                     x, NT_, D_, DFF_);
    }
    rmsnorm_kernel<<<NT_, 256>>>(x, wf, hh);
    gemm_async<0><<<g_hd, 256>>>(hh, wh + OFF_HD, heads, out, NT_, V_, D_);
}

// round 7
// speedup vs baseline: 9.5187x; 2.1648x over previous
#include <cuda_runtime.h>
#include <cuda_fp16.h>
#include <cuda_bf16.h>
#include <cstdint>

// ---------------- dims ----------------
#define B_  2
#define S_  1024
#define D_  1024
#define H_  16
#define DH_ 64
#define DFF_ 4096
#define L_  2
#define V_  32000
#define GS_ 128
#define NT_ (B_*S_)   // 2048 tokens

// weight regions in g_wh (element offsets, halves)
#define OFF_QKV 0ull                       // 2 layers x 3M
#define OFF_O   (6ull*1024*1024)           // 2 x 1M
#define OFF_GU  (8ull*1024*1024)           // 2 x 8M (gate 4M + up 4M)
#define OFF_DN  (24ull*1024*1024)          // 2 x 4M
#define OFF_HD  (32ull*1024*1024)          // 32M
#define WH_TOT  (64ull*1024*1024)

// ---------------- scratch ----------------
__device__ __align__(16) float  g_x  [NT_*D_];
__device__ __align__(16) float  g_qkv[NT_*3*D_];
__device__ __align__(16) float  g_gu [NT_*2*DFF_];
__device__ __align__(16) __half g_hh [NT_*D_];
__device__ __align__(16) __half g_oh [NT_*D_];
__device__ __align__(16) __half g_gh [NT_*DFF_];
__device__ __align__(16) __half g_wh [WH_TOT];
__device__ float g_scqkv[2*3*8192];
__device__ float g_scgu [2*2*32768];
__device__ int   g_wfmt;   // 0=int8, 1=int32, 2=bf16

// ---------------- weight format detector ----------------
__global__ void detect_fmt_kernel(const void* __restrict__ w)
{
    const unsigned* u = (const unsigned*)w;
    bool i32 = true, b16 = true;
    for (int i = 0; i < 64; i++) {
        unsigned x = u[i];
        if (!(x == 0u || x == 1u || x == 0xFFFFFFFFu)) i32 = false;
        unsigned lo = x & 0xFFFFu, hi = x >> 16;
        bool lok = (lo == 0u || lo == 0x3F80u || lo == 0xBF80u);
        bool hok = (hi == 0u || hi == 0x3F80u || hi == 0xBF80u);
        if (!(lok && hok)) b16 = false;
    }
    g_wfmt = i32 ? 1 : (b16 ? 2 : 0);
}

__device__ __forceinline__ void load_w4(const void* W, size_t idx, int fmt,
                                        float& w0, float& w1, float& w2, float& w3)
{
    if (fmt == 1) {
        int4 wv = *(const int4*)((const int*)W + idx);
        w0 = (float)wv.x; w1 = (float)wv.y; w2 = (float)wv.z; w3 = (float)wv.w;
    } else if (fmt == 2) {
        uint2 v = *(const uint2*)((const __nv_bfloat16*)W + idx);
        w0 = __bfloat162float(__ushort_as_bfloat16((unsigned short)( v.x        & 0xFFFFu)));
        w1 = __bfloat162float(__ushort_as_bfloat16((unsigned short)( v.x >> 16          )));
        w2 = __bfloat162float(__ushort_as_bfloat16((unsigned short)( v.y        & 0xFFFFu)));
        w3 = __bfloat162float(__ushort_as_bfloat16((unsigned short)( v.y >> 16          )));
    } else {
        int wv = *(const int*)((const int8_t*)W + idx);
        w0 = (float)(int8_t)( wv         & 0xff);
        w1 = (float)(int8_t)((wv >> 8 )  & 0xff);
        w2 = (float)(int8_t)((wv >> 16)  & 0xff);
        w3 = (float)(int8_t)( wv >> 24         );
    }
}

// ---------------- weight conversion: ternary -> exact fp16 ----------------
__global__ void convert_w(const void* __restrict__ W, size_t src_base,
                          __half* __restrict__ dst, int nelems)
{
    int i = (blockIdx.x * 256 + threadIdx.x) * 4;
    if (i >= nelems) return;
    int fmt = g_wfmt;
    float w0, w1, w2, w3;
    load_w4(W, src_base + i, fmt, w0, w1, w2, w3);
    __half2 h0 = __floats2half2_rn(w0, w1);
    __half2 h1 = __floats2half2_rn(w2, w3);
    *(uint2*)&dst[i] = make_uint2(*(uint32_t*)&h0, *(uint32_t*)&h1);
}

// ---------------- embedding gather + dequant ----------------
__global__ void embed_kernel(const int* __restrict__ ids,
                             const void* __restrict__ et,
                             const float* __restrict__ es,
                             float* __restrict__ X)
{
    int token = blockIdx.x;
    int id = ids[token];
    int d0 = threadIdx.x * 4;
    int fmt = g_wfmt;
    float w0, w1, w2, w3;
    load_w4(et, (size_t)id * D_ + d0, fmt, w0, w1, w2, w3);
    float s = es[id * (D_/GS_) + (d0 >> 7)];
    *(float4*)(X + (size_t)token * D_ + d0) = make_float4(w0*s, w1*s, w2*s, w3*s);
}

// ---------------- rmsnorm (f32 in, f16 out) ----------------
__global__ void rmsnorm_kernel(const float* __restrict__ X,
                               const float* __restrict__ w,
                               __half* __restrict__ Y)
{
    int row = blockIdx.x;
    const float* x = X + (size_t)row * D_;
    float ss = 0.f;
    float vals[4];
#pragma unroll
    for (int j = 0; j < 4; j++) {
        vals[j] = x[threadIdx.x + j*256];
        ss += vals[j]*vals[j];
    }
    __shared__ float red[256];
    red[threadIdx.x] = ss;
    __syncthreads();
    for (int s = 128; s > 0; s >>= 1) {
        if (threadIdx.x < s) red[threadIdx.x] += red[threadIdx.x + s];
        __syncthreads();
    }
    float rs = rsqrtf(red[0] * (1.0f/(float)D_) + 1e-6f);
#pragma unroll
    for (int j = 0; j < 4; j++) {
        int d = threadIdx.x + j*256;
        Y[(size_t)row * D_ + d] = __float2half(vals[j] * rs * w[d]);
    }
}

// ---------------- mma helpers ----------------
__device__ __forceinline__ void mma16816(float* c, const uint32_t* a, const uint32_t* b)
{
    asm volatile(
        "mma.sync.aligned.m16n8k16.row.col.f32.f16.f16.f32 "
        "{%0,%1,%2,%3}, {%4,%5,%6,%7}, {%8,%9}, {%0,%1,%2,%3};\n"
        : "+f"(c[0]), "+f"(c[1]), "+f"(c[2]), "+f"(c[3])
        : "r"(a[0]), "r"(a[1]), "r"(a[2]), "r"(a[3]), "r"(b[0]), "r"(b[1]));
}
__device__ __forceinline__ void cp16(uint32_t dst, const void* src)
{
    asm volatile("cp.async.cg.shared.global [%0], [%1], 16;\n" :: "r"(dst), "l"(src));
}
__device__ __forceinline__ void ldm_x4(uint32_t& r0, uint32_t& r1, uint32_t& r2, uint32_t& r3,
                                       uint32_t addr)
{
    asm volatile("ldmatrix.sync.aligned.m8n8.x4.shared.b16 {%0,%1,%2,%3}, [%4];"
                 : "=r"(r0), "=r"(r1), "=r"(r2), "=r"(r3) : "r"(addr));
}
__device__ __forceinline__ uint32_t smem_u32(const void* p) {
    return (uint32_t)__cvta_generic_to_shared(p);
}

// ---------------- async HMMA GEMM (unchanged from round 5 - proven) ----------------
#define BM 128
#define BN 128
#define BKT 32

template<int OP>
__global__ void __launch_bounds__(256, 2)
gemm_async(const __half* __restrict__ A, const __half* __restrict__ Wh,
           const float* __restrict__ Sc, float* __restrict__ C,
           int M, int N, int K)
{
    __shared__ __align__(16) __half As[2][BM*BKT];
    __shared__ __align__(16) __half Bs[2][BN*BKT];
    __shared__ float Ssc[32][128];          // [group][n]

    const int tid  = threadIdx.x;
    const int lane = tid & 31;
    const int wid  = tid >> 5;
    const int warp_m = wid >> 2;            // 0..1 (64 rows)
    const int warp_n = wid & 3;             // 0..3 (32 cols)
    const int m0 = blockIdx.x * BM;
    const int n0 = blockIdx.y * BN;
    const int ngroups = K >> 7;
    const int gid = lane >> 2, tig = lane & 3;

    const uint32_t sa = smem_u32(&As[0][0]);
    const uint32_t sb = smem_u32(&Bs[0][0]);

    const int a_row  = lane & 15;
    const int a_sel  = lane >> 4;
    const int a_xor  = ((lane & 15) >> 1) & 3;
    const int b_roff = ((lane >> 4) << 3) + (lane & 7);
    const int b_sel  = (lane >> 3) & 1;
    const int b_xor  = (b_roff >> 1) & 3;

    float acc[4][4][4] = {};
    float s_cur[4][2];

    for (int i = tid; i < 128 * ngroups; i += 256) {
        int n = i & 127, g = i >> 7;
        Ssc[g][n] = Sc[(size_t)(n0 + n) * ngroups + g];
    }

    const int iters = K / BKT;

    auto issue = [&](int stage, int k0) {
        uint32_t ab = sa + stage * (BM*BKT*2);
        uint32_t bb = sb + stage * (BN*BKT*2);
#pragma unroll
        for (int j = 0; j < 2; j++) {
            int c = tid + j*256;
            int row = c >> 2, ch = c & 3;
            int pch = ch ^ ((row >> 1) & 3);
            cp16(ab + row*64 + pch*16, A  + (size_t)(m0+row)*K + k0 + ch*8);
        }
#pragma unroll
        for (int j = 0; j < 2; j++) {
            int c = tid + j*256;
            int row = c >> 2, ch = c & 3;
            int pch = ch ^ ((row >> 1) & 3);
            cp16(bb + row*64 + pch*16, Wh + (size_t)(n0+row)*K + k0 + ch*8);
        }
        asm volatile("cp.async.commit_group;\n");
    };

    issue(0, 0);

    for (int it = 0; it < iters; it++) {
        if (it + 1 < iters) {
            issue((it + 1) & 1, (it + 1) * BKT);
            asm volatile("cp.async.wait_group 1;\n");
        } else {
            asm volatile("cp.async.wait_group 0;\n");
        }
        __syncthreads();

        if ((it & 3) == 0) {
            int g = it >> 2;
#pragma unroll
            for (int nt = 0; nt < 4; nt++) {
                int nc = warp_n*32 + nt*8 + 2*tig;
                float s0 = Ssc[g][nc], s1 = Ssc[g][nc + 1];
                if (it) {
                    float r0 = __fdividef(s_cur[nt][0], s0);
                    float r1 = __fdividef(s_cur[nt][1], s1);
#pragma unroll
                    for (int mt = 0; mt < 4; mt++) {
                        acc[mt][nt][0] *= r0; acc[mt][nt][1] *= r1;
                        acc[mt][nt][2] *= r0; acc[mt][nt][3] *= r1;
                    }
                }
                s_cur[nt][0] = s0; s_cur[nt][1] = s1;
            }
        }

        const int stage = it & 1;
        const uint32_t ab = sa + stage * (BM*BKT*2);
        const uint32_t bb = sb + stage * (BN*BKT*2);
#pragma unroll
        for (int kk = 0; kk < 2; kk++) {
            uint32_t af[4][4];
#pragma unroll
            for (int mt = 0; mt < 4; mt++) {
                int row = warp_m*64 + mt*16 + a_row;
                int pch = (kk*2 + a_sel) ^ a_xor;
                ldm_x4(af[mt][0], af[mt][1], af[mt][2], af[mt][3],
                       ab + row*64 + pch*16);
            }
            uint32_t bf[4][2];
#pragma unroll
            for (int p = 0; p < 2; p++) {
                int row = warp_n*32 + p*16 + b_roff;
                int pch = (kk*2 + b_sel) ^ b_xor;
                uint32_t r0, r1, r2, r3;
                ldm_x4(r0, r1, r2, r3, bb + row*64 + pch*16);
                bf[2*p  ][0] = r0; bf[2*p  ][1] = r1;
                bf[2*p+1][0] = r2; bf[2*p+1][1] = r3;
            }
#pragma unroll
            for (int mt = 0; mt < 4; mt++)
#pragma unroll
                for (int nt = 0; nt < 4; nt++)
                    mma16816(acc[mt][nt], af[mt], bf[nt]);
        }
        __syncthreads();
    }

#pragma unroll
    for (int mt = 0; mt < 4; mt++) {
        int r = m0 + warp_m*64 + mt*16 + gid;
#pragma unroll
        for (int nt = 0; nt < 4; nt++) {
            int c = n0 + warp_n*32 + nt*8 + 2*tig;
            float s0 = s_cur[nt][0], s1 = s_cur[nt][1];
            float2 v0 = make_float2(acc[mt][nt][0]*s0, acc[mt][nt][1]*s1);
            float2 v1 = make_float2(acc[mt][nt][2]*s0, acc[mt][nt][3]*s1);
            float* p0 = C + (size_t)r*N + c;
            float* p1 = C + (size_t)(r+8)*N + c;
            if (OP == 1) {
                float2 o0 = *(float2*)p0, o1 = *(float2*)p1;
                v0.x += o0.x; v0.y += o0.y; v1.x += o1.x; v1.y += o1.y;
            }
            *(float2*)p0 = v0;
            *(float2*)p1 = v1;
        }
    }
}

// ---------------- mma flash attention + per-head residual ----------------
// QKV fused f32 [NT, 3072]; block = 64 q rows x (b,h); 4 warps x 16 rows.
#define AQ 64
#define QKVS (3*D_)
__global__ void __launch_bounds__(128)
attn_mma(const float* __restrict__ QKV, const __half* __restrict__ Hn,
         const float* __restrict__ alpha, __half* __restrict__ O, int layer)
{
    __shared__ __align__(16) __half Qs[AQ][72];
    __shared__ __align__(16) __half Ks[AQ][72];
    __shared__ __align__(16) __half Vt[AQ][72];   // Vt[dh][key]

    const int tid = threadIdx.x, lane = tid & 31, wid = tid >> 5;
    const int qt = blockIdx.x, hh = blockIdx.y, b = blockIdx.z;
    const int q0 = qt * AQ;

    // load Q tile (64 rows x 64 dims), f32 -> f16
    for (int t = tid; t < AQ*16; t += 128) {
        int r = t >> 4, c4 = t & 15;
        float4 v = *(const float4*)(QKV + ((size_t)(b*S_ + q0 + r))*QKVS + hh*DH_ + c4*4);
        __half2 h0 = __floats2half2_rn(v.x, v.y);
        __half2 h1 = __floats2half2_rn(v.z, v.w);
        *(uint2*)&Qs[r][c4*4] = make_uint2(*(uint32_t*)&h0, *(uint32_t*)&h1);
    }
    __syncthreads();

    // Q fragments: warp owns rows wid*16..+15
    uint32_t qf[4][4];
    {
        int rr = wid*16 + (lane & 15);
        int cc = ((lane >> 4) & 1) * 8;
#pragma unroll
        for (int ks = 0; ks < 4; ks++)
            ldm_x4(qf[ks][0], qf[ks][1], qf[ks][2], qf[ks][3],
                   smem_u32(&Qs[rr][ks*16 + cc]));
    }

    float o[8][4] = {};
    float m_lo = -1e30f, m_hi = -1e30f, l_lo = 0.f, l_hi = 0.f;
    const int qi_lo = q0 + wid*16 + (lane >> 2);
    const int qi_hi = qi_lo + 8;
    const int row_off = ((lane >> 4) << 3) + (lane & 7);
    const int col_sel = ((lane >> 3) & 1) * 8;

    for (int t0 = 0; t0 < q0 + AQ; t0 += AQ) {
        __syncthreads();
        // load K (row-major) and V (transposed) tiles, f32 -> f16
        for (int t = tid; t < AQ*16; t += 128) {
            int r = t >> 4, c4 = t & 15;
            const float* base = QKV + ((size_t)(b*S_ + t0 + r))*QKVS + hh*DH_ + c4*4;
            float4 kv = *(const float4*)(base + D_);
            __half2 h0 = __floats2half2_rn(kv.x, kv.y);
            __half2 h1 = __floats2half2_rn(kv.z, kv.w);
            *(uint2*)&Ks[r][c4*4] = make_uint2(*(uint32_t*)&h0, *(uint32_t*)&h1);
            float4 vv = *(const float4*)(base + 2*D_);
            Vt[c4*4+0][r] = __float2half(vv.x);
            Vt[c4*4+1][r] = __float2half(vv.y);
            Vt[c4*4+2][r] = __float2half(vv.z);
            Vt[c4*4+3][r] = __float2half(vv.w);
        }
        __syncthreads();

        // ---- S = Q K^T (fp32 accum) ----
        float sacc[8][4] = {};
#pragma unroll
        for (int ks = 0; ks < 4; ks++) {
#pragma unroll
            for (int jp = 0; jp < 4; jp++) {
                uint32_t r0, r1, r2, r3;
                ldm_x4(r0, r1, r2, r3, smem_u32(&Ks[jp*16 + row_off][ks*16 + col_sel]));
                uint32_t bA[2] = {r0, r1};
                uint32_t bB[2] = {r2, r3};
                mma16816(sacc[2*jp  ], qf[ks], bA);
                mma16816(sacc[2*jp+1], qf[ks], bB);
            }
        }

        // ---- scale + causal mask + online softmax ----
        float mx_lo = -1e30f, mx_hi = -1e30f;
#pragma unroll
        for (int j = 0; j < 8; j++) {
            int kb = t0 + j*8 + 2*(lane & 3);
            sacc[j][0] = (kb     <= qi_lo) ? sacc[j][0]*0.125f : -1e30f;
            sacc[j][1] = (kb + 1 <= qi_lo) ? sacc[j][1]*0.125f : -1e30f;
            sacc[j][2] = (kb     <= qi_hi) ? sacc[j][2]*0.125f : -1e30f;
            sacc[j][3] = (kb + 1 <= qi_hi) ? sacc[j][3]*0.125f : -1e30f;
            mx_lo = fmaxf(mx_lo, fmaxf(sacc[j][0], sacc[j][1]));
            mx_hi = fmaxf(mx_hi, fmaxf(sacc[j][2], sacc[j][3]));
        }
        mx_lo = fmaxf(mx_lo, __shfl_xor_sync(0xffffffffu, mx_lo, 1));
        mx_lo = fmaxf(mx_lo, __shfl_xor_sync(0xffffffffu, mx_lo, 2));
        mx_hi = fmaxf(mx_hi, __shfl_xor_sync(0xffffffffu, mx_hi, 1));
        mx_hi = fmaxf(mx_hi, __shfl_xor_sync(0xffffffffu, mx_hi, 2));

        float mn_lo = fmaxf(m_lo, mx_lo), mn_hi = fmaxf(m_hi, mx_hi);
        float c_lo = __expf(m_lo - mn_lo), c_hi = __expf(m_hi - mn_hi);
        m_lo = mn_lo; m_hi = mn_hi;
        l_lo *= c_lo; l_hi *= c_hi;
#pragma unroll
        for (int j = 0; j < 8; j++) {
            o[j][0] *= c_lo; o[j][1] *= c_lo;
            o[j][2] *= c_hi; o[j][3] *= c_hi;
        }

        uint32_t pa[8], pb[8];
        float ps_lo = 0.f, ps_hi = 0.f;
#pragma unroll
        for (int j = 0; j < 8; j++) {
            float e0 = __expf(sacc[j][0] - mn_lo);
            float e1 = __expf(sacc[j][1] - mn_lo);
            float e2 = __expf(sacc[j][2] - mn_hi);
            float e3 = __expf(sacc[j][3] - mn_hi);
            ps_lo += e0 + e1; ps_hi += e2 + e3;
            __half2 hl = __floats2half2_rn(e0, e1);
            __half2 hb = __floats2half2_rn(e2, e3);
            pa[j] = *(uint32_t*)&hl;
            pb[j] = *(uint32_t*)&hb;
        }
        ps_lo += __shfl_xor_sync(0xffffffffu, ps_lo, 1);
        ps_lo += __shfl_xor_sync(0xffffffffu, ps_lo, 2);
        ps_hi += __shfl_xor_sync(0xffffffffu, ps_hi, 1);
        ps_hi += __shfl_xor_sync(0xffffffffu, ps_hi, 2);
        l_lo += ps_lo; l_hi += ps_hi;

        // ---- O += P V ----
#pragma unroll
        for (int kk = 0; kk < 4; kk++) {
            uint32_t af[4] = {pa[2*kk], pb[2*kk], pa[2*kk+1], pb[2*kk+1]};
#pragma unroll
            for (int dp = 0; dp < 4; dp++) {
                uint32_t r0, r1, r2, r3;
                ldm_x4(r0, r1, r2, r3, smem_u32(&Vt[dp*16 + row_off][kk*16 + col_sel]));
                uint32_t bA[2] = {r0, r1};
                uint32_t bB[2] = {r2, r3};
                mma16816(o[2*dp  ], af, bA);
                mma16816(o[2*dp+1], af, bB);
            }
        }
    }

    // ---- epilogue: 1/l, per-head alpha residual, write f16 ----
    float i_lo = 1.f / l_lo, i_hi = 1.f / l_hi;
    float a = alpha[layer*H_ + hh];
    size_t tok_lo = (size_t)(b*S_ + qi_lo);
#pragma unroll
    for (int j = 0; j < 8; j++) {
        int col = hh*DH_ + j*8 + 2*(lane & 3);
        float2 fh_lo = __half22float2(*(const __half2*)(Hn + tok_lo*D_ + col));
        float2 fh_hi = __half22float2(*(const __half2*)(Hn + (tok_lo+8)*D_ + col));
        __half2 o_lo = __floats2half2_rn(o[j][0]*i_lo + a*fh_lo.x,
                                         o[j][1]*i_lo + a*fh_lo.y);
        __half2 o_hi = __floats2half2_rn(o[j][2]*i_hi + a*fh_hi.x,
                                         o[j][3]*i_hi + a*fh_hi.y);
        *(__half2*)(O + tok_lo*D_ + col)     = o_lo;
        *(__half2*)(O + (tok_lo+8)*D_ + col) = o_hi;
    }
}

// ---------------- silu(gate) * up ----------------
__global__ void silu_mul(const float* __restrict__ GU, __half* __restrict__ Out)
{
    int i = blockIdx.x * blockDim.x + threadIdx.x;
    int row = i >> 12, col = i & 4095;
    float g = GU[(size_t)row*(2*DFF_) + col];
    float u = GU[(size_t)row*(2*DFF_) + DFF_ + col];
    Out[i] = __float2half(g / (1.f + __expf(-g)) * u);
}

// ---------------- launch ----------------
extern "C" void kernel_launch(void* const* d_in, const int* in_sizes, int n_in,
                              void* d_out, int out_size)
{
    const int*   ids    = (const int*)  d_in[0];
    const void*  emb_t  = d_in[1];
    const float* emb_s  = (const float*)d_in[2];
    const void*  qt_    = d_in[3];
    const float* qs_    = (const float*)d_in[4];
    const void*  kt_    = d_in[5];
    const float* ks_    = (const float*)d_in[6];
    const void*  vt_    = d_in[7];
    const float* vs_    = (const float*)d_in[8];
    const void*  ot_    = d_in[9];
    const float* os_    = (const float*)d_in[10];
    const void*  gatet  = d_in[11];
    const float* gates  = (const float*)d_in[12];
    const void*  upt    = d_in[13];
    const float* ups    = (const float*)d_in[14];
    const void*  downt  = d_in[15];
    const float* downs  = (const float*)d_in[16];
    const float* wa     = (const float*)d_in[17];
    const float* wm     = (const float*)d_in[18];
    const float* alpha  = (const float*)d_in[19];
    const float* wf     = (const float*)d_in[20];
    const void*  headt  = d_in[21];
    const float* heads  = (const float*)d_in[22];
    float* out = (float*)d_out;

    float *x, *qkv, *gu, *scqkv, *scgu;
    __half *hh, *oh, *gh, *wh;
    cudaGetSymbolAddress((void**)&x,    g_x);
    cudaGetSymbolAddress((void**)&qkv,  g_qkv);
    cudaGetSymbolAddress((void**)&gu,   g_gu);
    cudaGetSymbolAddress((void**)&hh,   g_hh);
    cudaGetSymbolAddress((void**)&oh,   g_oh);
    cudaGetSymbolAddress((void**)&gh,   g_gh);
    cudaGetSymbolAddress((void**)&wh,   g_wh);
    cudaGetSymbolAddress((void**)&scqkv,g_scqkv);
    cudaGetSymbolAddress((void**)&scgu, g_scgu);

    const size_t wDD = (size_t)D_*D_;          // 1M
    const size_t wFD = (size_t)DFF_*D_;        // 4M
    const size_t sDD = wDD/GS_;                // 8192
    const size_t sFD = wFD/GS_;                // 32768

    detect_fmt_kernel<<<1, 1>>>(emb_t);

    const int CB = 256;
    for (int l = 0; l < L_; l++) {
        convert_w<<<wDD/1024, CB>>>(qt_,   l*wDD, wh + OFF_QKV + l*3*wDD,          (int)wDD);
        convert_w<<<wDD/1024, CB>>>(kt_,   l*wDD, wh + OFF_QKV + l*3*wDD + wDD,    (int)wDD);
        convert_w<<<wDD/1024, CB>>>(vt_,   l*wDD, wh + OFF_QKV + l*3*wDD + 2*wDD,  (int)wDD);
        convert_w<<<wDD/1024, CB>>>(ot_,   l*wDD, wh + OFF_O   + l*wDD,            (int)wDD);
        convert_w<<<wFD/1024, CB>>>(gatet, l*wFD, wh + OFF_GU  + l*2*wFD,          (int)wFD);
        convert_w<<<wFD/1024, CB>>>(upt,   l*wFD, wh + OFF_GU  + l*2*wFD + wFD,    (int)wFD);
        convert_w<<<wFD/1024, CB>>>(downt, l*wFD, wh + OFF_DN  + l*wFD,            (int)wFD);
        cudaMemcpyAsync(scqkv + l*3*sDD,         qs_   + l*sDD, sDD*4, cudaMemcpyDeviceToDevice, 0);
        cudaMemcpyAsync(scqkv + l*3*sDD +   sDD, ks_   + l*sDD, sDD*4, cudaMemcpyDeviceToDevice, 0);
        cudaMemcpyAsync(scqkv + l*3*sDD + 2*sDD, vs_   + l*sDD, sDD*4, cudaMemcpyDeviceToDevice, 0);
        cudaMemcpyAsync(scgu  + l*2*sFD,         gates + l*sFD, sFD*4, cudaMemcpyDeviceToDevice, 0);
        cudaMemcpyAsync(scgu  + l*2*sFD +   sFD, ups   + l*sFD, sFD*4, cudaMemcpyDeviceToDevice, 0);
    }
    convert_w<<<(V_*(size_t)D_)/1024, CB>>>(headt, 0, wh + OFF_HD, V_*D_);

    embed_kernel<<<NT_, 256>>>(ids, emb_t, emb_s, x);

    dim3 g_qkvp(NT_/BM, 3*D_/BN);    // 16 x 24
    dim3 g_op  (NT_/BM, D_/BN);      // 16 x 8
    dim3 g_gup (NT_/BM, 2*DFF_/BN);  // 16 x 64
    dim3 g_hd  (NT_/BM, V_/BN);      // 16 x 250

    for (int l = 0; l < L_; l++) {
        rmsnorm_kernel<<<NT_, 256>>>(x, wa + (size_t)l*D_, hh);
        gemm_async<0><<<g_qkvp, 256>>>(hh, wh + OFF_QKV + l*3*wDD, scqkv + l*3*sDD,
                                       qkv, NT_, 3*D_, D_);
        attn_mma<<<dim3(S_/AQ, H_, B_), 128>>>(qkv, hh, alpha, oh, l);
        gemm_async<1><<<g_op, 256>>>(oh, wh + OFF_O + l*wDD, os_ + l*sDD,
                                     x, NT_, D_, D_);

        rmsnorm_kernel<<<NT_, 256>>>(x, wm + (size_t)l*D_, hh);
        gemm_async<0><<<g_gup, 256>>>(hh, wh + OFF_GU + l*2*wFD, scgu + l*2*sFD,
                                      gu, NT_, 2*DFF_, D_);
        silu_mul<<<(NT_*DFF_)/256, 256>>>(gu, gh);
        gemm_async<1><<<g_op, 256>>>(gh, wh + OFF_DN + l*wFD, downs + l*sFD,
                                     x, NT_, D_, DFF_);
    }
    rmsnorm_kernel<<<NT_, 256>>>(x, wf, hh);
    gemm_async<0><<<g_hd, 256>>>(hh, wh + OFF_HD, heads, out, NT_, V_, D_);
}

// round 9
// speedup vs baseline: 9.9069x; 1.0408x over previous
#include <cuda_runtime.h>
#include <cuda_fp16.h>
#include <cuda_bf16.h>
#include <cstdint>

// ---------------- dims ----------------
#define B_  2
#define S_  1024
#define D_  1024
#define H_  16
#define DH_ 64
#define DFF_ 4096
#define L_  2
#define V_  32000
#define GS_ 128
#define NT_ (B_*S_)   // 2048 tokens

// weight regions in g_wh (element offsets, halves)
#define OFF_QKV 0ull                       // 2 layers x 3M
#define OFF_O   (6ull*1024*1024)           // 2 x 1M
#define OFF_GU  (8ull*1024*1024)           // 2 x 8M (interleaved gate/up)
#define OFF_DN  (24ull*1024*1024)          // 2 x 4M
#define OFF_HD  (32ull*1024*1024)          // 32M
#define WH_TOT  (64ull*1024*1024)

// ---------------- scratch ----------------
__device__ __align__(16) float  g_x  [NT_*D_];
__device__ __align__(16) __half g_qkv[NT_*3*D_];
__device__ __align__(16) __half g_hh [NT_*D_];
__device__ __align__(16) __half g_oh [NT_*D_];
__device__ __align__(16) __half g_gh [NT_*DFF_];
__device__ __align__(16) __half g_wh [WH_TOT];
__device__ float g_scqkv[2*3*8192];
__device__ float g_scgu [2*2*32768];       // interleaved gate/up scales
__device__ int   g_wfmt;   // 0=int8, 1=int32, 2=bf16

// ---------------- weight format detector ----------------
__global__ void detect_fmt_kernel(const void* __restrict__ w)
{
    const unsigned* u = (const unsigned*)w;
    bool i32 = true, b16 = true;
    for (int i = 0; i < 64; i++) {
        unsigned x = u[i];
        if (!(x == 0u || x == 1u || x == 0xFFFFFFFFu)) i32 = false;
        unsigned lo = x & 0xFFFFu, hi = x >> 16;
        bool lok = (lo == 0u || lo == 0x3F80u || lo == 0xBF80u);
        bool hok = (hi == 0u || hi == 0x3F80u || hi == 0xBF80u);
        if (!(lok && hok)) b16 = false;
    }
    g_wfmt = i32 ? 1 : (b16 ? 2 : 0);
}

__device__ __forceinline__ void load_w4(const void* W, size_t idx, int fmt,
                                        float& w0, float& w1, float& w2, float& w3)
{
    if (fmt == 1) {
        int4 wv = *(const int4*)((const int*)W + idx);
        w0 = (float)wv.x; w1 = (float)wv.y; w2 = (float)wv.z; w3 = (float)wv.w;
    } else if (fmt == 2) {
        uint2 v = *(const uint2*)((const __nv_bfloat16*)W + idx);
        w0 = __bfloat162float(__ushort_as_bfloat16((unsigned short)( v.x        & 0xFFFFu)));
        w1 = __bfloat162float(__ushort_as_bfloat16((unsigned short)( v.x >> 16          )));
        w2 = __bfloat162float(__ushort_as_bfloat16((unsigned short)( v.y        & 0xFFFFu)));
        w3 = __bfloat162float(__ushort_as_bfloat16((unsigned short)( v.y >> 16          )));
    } else {
        int wv = *(const int*)((const int8_t*)W + idx);
        w0 = (float)(int8_t)( wv         & 0xff);
        w1 = (float)(int8_t)((wv >> 8 )  & 0xff);
        w2 = (float)(int8_t)((wv >> 16)  & 0xff);
        w3 = (float)(int8_t)( wv >> 24         );
    }
}

// ---------------- weight conversion: ternary -> exact fp16 ----------------
__global__ void convert_w(const void* __restrict__ W, size_t src_base,
                          __half* __restrict__ dst, int nelems)
{
    int i = (blockIdx.x * 256 + threadIdx.x) * 4;
    if (i >= nelems) return;
    int fmt = g_wfmt;
    float w0, w1, w2, w3;
    load_w4(W, src_base + i, fmt, w0, w1, w2, w3);
    __half2 h0 = __floats2half2_rn(w0, w1);
    __half2 h1 = __floats2half2_rn(w2, w3);
    *(uint2*)&dst[i] = make_uint2(*(uint32_t*)&h0, *(uint32_t*)&h1);
}

// interleaved variant: rows of length 1024, dst row = 2*row + off
__global__ void convert_w2(const void* __restrict__ W, size_t src_base,
                           __half* __restrict__ dst, int nelems, int off)
{
    int i = (blockIdx.x * 256 + threadIdx.x) * 4;
    if (i >= nelems) return;
    int fmt = g_wfmt;
    float w0, w1, w2, w3;
    load_w4(W, src_base + i, fmt, w0, w1, w2, w3);
    __half2 h0 = __floats2half2_rn(w0, w1);
    __half2 h1 = __floats2half2_rn(w2, w3);
    int row = i >> 10, col = i & 1023;
    size_t di = (((size_t)(2*row + off)) << 10) + col;
    *(uint2*)&dst[di] = make_uint2(*(uint32_t*)&h0, *(uint32_t*)&h1);
}

// interleave gate/up scales: dst[(2j+off)*8+g] = src[j*8+g]  (ngroups=8)
__global__ void interleave_sc(const float* __restrict__ src, float* __restrict__ dst,
                              int n, int off)
{
    int i = blockIdx.x * 256 + threadIdx.x;
    if (i >= n) return;
    int row = i >> 3, g = i & 7;
    dst[(((size_t)(2*row + off)) << 3) + g] = src[i];
}

// ---------------- embedding gather + dequant ----------------
__global__ void embed_kernel(const int* __restrict__ ids,
                             const void* __restrict__ et,
                             const float* __restrict__ es,
                             float* __restrict__ X)
{
    int token = blockIdx.x;
    int id = ids[token];
    int d0 = threadIdx.x * 4;
    int fmt = g_wfmt;
    float w0, w1, w2, w3;
    load_w4(et, (size_t)id * D_ + d0, fmt, w0, w1, w2, w3);
    float s = es[id * (D_/GS_) + (d0 >> 7)];
    *(float4*)(X + (size_t)token * D_ + d0) = make_float4(w0*s, w1*s, w2*s, w3*s);
}

// ---------------- rmsnorm (f32 in, f16 out) ----------------
__global__ void rmsnorm_kernel(const float* __restrict__ X,
                               const float* __restrict__ w,
                               __half* __restrict__ Y)
{
    int row = blockIdx.x;
    const float* x = X + (size_t)row * D_;
    float ss = 0.f;
    float vals[4];
#pragma unroll
    for (int j = 0; j < 4; j++) {
        vals[j] = x[threadIdx.x + j*256];
        ss += vals[j]*vals[j];
    }
    __shared__ float red[256];
    red[threadIdx.x] = ss;
    __syncthreads();
    for (int s = 128; s > 0; s >>= 1) {
        if (threadIdx.x < s) red[threadIdx.x] += red[threadIdx.x + s];
        __syncthreads();
    }
    float rs = rsqrtf(red[0] * (1.0f/(float)D_) + 1e-6f);
#pragma unroll
    for (int j = 0; j < 4; j++) {
        int d = threadIdx.x + j*256;
        Y[(size_t)row * D_ + d] = __float2half(vals[j] * rs * w[d]);
    }
}

// ---------------- mma helpers ----------------
__device__ __forceinline__ void mma16816(float* c, const uint32_t* a, const uint32_t* b)
{
    asm volatile(
        "mma.sync.aligned.m16n8k16.row.col.f32.f16.f16.f32 "
        "{%0,%1,%2,%3}, {%4,%5,%6,%7}, {%8,%9}, {%0,%1,%2,%3};\n"
        : "+f"(c[0]), "+f"(c[1]), "+f"(c[2]), "+f"(c[3])
        : "r"(a[0]), "r"(a[1]), "r"(a[2]), "r"(a[3]), "r"(b[0]), "r"(b[1]));
}
__device__ __forceinline__ void cp16(uint32_t dst, const void* src)
{
    asm volatile("cp.async.cg.shared.global [%0], [%1], 16;\n" :: "r"(dst), "l"(src));
}
__device__ __forceinline__ void ldm_x4(uint32_t& r0, uint32_t& r1, uint32_t& r2, uint32_t& r3,
                                       uint32_t addr)
{
    asm volatile("ldmatrix.sync.aligned.m8n8.x4.shared.b16 {%0,%1,%2,%3}, [%4];"
                 : "=r"(r0), "=r"(r1), "=r"(r2), "=r"(r3) : "r"(addr));
}
__device__ __forceinline__ uint32_t smem_u32(const void* p) {
    return (uint32_t)__cvta_generic_to_shared(p);
}

// ---------------- async HMMA GEMM ----------------
// OP=0: f32 store.  OP=1: f32 accumulate.  OP=2: f16 store.
// OP=3: fused silu(gate)*up -> f16 [M, N/2] (weights interleaved gate/up).
#define BM 128
#define BN 128
#define BKT 32

template<int OP>
__global__ void __launch_bounds__(256, 2)
gemm_async(const __half* __restrict__ A, const __half* __restrict__ Wh,
           const float* __restrict__ Sc, void* __restrict__ Cv,
           int M, int N, int K)
{
    __shared__ __align__(16) __half As[2][BM*BKT];
    __shared__ __align__(16) __half Bs[2][BN*BKT];
    __shared__ float Ssc[32][128];          // [group][n]

    const int tid  = threadIdx.x;
    const int lane = tid & 31;
    const int wid  = tid >> 5;
    const int warp_m = wid >> 2;            // 0..1 (64 rows)
    const int warp_n = wid & 3;             // 0..3 (32 cols)
    const int m0 = blockIdx.x * BM;
    const int n0 = blockIdx.y * BN;
    const int ngroups = K >> 7;
    const int gid = lane >> 2, tig = lane & 3;

    const uint32_t sa = smem_u32(&As[0][0]);
    const uint32_t sb = smem_u32(&Bs[0][0]);

    const int a_row  = lane & 15;
    const int a_sel  = lane >> 4;
    const int a_xor  = ((lane & 15) >> 1) & 3;
    const int b_roff = ((lane >> 4) << 3) + (lane & 7);
    const int b_sel  = (lane >> 3) & 1;
    const int b_xor  = (b_roff >> 1) & 3;

    float acc[4][4][4] = {};
    float s_cur[4][2];

    for (int i = tid; i < 128 * ngroups; i += 256) {
        int n = i & 127, g = i >> 7;
        Ssc[g][n] = Sc[(size_t)(n0 + n) * ngroups + g];
    }

    const int iters = K / BKT;

    auto issue = [&](int stage, int k0) {
        uint32_t ab = sa + stage * (BM*BKT*2);
        uint32_t bb = sb + stage * (BN*BKT*2);
#pragma unroll
        for (int j = 0; j < 2; j++) {
            int c = tid + j*256;
            int row = c >> 2, ch = c & 3;
            int pch = ch ^ ((row >> 1) & 3);
            cp16(ab + row*64 + pch*16, A  + (size_t)(m0+row)*K + k0 + ch*8);
        }
#pragma unroll
        for (int j = 0; j < 2; j++) {
            int c = tid + j*256;
            int row = c >> 2, ch = c & 3;
            int pch = ch ^ ((row >> 1) & 3);
            cp16(bb + row*64 + pch*16, Wh + (size_t)(n0+row)*K + k0 + ch*8);
        }
        asm volatile("cp.async.commit_group;\n");
    };

    issue(0, 0);

    for (int it = 0; it < iters; it++) {
        if (it + 1 < iters) {
            issue((it + 1) & 1, (it + 1) * BKT);
            asm volatile("cp.async.wait_group 1;\n");
        } else {
            asm volatile("cp.async.wait_group 0;\n");
        }
        __syncthreads();

        if ((it & 3) == 0) {
            int g = it >> 2;
#pragma unroll
            for (int nt = 0; nt < 4; nt++) {
                int nc = warp_n*32 + nt*8 + 2*tig;
                float s0 = Ssc[g][nc], s1 = Ssc[g][nc + 1];
                if (it) {
                    float r0 = __fdividef(s_cur[nt][0], s0);
                    float r1 = __fdividef(s_cur[nt][1], s1);
#pragma unroll
                    for (int mt = 0; mt < 4; mt++) {
                        acc[mt][nt][0] *= r0; acc[mt][nt][1] *= r1;
                        acc[mt][nt][2] *= r0; acc[mt][nt][3] *= r1;
                    }
                }
                s_cur[nt][0] = s0; s_cur[nt][1] = s1;
            }
        }

        const int stage = it & 1;
        const uint32_t ab = sa + stage * (BM*BKT*2);
        const uint32_t bb = sb + stage * (BN*BKT*2);
#pragma unroll
        for (int kk = 0; kk < 2; kk++) {
            uint32_t af[4][4];
#pragma unroll
            for (int mt = 0; mt < 4; mt++) {
                int row = warp_m*64 + mt*16 + a_row;
                int pch = (kk*2 + a_sel) ^ a_xor;
                ldm_x4(af[mt][0], af[mt][1], af[mt][2], af[mt][3],
                       ab + row*64 + pch*16);
            }
            uint32_t bf[4][2];
#pragma unroll
            for (int p = 0; p < 2; p++) {
                int row = warp_n*32 + p*16 + b_roff;
                int pch = (kk*2 + b_sel) ^ b_xor;
                uint32_t r0, r1, r2, r3;
                ldm_x4(r0, r1, r2, r3, bb + row*64 + pch*16);
                bf[2*p  ][0] = r0; bf[2*p  ][1] = r1;
                bf[2*p+1][0] = r2; bf[2*p+1][1] = r3;
            }
#pragma unroll
            for (int mt = 0; mt < 4; mt++)
#pragma unroll
                for (int nt = 0; nt < 4; nt++)
                    mma16816(acc[mt][nt], af[mt], bf[nt]);
        }
        __syncthreads();
    }

    // ---- epilogue ----
#pragma unroll
    for (int mt = 0; mt < 4; mt++) {
        int r = m0 + warp_m*64 + mt*16 + gid;
#pragma unroll
        for (int nt = 0; nt < 4; nt++) {
            int c = n0 + warp_n*32 + nt*8 + 2*tig;
            float s0 = s_cur[nt][0], s1 = s_cur[nt][1];
            float v00 = acc[mt][nt][0]*s0, v01 = acc[mt][nt][1]*s1;
            float v10 = acc[mt][nt][2]*s0, v11 = acc[mt][nt][3]*s1;
            if (OP == 0 || OP == 1) {
                float* C = (float*)Cv;
                float* p0 = C + (size_t)r*N + c;
                float* p1 = C + (size_t)(r+8)*N + c;
                float2 v0 = make_float2(v00, v01);
                float2 v1 = make_float2(v10, v11);
                if (OP == 1) {
                    float2 o0 = *(float2*)p0, o1 = *(float2*)p1;
                    v0.x += o0.x; v0.y += o0.y; v1.x += o1.x; v1.y += o1.y;
                }
                *(float2*)p0 = v0;
                *(float2*)p1 = v1;
            } else if (OP == 2) {
                __half* C = (__half*)Cv;
                *(__half2*)(C + (size_t)r*N + c)     = __floats2half2_rn(v00, v01);
                *(__half2*)(C + (size_t)(r+8)*N + c) = __floats2half2_rn(v10, v11);
            } else {
                // silu(gate)*up; (v00,v01) = (gate,up) of out col c/2
                __half* C = (__half*)Cv;
                int oN = N >> 1, oc = c >> 1;
                float o0 = v00 / (1.f + __expf(-v00)) * v01;
                float o1 = v10 / (1.f + __expf(-v10)) * v11;
                C[(size_t)r*oN + oc]     = __float2half(o0);
                C[(size_t)(r+8)*oN + oc] = __float2half(o1);
            }
        }
    }
}

// ---------------- mma flash attention + per-head residual ----------------
// QKV fused f16 [NT, 3072]; block = 64 q rows x (b,h); 4 warps x 16 rows.
#define AQ 64
#define QKVS (3*D_)
__global__ void __launch_bounds__(128)
attn_mma(const __half* __restrict__ QKV, const __half* __restrict__ Hn,
         const float* __restrict__ alpha, __half* __restrict__ O, int layer)
{
    __shared__ __align__(16) __half Qs[AQ][72];
    __shared__ __align__(16) __half Ks[AQ][72];
    __shared__ __align__(16) __half Vt[AQ][72];   // Vt[dh][key]

    const int tid = threadIdx.x, lane = tid & 31, wid = tid >> 5;
    const int qt = blockIdx.x, hh = blockIdx.y, b = blockIdx.z;
    const int q0 = qt * AQ;

    // load Q tile (64 rows x 64 dims) f16
    for (int t = tid; t < AQ*8; t += 128) {
        int r = t >> 3, c8 = t & 7;
        *(uint4*)&Qs[r][c8*8] =
            *(const uint4*)(QKV + ((size_t)(b*S_ + q0 + r))*QKVS + hh*DH_ + c8*8);
    }
    __syncthreads();

    uint32_t qf[4][4];
    {
        int rr = wid*16 + (lane & 15);
        int cc = ((lane >> 4) & 1) * 8;
#pragma unroll
        for (int ks = 0; ks < 4; ks++)
            ldm_x4(qf[ks][0], qf[ks][1], qf[ks][2], qf[ks][3],
                   smem_u32(&Qs[rr][ks*16 + cc]));
    }

    float o[8][4] = {};
    float m_lo = -1e30f, m_hi = -1e30f, l_lo = 0.f, l_hi = 0.f;
    const int qi_lo = q0 + wid*16 + (lane >> 2);
    const int qi_hi = qi_lo + 8;
    const int row_off = ((lane >> 4) << 3) + (lane & 7);
    const int col_sel = ((lane >> 3) & 1) * 8;

    for (int t0 = 0; t0 < q0 + AQ; t0 += AQ) {
        __syncthreads();
        for (int t = tid; t < AQ*8; t += 128) {
            int r = t >> 3, c8 = t & 7;
            const __half* base = QKV + ((size_t)(b*S_ + t0 + r))*QKVS + hh*DH_ + c8*8;
            *(uint4*)&Ks[r][c8*8] = *(const uint4*)(base + D_);
            uint4 raw = *(const uint4*)(base + 2*D_);
            const __half* hp = (const __half*)&raw;
#pragma unroll
            for (int d = 0; d < 8; d++) Vt[c8*8 + d][r] = hp[d];
        }
        __syncthreads();

        // ---- S = Q K^T ----
        float sacc[8][4] = {};
#pragma unroll
        for (int ks = 0; ks < 4; ks++) {
#pragma unroll
            for (int jp = 0; jp < 4; jp++) {
                uint32_t r0, r1, r2, r3;
                ldm_x4(r0, r1, r2, r3, smem_u32(&Ks[jp*16 + row_off][ks*16 + col_sel]));
                uint32_t bA[2] = {r0, r1};
                uint32_t bB[2] = {r2, r3};
                mma16816(sacc[2*jp  ], qf[ks], bA);
                mma16816(sacc[2*jp+1], qf[ks], bB);
            }
        }

        // ---- scale + causal mask + online softmax ----
        float mx_lo = -1e30f, mx_hi = -1e30f;
#pragma unroll
        for (int j = 0; j < 8; j++) {
            int kb = t0 + j*8 + 2*(lane & 3);
            sacc[j][0] = (kb     <= qi_lo) ? sacc[j][0]*0.125f : -1e30f;
            sacc[j][1] = (kb + 1 <= qi_lo) ? sacc[j][1]*0.125f : -1e30f;
            sacc[j][2] = (kb     <= qi_hi) ? sacc[j][2]*0.125f : -1e30f;
            sacc[j][3] = (kb + 1 <= qi_hi) ? sacc[j][3]*0.125f : -1e30f;
            mx_lo = fmaxf(mx_lo, fmaxf(sacc[j][0], sacc[j][1]));
            mx_hi = fmaxf(mx_hi, fmaxf(sacc[j][2], sacc[j][3]));
        }
        mx_lo = fmaxf(mx_lo, __shfl_xor_sync(0xffffffffu, mx_lo, 1));
        mx_lo = fmaxf(mx_lo, __shfl_xor_sync(0xffffffffu, mx_lo, 2));
        mx_hi = fmaxf(mx_hi, __shfl_xor_sync(0xffffffffu, mx_hi, 1));
        mx_hi = fmaxf(mx_hi, __shfl_xor_sync(0xffffffffu, mx_hi, 2));

        float mn_lo = fmaxf(m_lo, mx_lo), mn_hi = fmaxf(m_hi, mx_hi);
        float c_lo = __expf(m_lo - mn_lo), c_hi = __expf(m_hi - mn_hi);
        m_lo = mn_lo; m_hi = mn_hi;
        l_lo *= c_lo; l_hi *= c_hi;
#pragma unroll
        for (int j = 0; j < 8; j++) {
            o[j][0] *= c_lo; o[j][1] *= c_lo;
            o[j][2] *= c_hi; o[j][3] *= c_hi;
        }

        uint32_t pa[8], pb[8];
        float ps_lo = 0.f, ps_hi = 0.f;
#pragma unroll
        for (int j = 0; j < 8; j++) {
            float e0 = __expf(sacc[j][0] - mn_lo);
            float e1 = __expf(sacc[j][1] - mn_lo);
            float e2 = __expf(sacc[j][2] - mn_hi);
            float e3 = __expf(sacc[j][3] - mn_hi);
            ps_lo += e0 + e1; ps_hi += e2 + e3;
            __half2 hl = __floats2half2_rn(e0, e1);
            __half2 hb = __floats2half2_rn(e2, e3);
            pa[j] = *(uint32_t*)&hl;
            pb[j] = *(uint32_t*)&hb;
        }
        ps_lo += __shfl_xor_sync(0xffffffffu, ps_lo, 1);
        ps_lo += __shfl_xor_sync(0xffffffffu, ps_lo, 2);
        ps_hi += __shfl_xor_sync(0xffffffffu, ps_hi, 1);
        ps_hi += __shfl_xor_sync(0xffffffffu, ps_hi, 2);
        l_lo += ps_lo; l_hi += ps_hi;

        // ---- O += P V ----
#pragma unroll
        for (int kk = 0; kk < 4; kk++) {
            uint32_t af[4] = {pa[2*kk], pb[2*kk], pa[2*kk+1], pb[2*kk+1]};
#pragma unroll
            for (int dp = 0; dp < 4; dp++) {
                uint32_t r0, r1, r2, r3;
                ldm_x4(r0, r1, r2, r3, smem_u32(&Vt[dp*16 + row_off][kk*16 + col_sel]));
                uint32_t bA[2] = {r0, r1};
                uint32_t bB[2] = {r2, r3};
                mma16816(o[2*dp  ], af, bA);
                mma16816(o[2*dp+1], af, bB);
            }
        }
    }

    // ---- epilogue ----
    float i_lo = 1.f / l_lo, i_hi = 1.f / l_hi;
    float a = alpha[layer*H_ + hh];
    size_t tok_lo = (size_t)(b*S_ + qi_lo);
#pragma unroll
    for (int j = 0; j < 8; j++) {
        int col = hh*DH_ + j*8 + 2*(lane & 3);
        float2 fh_lo = __half22float2(*(const __half2*)(Hn + tok_lo*D_ + col));
        float2 fh_hi = __half22float2(*(const __half2*)(Hn + (tok_lo+8)*D_ + col));
        __half2 o_lo = __floats2half2_rn(o[j][0]*i_lo + a*fh_lo.x,
                                         o[j][1]*i_lo + a*fh_lo.y);
        __half2 o_hi = __floats2half2_rn(o[j][2]*i_hi + a*fh_hi.x,
                                         o[j][3]*i_hi + a*fh_hi.y);
        *(__half2*)(O + tok_lo*D_ + col)     = o_lo;
        *(__half2*)(O + (tok_lo+8)*D_ + col) = o_hi;
    }
}

// ---------------- launch ----------------
extern "C" void kernel_launch(void* const* d_in, const int* in_sizes, int n_in,
                              void* d_out, int out_size)
{
    const int*   ids    = (const int*)  d_in[0];
    const void*  emb_t  = d_in[1];
    const float* emb_s  = (const float*)d_in[2];
    const void*  qt_    = d_in[3];
    const float* qs_    = (const float*)d_in[4];
    const void*  kt_    = d_in[5];
    const float* ks_    = (const float*)d_in[6];
    const void*  vt_    = d_in[7];
    const float* vs_    = (const float*)d_in[8];
    const void*  ot_    = d_in[9];
    const float* os_    = (const float*)d_in[10];
    const void*  gatet  = d_in[11];
    const float* gates  = (const float*)d_in[12];
    const void*  upt    = d_in[13];
    const float* ups    = (const float*)d_in[14];
    const void*  downt  = d_in[15];
    const float* downs  = (const float*)d_in[16];
    const float* wa     = (const float*)d_in[17];
    const float* wm     = (const float*)d_in[18];
    const float* alpha  = (const float*)d_in[19];
    const float* wf     = (const float*)d_in[20];
    const void*  headt  = d_in[21];
    const float* heads  = (const float*)d_in[22];
    float* out = (float*)d_out;

    float *x, *scqkv, *scgu;
    __half *qkv, *hh, *oh, *gh, *wh;
    cudaGetSymbolAddress((void**)&x,    g_x);
    cudaGetSymbolAddress((void**)&qkv,  g_qkv);
    cudaGetSymbolAddress((void**)&hh,   g_hh);
    cudaGetSymbolAddress((void**)&oh,   g_oh);
    cudaGetSymbolAddress((void**)&gh,   g_gh);
    cudaGetSymbolAddress((void**)&wh,   g_wh);
    cudaGetSymbolAddress((void**)&scqkv,g_scqkv);
    cudaGetSymbolAddress((void**)&scgu, g_scgu);

    const size_t wDD = (size_t)D_*D_;          // 1M
    const size_t wFD = (size_t)DFF_*D_;        // 4M
    const size_t sDD = wDD/GS_;                // 8192
    const size_t sFD = wFD/GS_;                // 32768

    detect_fmt_kernel<<<1, 1>>>(emb_t);

    const int CB = 256;
    for (int l = 0; l < L_; l++) {
        convert_w <<<wDD/1024, CB>>>(qt_,   l*wDD, wh + OFF_QKV + l*3*wDD,          (int)wDD);
        convert_w <<<wDD/1024, CB>>>(kt_,   l*wDD, wh + OFF_QKV + l*3*wDD + wDD,    (int)wDD);
        convert_w <<<wDD/1024, CB>>>(vt_,   l*wDD, wh + OFF_QKV + l*3*wDD + 2*wDD,  (int)wDD);
        convert_w <<<wDD/1024, CB>>>(ot_,   l*wDD, wh + OFF_O   + l*wDD,            (int)wDD);
        convert_w2<<<wFD/1024, CB>>>(gatet, l*wFD, wh + OFF_GU  + l*2*wFD, (int)wFD, 0);
        convert_w2<<<wFD/1024, CB>>>(upt,   l*wFD, wh + OFF_GU  + l*2*wFD, (int)wFD, 1);
        convert_w <<<wFD/1024, CB>>>(downt, l*wFD, wh + OFF_DN  + l*wFD,            (int)wFD);
        cudaMemcpyAsync(scqkv + l*3*sDD,         qs_ + l*sDD, sDD*4, cudaMemcpyDeviceToDevice, 0);
        cudaMemcpyAsync(scqkv + l*3*sDD +   sDD, ks_ + l*sDD, sDD*4, cudaMemcpyDeviceToDevice, 0);
        cudaMemcpyAsync(scqkv + l*3*sDD + 2*sDD, vs_ + l*sDD, sDD*4, cudaMemcpyDeviceToDevice, 0);
        interleave_sc<<<(sFD + 255)/256, CB>>>(gates + l*sFD, scgu + l*2*sFD, (int)sFD, 0);
        interleave_sc<<<(sFD + 255)/256, CB>>>(ups   + l*sFD, scgu + l*2*sFD, (int)sFD, 1);
    }
    convert_w<<<(V_*(size_t)D_)/1024, CB>>>(headt, 0, wh + OFF_HD, V_*D_);

    embed_kernel<<<NT_, 256>>>(ids, emb_t, emb_s, x);

    dim3 g_qkvp(NT_/BM, 3*D_/BN);    // 16 x 24
    dim3 g_op  (NT_/BM, D_/BN);      // 16 x 8
    dim3 g_gup (NT_/BM, 2*DFF_/BN);  // 16 x 64
    dim3 g_hd  (NT_/BM, V_/BN);      // 16 x 250

    for (int l = 0; l < L_; l++) {
        rmsnorm_kernel<<<NT_, 256>>>(x, wa + (size_t)l*D_, hh);
        gemm_async<2><<<g_qkvp, 256>>>(hh, wh + OFF_QKV + l*3*wDD, scqkv + l*3*sDD,
                                       qkv, NT_, 3*D_, D_);
        attn_mma<<<dim3(S_/AQ, H_, B_), 128>>>(qkv, hh, alpha, oh, l);
        gemm_async<1><<<g_op, 256>>>(oh, wh + OFF_O + l*wDD, os_ + l*sDD,
                                     x, NT_, D_, D_);

        rmsnorm_kernel<<<NT_, 256>>>(x, wm + (size_t)l*D_, hh);
        gemm_async<3><<<g_gup, 256>>>(hh, wh + OFF_GU + l*2*wFD, scgu + l*2*sFD,
                                      gh, NT_, 2*DFF_, D_);
        gemm_async<1><<<g_op, 256>>>(gh, wh + OFF_DN + l*wFD, downs + l*sFD,
                                     x, NT_, D_, DFF_);
    }
    rmsnorm_kernel<<<NT_, 256>>>(x, wf, hh);
    gemm_async<0><<<g_hd, 256>>>(hh, wh + OFF_HD, heads, out, NT_, V_, D_);
}

// round 10
// speedup vs baseline: 9.9639x; 1.0058x over previous
#include <cuda_runtime.h>
#include <cuda_fp16.h>
#include <cuda_bf16.h>
#include <cstdint>

// ---------------- dims ----------------
#define B_  2
#define S_  1024
#define D_  1024
#define H_  16
#define DH_ 64
#define DFF_ 4096
#define L_  2
#define V_  32000
#define GS_ 128
#define NT_ (B_*S_)   // 2048 tokens

// weight regions in g_wh (element offsets, halves)
#define OFF_QKV 0ull                       // 2 layers x 3M
#define OFF_O   (6ull*1024*1024)           // 2 x 1M
#define OFF_GU  (8ull*1024*1024)           // 2 x 8M (interleaved gate/up)
#define OFF_DN  (24ull*1024*1024)          // 2 x 4M
#define OFF_HD  (32ull*1024*1024)          // 32M
#define WH_TOT  (64ull*1024*1024)

// ---------------- scratch ----------------
__device__ __align__(16) float  g_x  [NT_*D_];
__device__ __align__(16) __half g_qkv[NT_*3*D_];
__device__ __align__(16) __half g_hh [NT_*D_];
__device__ __align__(16) __half g_oh [NT_*D_];
__device__ __align__(16) __half g_gh [NT_*DFF_];
__device__ __align__(16) __half g_wh [WH_TOT];
__device__ float g_scqkv[2*3*8192];
__device__ float g_scgu [2*2*32768];       // interleaved gate/up scales
__device__ int   g_wfmt;   // 0=int8, 1=int32, 2=bf16

// ---------------- weight format detector ----------------
__global__ void detect_fmt_kernel(const void* __restrict__ w)
{
    const unsigned* u = (const unsigned*)w;
    bool i32 = true, b16 = true;
    for (int i = 0; i < 64; i++) {
        unsigned x = u[i];
        if (!(x == 0u || x == 1u || x == 0xFFFFFFFFu)) i32 = false;
        unsigned lo = x & 0xFFFFu, hi = x >> 16;
        bool lok = (lo == 0u || lo == 0x3F80u || lo == 0xBF80u);
        bool hok = (hi == 0u || hi == 0x3F80u || hi == 0xBF80u);
        if (!(lok && hok)) b16 = false;
    }
    g_wfmt = i32 ? 1 : (b16 ? 2 : 0);
}

__device__ __forceinline__ void load_w4(const void* W, size_t idx, int fmt,
                                        float& w0, float& w1, float& w2, float& w3)
{
    if (fmt == 1) {
        int4 wv = *(const int4*)((const int*)W + idx);
        w0 = (float)wv.x; w1 = (float)wv.y; w2 = (float)wv.z; w3 = (float)wv.w;
    } else if (fmt == 2) {
        uint2 v = *(const uint2*)((const __nv_bfloat16*)W + idx);
        w0 = __bfloat162float(__ushort_as_bfloat16((unsigned short)( v.x        & 0xFFFFu)));
        w1 = __bfloat162float(__ushort_as_bfloat16((unsigned short)( v.x >> 16          )));
        w2 = __bfloat162float(__ushort_as_bfloat16((unsigned short)( v.y        & 0xFFFFu)));
        w3 = __bfloat162float(__ushort_as_bfloat16((unsigned short)( v.y >> 16          )));
    } else {
        int wv = *(const int*)((const int8_t*)W + idx);
        w0 = (float)(int8_t)( wv         & 0xff);
        w1 = (float)(int8_t)((wv >> 8 )  & 0xff);
        w2 = (float)(int8_t)((wv >> 16)  & 0xff);
        w3 = (float)(int8_t)( wv >> 24         );
    }
}

// ---------------- weight conversion (16 elems/thread, MLP=4) ----------------
__global__ void convert_w(const void* __restrict__ W, size_t src_base,
                          __half* __restrict__ dst, int nelems)
{
    int i = (blockIdx.x * 256 + threadIdx.x) * 16;
    if (i >= nelems) return;
    int fmt = g_wfmt;
    float w[16];
#pragma unroll
    for (int j = 0; j < 4; j++)
        load_w4(W, src_base + i + j*4, fmt, w[j*4], w[j*4+1], w[j*4+2], w[j*4+3]);
    uint32_t h[8];
#pragma unroll
    for (int j = 0; j < 8; j++) {
        __half2 p = __floats2half2_rn(w[2*j], w[2*j+1]);
        h[j] = *(uint32_t*)&p;
    }
    *(uint4*)&dst[i]     = make_uint4(h[0], h[1], h[2], h[3]);
    *(uint4*)&dst[i + 8] = make_uint4(h[4], h[5], h[6], h[7]);
}

// interleaved variant: rows of length 1024 (D_), dst row = 2*row + off.
// 16-elem blocks never cross a row boundary (16 | 1024).
__global__ void convert_w2(const void* __restrict__ W, size_t src_base,
                           __half* __restrict__ dst, int nelems, int off)
{
    int i = (blockIdx.x * 256 + threadIdx.x) * 16;
    if (i >= nelems) return;
    int fmt = g_wfmt;
    float w[16];
#pragma unroll
    for (int j = 0; j < 4; j++)
        load_w4(W, src_base + i + j*4, fmt, w[j*4], w[j*4+1], w[j*4+2], w[j*4+3]);
    uint32_t h[8];
#pragma unroll
    for (int j = 0; j < 8; j++) {
        __half2 p = __floats2half2_rn(w[2*j], w[2*j+1]);
        h[j] = *(uint32_t*)&p;
    }
    int row = i >> 10, col = i & 1023;
    size_t di = (((size_t)(2*row + off)) << 10) + col;
    *(uint4*)&dst[di]     = make_uint4(h[0], h[1], h[2], h[3]);
    *(uint4*)&dst[di + 8] = make_uint4(h[4], h[5], h[6], h[7]);
}

// interleave gate/up scales: dst[(2j+off)*8+g] = src[j*8+g]  (ngroups=8)
__global__ void interleave_sc(const float* __restrict__ src, float* __restrict__ dst,
                              int n, int off)
{
    int i = blockIdx.x * 256 + threadIdx.x;
    if (i >= n) return;
    int row = i >> 3, g = i & 7;
    dst[(((size_t)(2*row + off)) << 3) + g] = src[i];
}

// ---------------- embedding gather + dequant ----------------
__global__ void embed_kernel(const int* __restrict__ ids,
                             const void* __restrict__ et,
                             const float* __restrict__ es,
                             float* __restrict__ X)
{
    int token = blockIdx.x;
    int id = ids[token];
    int d0 = threadIdx.x * 4;
    int fmt = g_wfmt;
    float w0, w1, w2, w3;
    load_w4(et, (size_t)id * D_ + d0, fmt, w0, w1, w2, w3);
    float s = es[id * (D_/GS_) + (d0 >> 7)];
    *(float4*)(X + (size_t)token * D_ + d0) = make_float4(w0*s, w1*s, w2*s, w3*s);
}

// ---------------- rmsnorm (f32 in, f16 out) ----------------
__global__ void rmsnorm_kernel(const float* __restrict__ X,
                               const float* __restrict__ w,
                               __half* __restrict__ Y)
{
    int row = blockIdx.x;
    const float* x = X + (size_t)row * D_;
    float ss = 0.f;
    float vals[4];
#pragma unroll
    for (int j = 0; j < 4; j++) {
        vals[j] = x[threadIdx.x + j*256];
        ss += vals[j]*vals[j];
    }
    __shared__ float red[256];
    red[threadIdx.x] = ss;
    __syncthreads();
    for (int s = 128; s > 0; s >>= 1) {
        if (threadIdx.x < s) red[threadIdx.x] += red[threadIdx.x + s];
        __syncthreads();
    }
    float rs = rsqrtf(red[0] * (1.0f/(float)D_) + 1e-6f);
#pragma unroll
    for (int j = 0; j < 4; j++) {
        int d = threadIdx.x + j*256;
        Y[(size_t)row * D_ + d] = __float2half(vals[j] * rs * w[d]);
    }
}

// ---------------- mma helpers ----------------
__device__ __forceinline__ void mma16816(float* c, const uint32_t* a, const uint32_t* b)
{
    asm volatile(
        "mma.sync.aligned.m16n8k16.row.col.f32.f16.f16.f32 "
        "{%0,%1,%2,%3}, {%4,%5,%6,%7}, {%8,%9}, {%0,%1,%2,%3};\n"
        : "+f"(c[0]), "+f"(c[1]), "+f"(c[2]), "+f"(c[3])
        : "r"(a[0]), "r"(a[1]), "r"(a[2]), "r"(a[3]), "r"(b[0]), "r"(b[1]));
}
__device__ __forceinline__ void cp16(uint32_t dst, const void* src)
{
    asm volatile("cp.async.cg.shared.global [%0], [%1], 16;\n" :: "r"(dst), "l"(src));
}
__device__ __forceinline__ void ldm_x4(uint32_t& r0, uint32_t& r1, uint32_t& r2, uint32_t& r3,
                                       uint32_t addr)
{
    asm volatile("ldmatrix.sync.aligned.m8n8.x4.shared.b16 {%0,%1,%2,%3}, [%4];"
                 : "=r"(r0), "=r"(r1), "=r"(r2), "=r"(r3) : "r"(addr));
}
__device__ __forceinline__ uint32_t smem_u32(const void* p) {
    return (uint32_t)__cvta_generic_to_shared(p);
}

// ---------------- async HMMA GEMM ----------------
// OP=0: f32 store.  OP=1: f32 accumulate.  OP=2: f16 store.
// OP=3: fused silu(gate)*up -> f16 [M, N/2] (weights interleaved gate/up).
#define BM 128
#define BN 128
#define BKT 32

template<int OP>
__global__ void __launch_bounds__(256, 2)
gemm_async(const __half* __restrict__ A, const __half* __restrict__ Wh,
           const float* __restrict__ Sc, void* __restrict__ Cv,
           int M, int N, int K)
{
    __shared__ __align__(16) __half As[2][BM*BKT];
    __shared__ __align__(16) __half Bs[2][BN*BKT];
    __shared__ float Ssc[32][128];          // [group][n]

    const int tid  = threadIdx.x;
    const int lane = tid & 31;
    const int wid  = tid >> 5;
    const int warp_m = wid >> 2;            // 0..1 (64 rows)
    const int warp_n = wid & 3;             // 0..3 (32 cols)
    const int m0 = blockIdx.x * BM;
    const int n0 = blockIdx.y * BN;
    const int ngroups = K >> 7;
    const int gid = lane >> 2, tig = lane & 3;

    const uint32_t sa = smem_u32(&As[0][0]);
    const uint32_t sb = smem_u32(&Bs[0][0]);

    const int a_row  = lane & 15;
    const int a_sel  = lane >> 4;
    const int a_xor  = ((lane & 15) >> 1) & 3;
    const int b_roff = ((lane >> 4) << 3) + (lane & 7);
    const int b_sel  = (lane >> 3) & 1;
    const int b_xor  = (b_roff >> 1) & 3;

    float acc[4][4][4] = {};
    float s_cur[4][2];

    for (int i = tid; i < 128 * ngroups; i += 256) {
        int n = i & 127, g = i >> 7;
        Ssc[g][n] = Sc[(size_t)(n0 + n) * ngroups + g];
    }

    const int iters = K / BKT;

    auto issue = [&](int stage, int k0) {
        uint32_t ab = sa + stage * (BM*BKT*2);
        uint32_t bb = sb + stage * (BN*BKT*2);
#pragma unroll
        for (int j = 0; j < 2; j++) {
            int c = tid + j*256;
            int row = c >> 2, ch = c & 3;
            int pch = ch ^ ((row >> 1) & 3);
            cp16(ab + row*64 + pch*16, A  + (size_t)(m0+row)*K + k0 + ch*8);
        }
#pragma unroll
        for (int j = 0; j < 2; j++) {
            int c = tid + j*256;
            int row = c >> 2, ch = c & 3;
            int pch = ch ^ ((row >> 1) & 3);
            cp16(bb + row*64 + pch*16, Wh + (size_t)(n0+row)*K + k0 + ch*8);
        }
        asm volatile("cp.async.commit_group;\n");
    };

    issue(0, 0);

    for (int it = 0; it < iters; it++) {
        if (it + 1 < iters) {
            issue((it + 1) & 1, (it + 1) * BKT);
            asm volatile("cp.async.wait_group 1;\n");
        } else {
            asm volatile("cp.async.wait_group 0;\n");
        }
        __syncthreads();

        if ((it & 3) == 0) {
            int g = it >> 2;
#pragma unroll
            for (int nt = 0; nt < 4; nt++) {
                int nc = warp_n*32 + nt*8 + 2*tig;
                float s0 = Ssc[g][nc], s1 = Ssc[g][nc + 1];
                if (it) {
                    float r0 = __fdividef(s_cur[nt][0], s0);
                    float r1 = __fdividef(s_cur[nt][1], s1);
#pragma unroll
                    for (int mt = 0; mt < 4; mt++) {
                        acc[mt][nt][0] *= r0; acc[mt][nt][1] *= r1;
                        acc[mt][nt][2] *= r0; acc[mt][nt][3] *= r1;
                    }
                }
                s_cur[nt][0] = s0; s_cur[nt][1] = s1;
            }
        }

        const int stage = it & 1;
        const uint32_t ab = sa + stage * (BM*BKT*2);
        const uint32_t bb = sb + stage * (BN*BKT*2);
#pragma unroll
        for (int kk = 0; kk < 2; kk++) {
            uint32_t af[4][4];
#pragma unroll
            for (int mt = 0; mt < 4; mt++) {
                int row = warp_m*64 + mt*16 + a_row;
                int pch = (kk*2 + a_sel) ^ a_xor;
                ldm_x4(af[mt][0], af[mt][1], af[mt][2], af[mt][3],
                       ab + row*64 + pch*16);
            }
            uint32_t bf[4][2];
#pragma unroll
            for (int p = 0; p < 2; p++) {
                int row = warp_n*32 + p*16 + b_roff;
                int pch = (kk*2 + b_sel) ^ b_xor;
                uint32_t r0, r1, r2, r3;
                ldm_x4(r0, r1, r2, r3, bb + row*64 + pch*16);
                bf[2*p  ][0] = r0; bf[2*p  ][1] = r1;
                bf[2*p+1][0] = r2; bf[2*p+1][1] = r3;
            }
#pragma unroll
            for (int mt = 0; mt < 4; mt++)
#pragma unroll
                for (int nt = 0; nt < 4; nt++)
                    mma16816(acc[mt][nt], af[mt], bf[nt]);
        }
        __syncthreads();
    }

    // ---- epilogue ----
#pragma unroll
    for (int mt = 0; mt < 4; mt++) {
        int r = m0 + warp_m*64 + mt*16 + gid;
#pragma unroll
        for (int nt = 0; nt < 4; nt++) {
            int c = n0 + warp_n*32 + nt*8 + 2*tig;
            float s0 = s_cur[nt][0], s1 = s_cur[nt][1];
            float v00 = acc[mt][nt][0]*s0, v01 = acc[mt][nt][1]*s1;
            float v10 = acc[mt][nt][2]*s0, v11 = acc[mt][nt][3]*s1;
            if (OP == 0 || OP == 1) {
                float* C = (float*)Cv;
                float* p0 = C + (size_t)r*N + c;
                float* p1 = C + (size_t)(r+8)*N + c;
                float2 v0 = make_float2(v00, v01);
                float2 v1 = make_float2(v10, v11);
                if (OP == 1) {
                    float2 o0 = *(float2*)p0, o1 = *(float2*)p1;
                    v0.x += o0.x; v0.y += o0.y; v1.x += o1.x; v1.y += o1.y;
                }
                *(float2*)p0 = v0;
                *(float2*)p1 = v1;
            } else if (OP == 2) {
                __half* C = (__half*)Cv;
                *(__half2*)(C + (size_t)r*N + c)     = __floats2half2_rn(v00, v01);
                *(__half2*)(C + (size_t)(r+8)*N + c) = __floats2half2_rn(v10, v11);
            } else {
                // silu(gate)*up; (v00,v01) = (gate,up) of out col c/2
                __half* C = (__half*)Cv;
                int oN = N >> 1, oc = c >> 1;
                float o0 = v00 / (1.f + __expf(-v00)) * v01;
                float o1 = v10 / (1.f + __expf(-v10)) * v11;
                C[(size_t)r*oN + oc]     = __float2half(o0);
                C[(size_t)(r+8)*oN + oc] = __float2half(o1);
            }
        }
    }
}

// ---------------- mma flash attention + per-head residual ----------------
// QKV fused f16 [NT, 3072]; block = 64 q rows x (b,h); 4 warps x 16 rows.
#define AQ 64
#define QKVS (3*D_)
__global__ void __launch_bounds__(128)
attn_mma(const __half* __restrict__ QKV, const __half* __restrict__ Hn,
         const float* __restrict__ alpha, __half* __restrict__ O, int layer)
{
    __shared__ __align__(16) __half Qs[AQ][72];
    __shared__ __align__(16) __half Ks[AQ][72];
    __shared__ __align__(16) __half Vt[AQ][72];   // Vt[dh][key]

    const int tid = threadIdx.x, lane = tid & 31, wid = tid >> 5;
    const int qt = blockIdx.x, hh = blockIdx.y, b = blockIdx.z;
    const int q0 = qt * AQ;

    // load Q tile (64 rows x 64 dims) f16
    for (int t = tid; t < AQ*8; t += 128) {
        int r = t >> 3, c8 = t & 7;
        *(uint4*)&Qs[r][c8*8] =
            *(const uint4*)(QKV + ((size_t)(b*S_ + q0 + r))*QKVS + hh*DH_ + c8*8);
    }
    __syncthreads();

    uint32_t qf[4][4];
    {
        int rr = wid*16 + (lane & 15);
        int cc = ((lane >> 4) & 1) * 8;
#pragma unroll
        for (int ks = 0; ks < 4; ks++)
            ldm_x4(qf[ks][0], qf[ks][1], qf[ks][2], qf[ks][3],
                   smem_u32(&Qs[rr][ks*16 + cc]));
    }

    float o[8][4] = {};
    float m_lo = -1e30f, m_hi = -1e30f, l_lo = 0.f, l_hi = 0.f;
    const int qi_lo = q0 + wid*16 + (lane >> 2);
    const int qi_hi = qi_lo + 8;
    const int row_off = ((lane >> 4) << 3) + (lane & 7);
    const int col_sel = ((lane >> 3) & 1) * 8;

    for (int t0 = 0; t0 < q0 + AQ; t0 += AQ) {
        __syncthreads();
        for (int t = tid; t < AQ*8; t += 128) {
            int r = t >> 3, c8 = t & 7;
            const __half* base = QKV + ((size_t)(b*S_ + t0 + r))*QKVS + hh*DH_ + c8*8;
            *(uint4*)&Ks[r][c8*8] = *(const uint4*)(base + D_);
            uint4 raw = *(const uint4*)(base + 2*D_);
            const __half* hp = (const __half*)&raw;
#pragma unroll
            for (int d = 0; d < 8; d++) Vt[c8*8 + d][r] = hp[d];
        }
        __syncthreads();

        // ---- S = Q K^T ----
        float sacc[8][4] = {};
#pragma unroll
        for (int ks = 0; ks < 4; ks++) {
#pragma unroll
            for (int jp = 0; jp < 4; jp++) {
                uint32_t r0, r1, r2, r3;
                ldm_x4(r0, r1, r2, r3, smem_u32(&Ks[jp*16 + row_off][ks*16 + col_sel]));
                uint32_t bA[2] = {r0, r1};
                uint32_t bB[2] = {r2, r3};
                mma16816(sacc[2*jp  ], qf[ks], bA);
                mma16816(sacc[2*jp+1], qf[ks], bB);
            }
        }

        // ---- scale + causal mask + online softmax ----
        float mx_lo = -1e30f, mx_hi = -1e30f;
#pragma unroll
        for (int j = 0; j < 8; j++) {
            int kb = t0 + j*8 + 2*(lane & 3);
            sacc[j][0] = (kb     <= qi_lo) ? sacc[j][0]*0.125f : -1e30f;
            sacc[j][1] = (kb + 1 <= qi_lo) ? sacc[j][1]*0.125f : -1e30f;
            sacc[j][2] = (kb     <= qi_hi) ? sacc[j][2]*0.125f : -1e30f;
            sacc[j][3] = (kb + 1 <= qi_hi) ? sacc[j][3]*0.125f : -1e30f;
            mx_lo = fmaxf(mx_lo, fmaxf(sacc[j][0], sacc[j][1]));
            mx_hi = fmaxf(mx_hi, fmaxf(sacc[j][2], sacc[j][3]));
        }
        mx_lo = fmaxf(mx_lo, __shfl_xor_sync(0xffffffffu, mx_lo, 1));
        mx_lo = fmaxf(mx_lo, __shfl_xor_sync(0xffffffffu, mx_lo, 2));
        mx_hi = fmaxf(mx_hi, __shfl_xor_sync(0xffffffffu, mx_hi, 1));
        mx_hi = fmaxf(mx_hi, __shfl_xor_sync(0xffffffffu, mx_hi, 2));

        float mn_lo = fmaxf(m_lo, mx_lo), mn_hi = fmaxf(m_hi, mx_hi);
        float c_lo = __expf(m_lo - mn_lo), c_hi = __expf(m_hi - mn_hi);
        m_lo = mn_lo; m_hi = mn_hi;
        l_lo *= c_lo; l_hi *= c_hi;
#pragma unroll
        for (int j = 0; j < 8; j++) {
            o[j][0] *= c_lo; o[j][1] *= c_lo;
            o[j][2] *= c_hi; o[j][3] *= c_hi;
        }

        uint32_t pa[8], pb[8];
        float ps_lo = 0.f, ps_hi = 0.f;
#pragma unroll
        for (int j = 0; j < 8; j++) {
            float e0 = __expf(sacc[j][0] - mn_lo);
            float e1 = __expf(sacc[j][1] - mn_lo);
            float e2 = __expf(sacc[j][2] - mn_hi);
            float e3 = __expf(sacc[j][3] - mn_hi);
            ps_lo += e0 + e1; ps_hi += e2 + e3;
            __half2 hl = __floats2half2_rn(e0, e1);
            __half2 hb = __floats2half2_rn(e2, e3);
            pa[j] = *(uint32_t*)&hl;
            pb[j] = *(uint32_t*)&hb;
        }
        ps_lo += __shfl_xor_sync(0xffffffffu, ps_lo, 1);
        ps_lo += __shfl_xor_sync(0xffffffffu, ps_lo, 2);
        ps_hi += __shfl_xor_sync(0xffffffffu, ps_hi, 1);
        ps_hi += __shfl_xor_sync(0xffffffffu, ps_hi, 2);
        l_lo += ps_lo; l_hi += ps_hi;

        // ---- O += P V ----
#pragma unroll
        for (int kk = 0; kk < 4; kk++) {
            uint32_t af[4] = {pa[2*kk], pb[2*kk], pa[2*kk+1], pb[2*kk+1]};
#pragma unroll
            for (int dp = 0; dp < 4; dp++) {
                uint32_t r0, r1, r2, r3;
                ldm_x4(r0, r1, r2, r3, smem_u32(&Vt[dp*16 + row_off][kk*16 + col_sel]));
                uint32_t bA[2] = {r0, r1};
                uint32_t bB[2] = {r2, r3};
                mma16816(o[2*dp  ], af, bA);
                mma16816(o[2*dp+1], af, bB);
            }
        }
    }

    // ---- epilogue ----
    float i_lo = 1.f / l_lo, i_hi = 1.f / l_hi;
    float a = alpha[layer*H_ + hh];
    size_t tok_lo = (size_t)(b*S_ + qi_lo);
#pragma unroll
    for (int j = 0; j < 8; j++) {
        int col = hh*DH_ + j*8 + 2*(lane & 3);
        float2 fh_lo = __half22float2(*(const __half2*)(Hn + tok_lo*D_ + col));
        float2 fh_hi = __half22float2(*(const __half2*)(Hn + (tok_lo+8)*D_ + col));
        __half2 o_lo = __floats2half2_rn(o[j][0]*i_lo + a*fh_lo.x,
                                         o[j][1]*i_lo + a*fh_lo.y);
        __half2 o_hi = __floats2half2_rn(o[j][2]*i_hi + a*fh_hi.x,
                                         o[j][3]*i_hi + a*fh_hi.y);
        *(__half2*)(O + tok_lo*D_ + col)     = o_lo;
        *(__half2*)(O + (tok_lo+8)*D_ + col) = o_hi;
    }
}

// ---------------- launch ----------------
extern "C" void kernel_launch(void* const* d_in, const int* in_sizes, int n_in,
                              void* d_out, int out_size)
{
    const int*   ids    = (const int*)  d_in[0];
    const void*  emb_t  = d_in[1];
    const float* emb_s  = (const float*)d_in[2];
    const void*  qt_    = d_in[3];
    const float* qs_    = (const float*)d_in[4];
    const void*  kt_    = d_in[5];
    const float* ks_    = (const float*)d_in[6];
    const void*  vt_    = d_in[7];
    const float* vs_    = (const float*)d_in[8];
    const void*  ot_    = d_in[9];
    const float* os_    = (const float*)d_in[10];
    const void*  gatet  = d_in[11];
    const float* gates  = (const float*)d_in[12];
    const void*  upt    = d_in[13];
    const float* ups    = (const float*)d_in[14];
    const void*  downt  = d_in[15];
    const float* downs  = (const float*)d_in[16];
    const float* wa     = (const float*)d_in[17];
    const float* wm     = (const float*)d_in[18];
    const float* alpha  = (const float*)d_in[19];
    const float* wf     = (const float*)d_in[20];
    const void*  headt  = d_in[21];
    const float* heads  = (const float*)d_in[22];
    float* out = (float*)d_out;

    float *x, *scqkv, *scgu;
    __half *qkv, *hh, *oh, *gh, *wh;
    cudaGetSymbolAddress((void**)&x,    g_x);
    cudaGetSymbolAddress((void**)&qkv,  g_qkv);
    cudaGetSymbolAddress((void**)&hh,   g_hh);
    cudaGetSymbolAddress((void**)&oh,   g_oh);
    cudaGetSymbolAddress((void**)&gh,   g_gh);
    cudaGetSymbolAddress((void**)&wh,   g_wh);
    cudaGetSymbolAddress((void**)&scqkv,g_scqkv);
    cudaGetSymbolAddress((void**)&scgu, g_scgu);

    const size_t wDD = (size_t)D_*D_;          // 1M
    const size_t wFD = (size_t)DFF_*D_;        // 4M
    const size_t sDD = wDD/GS_;                // 8192
    const size_t sFD = wFD/GS_;                // 32768

    detect_fmt_kernel<<<1, 1>>>(emb_t);

    const int CB = 256;
    for (int l = 0; l < L_; l++) {
        convert_w <<<wDD/4096, CB>>>(qt_,   l*wDD, wh + OFF_QKV + l*3*wDD,          (int)wDD);
        convert_w <<<wDD/4096, CB>>>(kt_,   l*wDD, wh + OFF_QKV + l*3*wDD + wDD,    (int)wDD);
        convert_w <<<wDD/4096, CB>>>(vt_,   l*wDD, wh + OFF_QKV + l*3*wDD + 2*wDD,  (int)wDD);
        convert_w <<<wDD/4096, CB>>>(ot_,   l*wDD, wh + OFF_O   + l*wDD,            (int)wDD);
        convert_w2<<<wFD/4096, CB>>>(gatet, l*wFD, wh + OFF_GU  + l*2*wFD, (int)wFD, 0);
        convert_w2<<<wFD/4096, CB>>>(upt,   l*wFD, wh + OFF_GU  + l*2*wFD, (int)wFD, 1);
        convert_w <<<wFD/4096, CB>>>(downt, l*wFD, wh + OFF_DN  + l*wFD,            (int)wFD);
        cudaMemcpyAsync(scqkv + l*3*sDD,         qs_ + l*sDD, sDD*4, cudaMemcpyDeviceToDevice, 0);
        cudaMemcpyAsync(scqkv + l*3*sDD +   sDD, ks_ + l*sDD, sDD*4, cudaMemcpyDeviceToDevice, 0);
        cudaMemcpyAsync(scqkv + l*3*sDD + 2*sDD, vs_ + l*sDD, sDD*4, cudaMemcpyDeviceToDevice, 0);
        interleave_sc<<<(sFD + 255)/256, CB>>>(gates + l*sFD, scgu + l*2*sFD, (int)sFD, 0);
        interleave_sc<<<(sFD + 255)/256, CB>>>(ups   + l*sFD, scgu + l*2*sFD, (int)sFD, 1);
    }
    convert_w<<<(V_*(size_t)D_)/4096, CB>>>(headt, 0, wh + OFF_HD, V_*D_);

    embed_kernel<<<NT_, 256>>>(ids, emb_t, emb_s, x);

    dim3 g_qkvp(NT_/BM, 3*D_/BN);    // 16 x 24
    dim3 g_op  (NT_/BM, D_/BN);      // 16 x 8
    dim3 g_gup (NT_/BM, 2*DFF_/BN);  // 16 x 64
    dim3 g_hd  (NT_/BM, V_/BN);      // 16 x 250

    for (int l = 0; l < L_; l++) {
        rmsnorm_kernel<<<NT_, 256>>>(x, wa + (size_t)l*D_, hh);
        gemm_async<2><<<g_qkvp, 256>>>(hh, wh + OFF_QKV + l*3*wDD, scqkv + l*3*sDD,
                                       qkv, NT_, 3*D_, D_);
        attn_mma<<<dim3(S_/AQ, H_, B_), 128>>>(qkv, hh, alpha, oh, l);
        gemm_async<1><<<g_op, 256>>>(oh, wh + OFF_O + l*wDD, os_ + l*sDD,
                                     x, NT_, D_, D_);

        rmsnorm_kernel<<<NT_, 256>>>(x, wm + (size_t)l*D_, hh);
        gemm_async<3><<<g_gup, 256>>>(hh, wh + OFF_GU + l*2*wFD, scgu + l*2*sFD,
                                      gh, NT_, 2*DFF_, D_);
        gemm_async<1><<<g_op, 256>>>(gh, wh + OFF_DN + l*wFD, downs + l*sFD,
                                     x, NT_, D_, DFF_);
    }
    rmsnorm_kernel<<<NT_, 256>>>(x, wf, hh);
    gemm_async<0><<<g_hd, 256>>>(hh, wh + OFF_HD, heads, out, NT_, V_, D_);
}

// round 12
// speedup vs baseline: 10.3960x; 1.0434x over previous
#include <cuda_runtime.h>
#include <cuda_fp16.h>
#include <cuda_bf16.h>
#include <cstdint>

// ---------------- dims ----------------
#define B_  2
#define S_  1024
#define D_  1024
#define H_  16
#define DH_ 64
#define DFF_ 4096
#define L_  2
#define V_  32000
#define GS_ 128
#define NT_ (B_*S_)   // 2048 tokens

// weight regions in g_wh (element offsets, halves)
#define OFF_QKV 0ull                       // 2 layers x 3M
#define OFF_O   (6ull*1024*1024)           // 2 x 1M
#define OFF_GU  (8ull*1024*1024)           // 2 x 8M (interleaved gate/up)
#define OFF_DN  (24ull*1024*1024)          // 2 x 4M
#define OFF_HD  (32ull*1024*1024)          // 32.77M
#define WH_TOT  (64ull*1024*1024)

// ---------------- scratch ----------------
__device__ __align__(16) float  g_x  [NT_*D_];
__device__ __align__(16) __half g_qkv[NT_*3*D_];
__device__ __align__(16) __half g_hh [NT_*D_];
__device__ __align__(16) __half g_oh [NT_*D_];
__device__ __align__(16) __half g_gh [NT_*DFF_];
__device__ __align__(16) __half g_wh [WH_TOT];
__device__ float g_scqkv[2*3*8192];
__device__ float g_scgu [2*2*32768];       // interleaved gate/up scales
__device__ int   g_wfmt;   // 0=int8, 1=int32, 2=bf16

// ---------------- weight format detector ----------------
__global__ void detect_fmt_kernel(const void* __restrict__ w)
{
    const unsigned* u = (const unsigned*)w;
    bool i32 = true, b16 = true;
    for (int i = 0; i < 64; i++) {
        unsigned x = u[i];
        if (!(x == 0u || x == 1u || x == 0xFFFFFFFFu)) i32 = false;
        unsigned lo = x & 0xFFFFu, hi = x >> 16;
        bool lok = (lo == 0u || lo == 0x3F80u || lo == 0xBF80u);
        bool hok = (hi == 0u || hi == 0x3F80u || hi == 0xBF80u);
        if (!(lok && hok)) b16 = false;
    }
    g_wfmt = i32 ? 1 : (b16 ? 2 : 0);
}

__device__ __forceinline__ void load_w4(const void* W, size_t idx, int fmt,
                                        float& w0, float& w1, float& w2, float& w3)
{
    if (fmt == 1) {
        int4 wv = *(const int4*)((const int*)W + idx);
        w0 = (float)wv.x; w1 = (float)wv.y; w2 = (float)wv.z; w3 = (float)wv.w;
    } else if (fmt == 2) {
        uint2 v = *(const uint2*)((const __nv_bfloat16*)W + idx);
        w0 = __bfloat162float(__ushort_as_bfloat16((unsigned short)( v.x        & 0xFFFFu)));
        w1 = __bfloat162float(__ushort_as_bfloat16((unsigned short)( v.x >> 16          )));
        w2 = __bfloat162float(__ushort_as_bfloat16((unsigned short)( v.y        & 0xFFFFu)));
        w3 = __bfloat162float(__ushort_as_bfloat16((unsigned short)( v.y >> 16          )));
    } else {
        int wv = *(const int*)((const int8_t*)W + idx);
        w0 = (float)(int8_t)( wv         & 0xff);
        w1 = (float)(int8_t)((wv >> 8 )  & 0xff);
        w2 = (float)(int8_t)((wv >> 16)  & 0xff);
        w3 = (float)(int8_t)( wv >> 24         );
    }
}

// ---------------- fused weight conversion (single launch) ----------------
#define NSEG 15
struct ConvSegs {
    const void*        src[NSEG];
    unsigned long long srcOff[NSEG];   // element offset in source tensor
    unsigned long long dstOff[NSEG];   // half offset in g_wh
    int                mode[NSEG];     // 0 plain, 1 interleave-even, 2 interleave-odd
    int                chunkEnd[NSEG]; // exclusive prefix in 16-elem chunks
    int                total;          // total chunks
};

__global__ void convert_all(ConvSegs P, __half* __restrict__ dst)
{
    const int fmt = g_wfmt;
    for (int chunk = blockIdx.x * blockDim.x + threadIdx.x; chunk < P.total;
         chunk += gridDim.x * blockDim.x) {
        int s = 0;
        while (chunk >= P.chunkEnd[s]) s++;
        int start = (s == 0) ? 0 : P.chunkEnd[s - 1];
        size_t i = (size_t)(chunk - start) * 16;

        float w[16];
#pragma unroll
        for (int j = 0; j < 4; j++)
            load_w4(P.src[s], P.srcOff[s] + i + j*4, fmt,
                    w[j*4], w[j*4+1], w[j*4+2], w[j*4+3]);
        uint32_t h[8];
#pragma unroll
        for (int j = 0; j < 8; j++) {
            __half2 p = __floats2half2_rn(w[2*j], w[2*j+1]);
            h[j] = *(uint32_t*)&p;
        }
        size_t di;
        int mode = P.mode[s];
        if (mode == 0) {
            di = (size_t)P.dstOff[s] + i;
        } else {
            size_t row = i >> 10, col = i & 1023;
            di = (size_t)P.dstOff[s] + ((2*row + (mode - 1)) << 10) + col;
        }
        *(uint4*)&dst[di]     = make_uint4(h[0], h[1], h[2], h[3]);
        *(uint4*)&dst[di + 8] = make_uint4(h[4], h[5], h[6], h[7]);
    }
}

// ---------------- scale packing (single launch) ----------------
// scqkv[l*24576 + which*8192 + j]; scgu interleaved rows (2*row+which)*8+g
__global__ void pack_scales(const float* __restrict__ qs, const float* __restrict__ ks,
                            const float* __restrict__ vs, const float* __restrict__ gs,
                            const float* __restrict__ us,
                            float* __restrict__ scqkv, float* __restrict__ scgu)
{
    int i = blockIdx.x * 256 + threadIdx.x;
    if (i < 49152) {
        int l = i / 24576, r = i % 24576;
        int which = r / 8192, j = r % 8192;
        const float* sp = (which == 0) ? qs : ((which == 1) ? ks : vs);
        scqkv[i] = sp[l*8192 + j];
    } else if (i < 180224) {
        int k = i - 49152;
        int l = k / 65536, r = k % 65536;
        int which = r / 32768, j = r % 32768;
        int row = j >> 3, g = j & 7;
        scgu[l*65536 + ((2*row + which) << 3) + g] = (which ? us : gs)[l*32768 + j];
    }
}

// ---------------- embedding gather + dequant ----------------
__global__ void embed_kernel(const int* __restrict__ ids,
                             const void* __restrict__ et,
                             const float* __restrict__ es,
                             float* __restrict__ X)
{
    int token = blockIdx.x;
    int id = ids[token];
    int d0 = threadIdx.x * 4;
    int fmt = g_wfmt;
    float w0, w1, w2, w3;
    load_w4(et, (size_t)id * D_ + d0, fmt, w0, w1, w2, w3);
    float s = es[id * (D_/GS_) + (d0 >> 7)];
    *(float4*)(X + (size_t)token * D_ + d0) = make_float4(w0*s, w1*s, w2*s, w3*s);
}

// ---------------- rmsnorm (f32 in, f16 out) ----------------
__global__ void rmsnorm_kernel(const float* __restrict__ X,
                               const float* __restrict__ w,
                               __half* __restrict__ Y)
{
    int row = blockIdx.x;
    const float* x = X + (size_t)row * D_;
    float ss = 0.f;
    float vals[4];
#pragma unroll
    for (int j = 0; j < 4; j++) {
        vals[j] = x[threadIdx.x + j*256];
        ss += vals[j]*vals[j];
    }
    __shared__ float red[256];
    red[threadIdx.x] = ss;
    __syncthreads();
    for (int s = 128; s > 0; s >>= 1) {
        if (threadIdx.x < s) red[threadIdx.x] += red[threadIdx.x + s];
        __syncthreads();
    }
    float rs = rsqrtf(red[0] * (1.0f/(float)D_) + 1e-6f);
#pragma unroll
    for (int j = 0; j < 4; j++) {
        int d = threadIdx.x + j*256;
        Y[(size_t)row * D_ + d] = __float2half(vals[j] * rs * w[d]);
    }
}

// ---------------- mma helpers ----------------
__device__ __forceinline__ void mma16816(float* c, const uint32_t* a, const uint32_t* b)
{
    asm volatile(
        "mma.sync.aligned.m16n8k16.row.col.f32.f16.f16.f32 "
        "{%0,%1,%2,%3}, {%4,%5,%6,%7}, {%8,%9}, {%0,%1,%2,%3};\n"
        : "+f"(c[0]), "+f"(c[1]), "+f"(c[2]), "+f"(c[3])
        : "r"(a[0]), "r"(a[1]), "r"(a[2]), "r"(a[3]), "r"(b[0]), "r"(b[1]));
}
__device__ __forceinline__ void cp16(uint32_t dst, const void* src)
{
    asm volatile("cp.async.cg.shared.global [%0], [%1], 16;\n" :: "r"(dst), "l"(src));
}
__device__ __forceinline__ void ldm_x4(uint32_t& r0, uint32_t& r1, uint32_t& r2, uint32_t& r3,
                                       uint32_t addr)
{
    asm volatile("ldmatrix.sync.aligned.m8n8.x4.shared.b16 {%0,%1,%2,%3}, [%4];"
                 : "=r"(r0), "=r"(r1), "=r"(r2), "=r"(r3) : "r"(addr));
}
__device__ __forceinline__ uint32_t smem_u32(const void* p) {
    return (uint32_t)__cvta_generic_to_shared(p);
}

// ---------------- async HMMA GEMM (3-stage, 1 barrier/iter) ----------------
// OP=0: f32 store.  OP=1: f32 accumulate.  OP=2: f16 store.
// OP=3: fused silu(gate)*up -> f16 [M, N/2] (weights interleaved gate/up).
#define BM 128
#define BN 128
#define BKT 32
#define STAGE_B (BM*BKT*2)   // 8192 bytes per stage per tile

template<int OP>
__global__ void __launch_bounds__(256, 2)
gemm_async(const __half* __restrict__ A, const __half* __restrict__ Wh,
           const float* __restrict__ Sc, void* __restrict__ Cv,
           int M, int N, int K)
{
    __shared__ __align__(16) __half As[3][BM*BKT];   // 24 KB
    __shared__ __align__(16) __half Bs[3][BN*BKT];   // 24 KB  (total 48 KB)

    const int tid  = threadIdx.x;
    const int lane = tid & 31;
    const int wid  = tid >> 5;
    const int warp_m = wid >> 2;            // 0..1 (64 rows)
    const int warp_n = wid & 3;             // 0..3 (32 cols)
    const int m0 = blockIdx.x * BM;
    const int n0 = blockIdx.y * BN;
    const int ngroups = K >> 7;
    const int gid = lane >> 2, tig = lane & 3;

    const uint32_t sa = smem_u32(&As[0][0]);
    const uint32_t sb = smem_u32(&Bs[0][0]);

    const int a_row  = lane & 15;
    const int a_sel  = lane >> 4;
    const int a_xor  = ((lane & 15) >> 1) & 3;
    const int b_roff = ((lane >> 4) << 3) + (lane & 7);
    const int b_sel  = (lane >> 3) & 1;
    const int b_xor  = (b_roff >> 1) & 3;

    float acc[4][4][4] = {};
    float s_cur[4][2];
    float s_nxt[4][2];

    const int iters = K / BKT;

    auto issue = [&](int stage, int k0) {
        uint32_t ab = sa + stage * STAGE_B;
        uint32_t bb = sb + stage * STAGE_B;
#pragma unroll
        for (int j = 0; j < 2; j++) {
            int c = tid + j*256;
            int row = c >> 2, ch = c & 3;
            int pch = ch ^ ((row >> 1) & 3);
            cp16(ab + row*64 + pch*16, A  + (size_t)(m0+row)*K + k0 + ch*8);
        }
#pragma unroll
        for (int j = 0; j < 2; j++) {
            int c = tid + j*256;
            int row = c >> 2, ch = c & 3;
            int pch = ch ^ ((row >> 1) & 3);
            cp16(bb + row*64 + pch*16, Wh + (size_t)(n0+row)*K + k0 + ch*8);
        }
        asm volatile("cp.async.commit_group;\n");
    };

    issue(0, 0);
    issue(1, BKT);

    int stage = 0;
    for (int it = 0; it < iters; it++) {
        if (it + 1 < iters) asm volatile("cp.async.wait_group 1;\n");
        else                asm volatile("cp.async.wait_group 0;\n");
        __syncthreads();

        // group boundary: rescale accumulators; prefetch next group's scales
        if ((it & 3) == 0) {
            int g = it >> 2;
#pragma unroll
            for (int nt = 0; nt < 4; nt++) {
                int nc = warp_n*32 + nt*8 + 2*tig;
                float ns0, ns1;
                if (g == 0) {
                    ns0 = Sc[(size_t)(n0 + nc)    *ngroups];
                    ns1 = Sc[(size_t)(n0 + nc + 1)*ngroups];
                } else {
                    ns0 = s_nxt[nt][0]; ns1 = s_nxt[nt][1];
                }
                if (it) {
                    float r0 = __fdividef(s_cur[nt][0], ns0);
                    float r1 = __fdividef(s_cur[nt][1], ns1);
#pragma unroll
                    for (int mt = 0; mt < 4; mt++) {
                        acc[mt][nt][0] *= r0; acc[mt][nt][1] *= r1;
                        acc[mt][nt][2] *= r0; acc[mt][nt][3] *= r1;
                    }
                }
                s_cur[nt][0] = ns0; s_cur[nt][1] = ns1;
            }
            if (g + 1 < ngroups) {
#pragma unroll
                for (int nt = 0; nt < 4; nt++) {
                    int nc = warp_n*32 + nt*8 + 2*tig;
                    s_nxt[nt][0] = Sc[(size_t)(n0 + nc)    *ngroups + g + 1];
                    s_nxt[nt][1] = Sc[(size_t)(n0 + nc + 1)*ngroups + g + 1];
                }
            }
        }

        const uint32_t ab = sa + stage * STAGE_B;
        const uint32_t bb = sb + stage * STAGE_B;
#pragma unroll
        for (int kk = 0; kk < 2; kk++) {
            uint32_t af[4][4];
#pragma unroll
            for (int mt = 0; mt < 4; mt++) {
                int row = warp_m*64 + mt*16 + a_row;
                int pch = (kk*2 + a_sel) ^ a_xor;
                ldm_x4(af[mt][0], af[mt][1], af[mt][2], af[mt][3],
                       ab + row*64 + pch*16);
            }
            uint32_t bf[4][2];
#pragma unroll
            for (int p = 0; p < 2; p++) {
                int row = warp_n*32 + p*16 + b_roff;
                int pch = (kk*2 + b_sel) ^ b_xor;
                uint32_t r0, r1, r2, r3;
                ldm_x4(r0, r1, r2, r3, bb + row*64 + pch*16);
                bf[2*p  ][0] = r0; bf[2*p  ][1] = r1;
                bf[2*p+1][0] = r2; bf[2*p+1][1] = r3;
            }
#pragma unroll
            for (int mt = 0; mt < 4; mt++)
#pragma unroll
                for (int nt = 0; nt < 4; nt++)
                    mma16816(acc[mt][nt], af[mt], bf[nt]);
        }

        if (it + 2 < iters) issue((stage + 2 >= 3) ? stage - 1 : stage + 2, (it + 2) * BKT);
        stage = (stage + 1 == 3) ? 0 : stage + 1;
    }

    // ---- epilogue ----
#pragma unroll
    for (int mt = 0; mt < 4; mt++) {
        int r = m0 + warp_m*64 + mt*16 + gid;
#pragma unroll
        for (int nt = 0; nt < 4; nt++) {
            int c = n0 + warp_n*32 + nt*8 + 2*tig;
            float s0 = s_cur[nt][0], s1 = s_cur[nt][1];
            float v00 = acc[mt][nt][0]*s0, v01 = acc[mt][nt][1]*s1;
            float v10 = acc[mt][nt][2]*s0, v11 = acc[mt][nt][3]*s1;
            if (OP == 0 || OP == 1) {
                float* C = (float*)Cv;
                float* p0 = C + (size_t)r*N + c;
                float* p1 = C + (size_t)(r+8)*N + c;
                float2 v0 = make_float2(v00, v01);
                float2 v1 = make_float2(v10, v11);
                if (OP == 1) {
                    float2 o0 = *(float2*)p0, o1 = *(float2*)p1;
                    v0.x += o0.x; v0.y += o0.y; v1.x += o1.x; v1.y += o1.y;
                }
                *(float2*)p0 = v0;
                *(float2*)p1 = v1;
            } else if (OP == 2) {
                __half* C = (__half*)Cv;
                *(__half2*)(C + (size_t)r*N + c)     = __floats2half2_rn(v00, v01);
                *(__half2*)(C + (size_t)(r+8)*N + c) = __floats2half2_rn(v10, v11);
            } else {
                __half* C = (__half*)Cv;
                int oN = N >> 1, oc = c >> 1;
                float o0 = v00 / (1.f + __expf(-v00)) * v01;
                float o1 = v10 / (1.f + __expf(-v10)) * v11;
                C[(size_t)r*oN + oc]     = __float2half(o0);
                C[(size_t)(r+8)*oN + oc] = __float2half(o1);
            }
        }
    }
}

// ---------------- mma flash attention + per-head residual ----------------
#define AQ 64
#define QKVS (3*D_)
__global__ void __launch_bounds__(128)
attn_mma(const __half* __restrict__ QKV, const __half* __restrict__ Hn,
         const float* __restrict__ alpha, __half* __restrict__ O, int layer)
{
    __shared__ __align__(16) __half Qs[AQ][72];
    __shared__ __align__(16) __half Ks[AQ][72];
    __shared__ __align__(16) __half Vt[AQ][72];   // Vt[dh][key]

    const int tid = threadIdx.x, lane = tid & 31, wid = tid >> 5;
    const int qt = blockIdx.x, hh = blockIdx.y, b = blockIdx.z;
    const int q0 = qt * AQ;

    for (int t = tid; t < AQ*8; t += 128) {
        int r = t >> 3, c8 = t & 7;
        *(uint4*)&Qs[r][c8*8] =
            *(const uint4*)(QKV + ((size_t)(b*S_ + q0 + r))*QKVS + hh*DH_ + c8*8);
    }
    __syncthreads();

    uint32_t qf[4][4];
    {
        int rr = wid*16 + (lane & 15);
        int cc = ((lane >> 4) & 1) * 8;
#pragma unroll
        for (int ks = 0; ks < 4; ks++)
            ldm_x4(qf[ks][0], qf[ks][1], qf[ks][2], qf[ks][3],
                   smem_u32(&Qs[rr][ks*16 + cc]));
    }

    float o[8][4] = {};
    float m_lo = -1e30f, m_hi = -1e30f, l_lo = 0.f, l_hi = 0.f;
    const int qi_lo = q0 + wid*16 + (lane >> 2);
    const int qi_hi = qi_lo + 8;
    const int row_off = ((lane >> 4) << 3) + (lane & 7);
    const int col_sel = ((lane >> 3) & 1) * 8;

    for (int t0 = 0; t0 < q0 + AQ; t0 += AQ) {
        __syncthreads();
        for (int t = tid; t < AQ*8; t += 128) {
            int r = t >> 3, c8 = t & 7;
            const __half* base = QKV + ((size_t)(b*S_ + t0 + r))*QKVS + hh*DH_ + c8*8;
            *(uint4*)&Ks[r][c8*8] = *(const uint4*)(base + D_);
            uint4 raw = *(const uint4*)(base + 2*D_);
            const __half* hp = (const __half*)&raw;
#pragma unroll
            for (int d = 0; d < 8; d++) Vt[c8*8 + d][r] = hp[d];
        }
        __syncthreads();

        float sacc[8][4] = {};
#pragma unroll
        for (int ks = 0; ks < 4; ks++) {
#pragma unroll
            for (int jp = 0; jp < 4; jp++) {
                uint32_t r0, r1, r2, r3;
                ldm_x4(r0, r1, r2, r3, smem_u32(&Ks[jp*16 + row_off][ks*16 + col_sel]));
                uint32_t bA[2] = {r0, r1};
                uint32_t bB[2] = {r2, r3};
                mma16816(sacc[2*jp  ], qf[ks], bA);
                mma16816(sacc[2*jp+1], qf[ks], bB);
            }
        }

        float mx_lo = -1e30f, mx_hi = -1e30f;
#pragma unroll
        for (int j = 0; j < 8; j++) {
            int kb = t0 + j*8 + 2*(lane & 3);
            sacc[j][0] = (kb     <= qi_lo) ? sacc[j][0]*0.125f : -1e30f;
            sacc[j][1] = (kb + 1 <= qi_lo) ? sacc[j][1]*0.125f : -1e30f;
            sacc[j][2] = (kb     <= qi_hi) ? sacc[j][2]*0.125f : -1e30f;
            sacc[j][3] = (kb + 1 <= qi_hi) ? sacc[j][3]*0.125f : -1e30f;
            mx_lo = fmaxf(mx_lo, fmaxf(sacc[j][0], sacc[j][1]));
            mx_hi = fmaxf(mx_hi, fmaxf(sacc[j][2], sacc[j][3]));
        }
        mx_lo = fmaxf(mx_lo, __shfl_xor_sync(0xffffffffu, mx_lo, 1));
        mx_lo = fmaxf(mx_lo, __shfl_xor_sync(0xffffffffu, mx_lo, 2));
        mx_hi = fmaxf(mx_hi, __shfl_xor_sync(0xffffffffu, mx_hi, 1));
        mx_hi = fmaxf(mx_hi, __shfl_xor_sync(0xffffffffu, mx_hi, 2));

        float mn_lo = fmaxf(m_lo, mx_lo), mn_hi = fmaxf(m_hi, mx_hi);
        float c_lo = __expf(m_lo - mn_lo), c_hi = __expf(m_hi - mn_hi);
        m_lo = mn_lo; m_hi = mn_hi;
        l_lo *= c_lo; l_hi *= c_hi;
#pragma unroll
        for (int j = 0; j < 8; j++) {
            o[j][0] *= c_lo; o[j][1] *= c_lo;
            o[j][2] *= c_hi; o[j][3] *= c_hi;
        }

        uint32_t pa[8], pb[8];
        float ps_lo = 0.f, ps_hi = 0.f;
#pragma unroll
        for (int j = 0; j < 8; j++) {
            float e0 = __expf(sacc[j][0] - mn_lo);
            float e1 = __expf(sacc[j][1] - mn_lo);
            float e2 = __expf(sacc[j][2] - mn_hi);
            float e3 = __expf(sacc[j][3] - mn_hi);
            ps_lo += e0 + e1; ps_hi += e2 + e3;
            __half2 hl = __floats2half2_rn(e0, e1);
            __half2 hb = __floats2half2_rn(e2, e3);
            pa[j] = *(uint32_t*)&hl;
            pb[j] = *(uint32_t*)&hb;
        }
        ps_lo += __shfl_xor_sync(0xffffffffu, ps_lo, 1);
        ps_lo += __shfl_xor_sync(0xffffffffu, ps_lo, 2);
        ps_hi += __shfl_xor_sync(0xffffffffu, ps_hi, 1);
        ps_hi += __shfl_xor_sync(0xffffffffu, ps_hi, 2);
        l_lo += ps_lo; l_hi += ps_hi;

#pragma unroll
        for (int kk = 0; kk < 4; kk++) {
            uint32_t af[4] = {pa[2*kk], pb[2*kk], pa[2*kk+1], pb[2*kk+1]};
#pragma unroll
            for (int dp = 0; dp < 4; dp++) {
                uint32_t r0, r1, r2, r3;
                ldm_x4(r0, r1, r2, r3, smem_u32(&Vt[dp*16 + row_off][kk*16 + col_sel]));
                uint32_t bA[2] = {r0, r1};
                uint32_t bB[2] = {r2, r3};
                mma16816(o[2*dp  ], af, bA);
                mma16816(o[2*dp+1], af, bB);
            }
        }
    }

    float i_lo = 1.f / l_lo, i_hi = 1.f / l_hi;
    float a = alpha[layer*H_ + hh];
    size_t tok_lo = (size_t)(b*S_ + qi_lo);
#pragma unroll
    for (int j = 0; j < 8; j++) {
        int col = hh*DH_ + j*8 + 2*(lane & 3);
        float2 fh_lo = __half22float2(*(const __half2*)(Hn + tok_lo*D_ + col));
        float2 fh_hi = __half22float2(*(const __half2*)(Hn + (tok_lo+8)*D_ + col));
        __half2 o_lo = __floats2half2_rn(o[j][0]*i_lo + a*fh_lo.x,
                                         o[j][1]*i_lo + a*fh_lo.y);
        __half2 o_hi = __floats2half2_rn(o[j][2]*i_hi + a*fh_hi.x,
                                         o[j][3]*i_hi + a*fh_hi.y);
        *(__half2*)(O + tok_lo*D_ + col)     = o_lo;
        *(__half2*)(O + (tok_lo+8)*D_ + col) = o_hi;
    }
}

// ---------------- launch ----------------
extern "C" void kernel_launch(void* const* d_in, const int* in_sizes, int n_in,
                              void* d_out, int out_size)
{
    const int*   ids    = (const int*)  d_in[0];
    const void*  emb_t  = d_in[1];
    const float* emb_s  = (const float*)d_in[2];
    const void*  qt_    = d_in[3];
    const float* qs_    = (const float*)d_in[4];
    const void*  kt_    = d_in[5];
    const float* ks_    = (const float*)d_in[6];
    const void*  vt_    = d_in[7];
    const float* vs_    = (const float*)d_in[8];
    const void*  ot_    = d_in[9];
    const float* os_    = (const float*)d_in[10];
    const void*  gatet  = d_in[11];
    const float* gates  = (const float*)d_in[12];
    const void*  upt    = d_in[13];
    const float* ups    = (const float*)d_in[14];
    const void*  downt  = d_in[15];
    const float* downs  = (const float*)d_in[16];
    const float* wa     = (const float*)d_in[17];
    const float* wm     = (const float*)d_in[18];
    const float* alpha  = (const float*)d_in[19];
    const float* wf     = (const float*)d_in[20];
    const void*  headt  = d_in[21];
    const float* heads  = (const float*)d_in[22];
    float* out = (float*)d_out;

    float *x, *scqkv, *scgu;
    __half *qkv, *hh, *oh, *gh, *wh;
    cudaGetSymbolAddress((void**)&x,    g_x);
    cudaGetSymbolAddress((void**)&qkv,  g_qkv);
    cudaGetSymbolAddress((void**)&hh,   g_hh);
    cudaGetSymbolAddress((void**)&oh,   g_oh);
    cudaGetSymbolAddress((void**)&gh,   g_gh);
    cudaGetSymbolAddress((void**)&wh,   g_wh);
    cudaGetSymbolAddress((void**)&scqkv,g_scqkv);
    cudaGetSymbolAddress((void**)&scgu, g_scgu);

    const size_t wDD = (size_t)D_*D_;          // 1M
    const size_t wFD = (size_t)DFF_*D_;        // 4M
    const size_t sDD = wDD/GS_;                // 8192
    const size_t sFD = wFD/GS_;                // 32768

    // launch #1
    detect_fmt_kernel<<<1, 1>>>(emb_t);

    // launch #2: fused weight conversion
    ConvSegs P;
    {
        int c = 0, seg = 0;
        auto add = [&](const void* src, size_t soff, size_t doff, int nelems, int mode) {
            P.src[seg] = src; P.srcOff[seg] = soff; P.dstOff[seg] = doff;
            P.mode[seg] = mode; c += nelems / 16; P.chunkEnd[seg] = c; seg++;
        };
        for (int l = 0; l < L_; l++) {
            add(qt_,   l*wDD, OFF_QKV + l*3*wDD,         (int)wDD, 0);
            add(kt_,   l*wDD, OFF_QKV + l*3*wDD + wDD,   (int)wDD, 0);
            add(vt_,   l*wDD, OFF_QKV + l*3*wDD + 2*wDD, (int)wDD, 0);
            add(ot_,   l*wDD, OFF_O   + l*wDD,           (int)wDD, 0);
            add(gatet, l*wFD, OFF_GU  + l*2*wFD,         (int)wFD, 1);
            add(upt,   l*wFD, OFF_GU  + l*2*wFD,         (int)wFD, 2);
            add(downt, l*wFD, OFF_DN  + l*wFD,           (int)wFD, 0);
        }
        add(headt, 0, OFF_HD, V_*D_, 0);
        P.total = c;
    }
    convert_all<<<(P.total + 255)/256, 256>>>(P, wh);

    // launch #3: scale packing
    pack_scales<<<(180224 + 255)/256, 256>>>(qs_, ks_, vs_, gates, ups, scqkv, scgu);

    // launch #4
    embed_kernel<<<NT_, 256>>>(ids, emb_t, emb_s, x);

    dim3 g_qkvp(NT_/BM, 3*D_/BN);    // 16 x 24
    dim3 g_op  (NT_/BM, D_/BN);      // 16 x 8
    dim3 g_gup (NT_/BM, 2*DFF_/BN);  // 16 x 64
    dim3 g_hd  (NT_/BM, V_/BN);      // 16 x 250

    for (int l = 0; l < L_; l++) {
        // launch #5 (l=0): rmsnorm; launch #6: qkv GEMM (ncu -s 5 target)
        rmsnorm_kernel<<<NT_, 256>>>(x, wa + (size_t)l*D_, hh);
        gemm_async<2><<<g_qkvp, 256>>>(hh, wh + OFF_QKV + l*3*wDD, scqkv + l*3*sDD,
                                       qkv, NT_, 3*D_, D_);
        attn_mma<<<dim3(S_/AQ, H_, B_), 128>>>(qkv, hh, alpha, oh, l);
        gemm_async<1><<<g_op, 256>>>(oh, wh + OFF_O + l*wDD, os_ + l*sDD,
                                     x, NT_, D_, D_);

        rmsnorm_kernel<<<NT_, 256>>>(x, wm + (size_t)l*D_, hh);
        gemm_async<3><<<g_gup, 256>>>(hh, wh + OFF_GU + l*2*wFD, scgu + l*2*sFD,
                                      gh, NT_, 2*DFF_, D_);
        gemm_async<1><<<g_op, 256>>>(gh, wh + OFF_DN + l*wFD, downs + l*sFD,
                                     x, NT_, D_, DFF_);
    }
    rmsnorm_kernel<<<NT_, 256>>>(x, wf, hh);
    gemm_async<0><<<g_hd, 256>>>(hh, wh + OFF_HD, heads, out, NT_, V_, D_);
}

// round 13
// speedup vs baseline: 10.5816x; 1.0179x over previous
#include <cuda_runtime.h>
#include <cuda_fp16.h>
#include <cuda_bf16.h>
#include <cstdint>

// ---------------- dims ----------------
#define B_  2
#define S_  1024
#define D_  1024
#define H_  16
#define DH_ 64
#define DFF_ 4096
#define L_  2
#define V_  32000
#define GS_ 128
#define NT_ (B_*S_)   // 2048 tokens

// weight regions in g_wh (element offsets, halves)
#define OFF_QKV 0ull                       // 2 layers x 3M
#define OFF_O   (6ull*1024*1024)           // 2 x 1M
#define OFF_GU  (8ull*1024*1024)           // 2 x 8M (interleaved gate/up)
#define OFF_DN  (24ull*1024*1024)          // 2 x 4M
#define OFF_HD  (32ull*1024*1024)          // 32.77M
#define WH_TOT  (66ull*1024*1024)

// ---------------- scratch ----------------
__device__ __align__(16) float  g_x  [NT_*D_];
__device__ __align__(16) __half g_qkv[NT_*3*D_];
__device__ __align__(16) __half g_hh [NT_*D_];
__device__ __align__(16) __half g_oh [NT_*D_];
__device__ __align__(16) __half g_gh [NT_*DFF_];
__device__ __align__(16) __half g_wh [WH_TOT];
__device__ float g_scqkv[2*3*8192];
__device__ float g_scgu [2*2*32768];       // interleaved gate/up scales
__device__ int   g_wfmt;   // 0=int8, 1=int32, 2=bf16

// ---------------- weight format detector ----------------
__global__ void detect_fmt_kernel(const void* __restrict__ w)
{
    const unsigned* u = (const unsigned*)w;
    bool i32 = true, b16 = true;
    for (int i = 0; i < 64; i++) {
        unsigned x = u[i];
        if (!(x == 0u || x == 1u || x == 0xFFFFFFFFu)) i32 = false;
        unsigned lo = x & 0xFFFFu, hi = x >> 16;
        bool lok = (lo == 0u || lo == 0x3F80u || lo == 0xBF80u);
        bool hok = (hi == 0u || hi == 0x3F80u || hi == 0xBF80u);
        if (!(lok && hok)) b16 = false;
    }
    g_wfmt = i32 ? 1 : (b16 ? 2 : 0);
}

__device__ __forceinline__ void load_w4(const void* W, size_t idx, int fmt,
                                        float& w0, float& w1, float& w2, float& w3)
{
    if (fmt == 1) {
        int4 wv = *(const int4*)((const int*)W + idx);
        w0 = (float)wv.x; w1 = (float)wv.y; w2 = (float)wv.z; w3 = (float)wv.w;
    } else if (fmt == 2) {
        uint2 v = *(const uint2*)((const __nv_bfloat16*)W + idx);
        w0 = __bfloat162float(__ushort_as_bfloat16((unsigned short)( v.x        & 0xFFFFu)));
        w1 = __bfloat162float(__ushort_as_bfloat16((unsigned short)( v.x >> 16          )));
        w2 = __bfloat162float(__ushort_as_bfloat16((unsigned short)( v.y        & 0xFFFFu)));
        w3 = __bfloat162float(__ushort_as_bfloat16((unsigned short)( v.y >> 16          )));
    } else {
        int wv = *(const int*)((const int8_t*)W + idx);
        w0 = (float)(int8_t)( wv         & 0xff);
        w1 = (float)(int8_t)((wv >> 8 )  & 0xff);
        w2 = (float)(int8_t)((wv >> 16)  & 0xff);
        w3 = (float)(int8_t)( wv >> 24         );
    }
}

// ---------------- fused weight conversion ----------------
#define NSEG 14
struct ConvSegs {
    const void*        src[NSEG];
    unsigned long long srcOff[NSEG];   // element offset in source tensor
    unsigned long long dstOff[NSEG];   // half offset in g_wh
    int                mode[NSEG];     // 0 plain, 1 interleave-even, 2 interleave-odd
    int                chunkEnd[NSEG]; // exclusive prefix in 16-elem chunks
    int                total;          // total chunks
};

__global__ void convert_all(ConvSegs P, __half* __restrict__ dst)
{
    const int fmt = g_wfmt;
    for (int chunk = blockIdx.x * blockDim.x + threadIdx.x; chunk < P.total;
         chunk += gridDim.x * blockDim.x) {
        int s = 0;
        while (chunk >= P.chunkEnd[s]) s++;
        int start = (s == 0) ? 0 : P.chunkEnd[s - 1];
        size_t i = (size_t)(chunk - start) * 16;

        float w[16];
#pragma unroll
        for (int j = 0; j < 4; j++)
            load_w4(P.src[s], P.srcOff[s] + i + j*4, fmt,
                    w[j*4], w[j*4+1], w[j*4+2], w[j*4+3]);
        uint32_t h[8];
#pragma unroll
        for (int j = 0; j < 8; j++) {
            __half2 p = __floats2half2_rn(w[2*j], w[2*j+1]);
            h[j] = *(uint32_t*)&p;
        }
        size_t di;
        int mode = P.mode[s];
        if (mode == 0) {
            di = (size_t)P.dstOff[s] + i;
        } else {
            size_t row = i >> 10, col = i & 1023;
            di = (size_t)P.dstOff[s] + ((2*row + (mode - 1)) << 10) + col;
        }
        *(uint4*)&dst[di]     = make_uint4(h[0], h[1], h[2], h[3]);
        *(uint4*)&dst[di + 8] = make_uint4(h[4], h[5], h[6], h[7]);
    }
}

// ---------------- scale packing ----------------
__global__ void pack_scales(const float* __restrict__ qs, const float* __restrict__ ks,
                            const float* __restrict__ vs, const float* __restrict__ gs,
                            const float* __restrict__ us,
                            float* __restrict__ scqkv, float* __restrict__ scgu)
{
    int i = blockIdx.x * 256 + threadIdx.x;
    if (i < 49152) {
        int l = i / 24576, r = i % 24576;
        int which = r / 8192, j = r % 8192;
        const float* sp = (which == 0) ? qs : ((which == 1) ? ks : vs);
        scqkv[i] = sp[l*8192 + j];
    } else if (i < 180224) {
        int k = i - 49152;
        int l = k / 65536, r = k % 65536;
        int which = r / 32768, j = r % 32768;
        int row = j >> 3, g = j & 7;
        scgu[l*65536 + ((2*row + which) << 3) + g] = (which ? us : gs)[l*32768 + j];
    }
}

// ---------------- embedding gather + dequant ----------------
__global__ void embed_kernel(const int* __restrict__ ids,
                             const void* __restrict__ et,
                             const float* __restrict__ es,
                             float* __restrict__ X)
{
    int token = blockIdx.x;
    int id = ids[token];
    int d0 = threadIdx.x * 4;
    int fmt = g_wfmt;
    float w0, w1, w2, w3;
    load_w4(et, (size_t)id * D_ + d0, fmt, w0, w1, w2, w3);
    float s = es[id * (D_/GS_) + (d0 >> 7)];
    *(float4*)(X + (size_t)token * D_ + d0) = make_float4(w0*s, w1*s, w2*s, w3*s);
}

// ---------------- rmsnorm (f32 in, f16 out) ----------------
__global__ void rmsnorm_kernel(const float* __restrict__ X,
                               const float* __restrict__ w,
                               __half* __restrict__ Y)
{
    int row = blockIdx.x;
    const float* x = X + (size_t)row * D_;
    float ss = 0.f;
    float vals[4];
#pragma unroll
    for (int j = 0; j < 4; j++) {
        vals[j] = x[threadIdx.x + j*256];
        ss += vals[j]*vals[j];
    }
    __shared__ float red[256];
    red[threadIdx.x] = ss;
    __syncthreads();
    for (int s = 128; s > 0; s >>= 1) {
        if (threadIdx.x < s) red[threadIdx.x] += red[threadIdx.x + s];
        __syncthreads();
    }
    float rs = rsqrtf(red[0] * (1.0f/(float)D_) + 1e-6f);
#pragma unroll
    for (int j = 0; j < 4; j++) {
        int d = threadIdx.x + j*256;
        Y[(size_t)row * D_ + d] = __float2half(vals[j] * rs * w[d]);
    }
}

// ---------------- mma helpers ----------------
__device__ __forceinline__ void mma16816(float* c, const uint32_t* a, const uint32_t* b)
{
    asm volatile(
        "mma.sync.aligned.m16n8k16.row.col.f32.f16.f16.f32 "
        "{%0,%1,%2,%3}, {%4,%5,%6,%7}, {%8,%9}, {%0,%1,%2,%3};\n"
        : "+f"(c[0]), "+f"(c[1]), "+f"(c[2]), "+f"(c[3])
        : "r"(a[0]), "r"(a[1]), "r"(a[2]), "r"(a[3]), "r"(b[0]), "r"(b[1]));
}
__device__ __forceinline__ void cp16(uint32_t dst, const void* src)
{
    asm volatile("cp.async.cg.shared.global [%0], [%1], 16;\n" :: "r"(dst), "l"(src));
}
__device__ __forceinline__ void ldm_x4(uint32_t& r0, uint32_t& r1, uint32_t& r2, uint32_t& r3,
                                       uint32_t addr)
{
    asm volatile("ldmatrix.sync.aligned.m8n8.x4.shared.b16 {%0,%1,%2,%3}, [%4];"
                 : "=r"(r0), "=r"(r1), "=r"(r2), "=r"(r3) : "r"(addr));
}
__device__ __forceinline__ uint32_t smem_u32(const void* p) {
    return (uint32_t)__cvta_generic_to_shared(p);
}

// ---------------- async HMMA GEMM (3-stage, 1 barrier/iter) ----------------
// OP=0: f32 store.  OP=1: f32 accumulate.  OP=2: f16 store.
// OP=3: fused silu(gate)*up -> f16 [M, N/2] (weights interleaved gate/up).
// MT: m16-tiles per warp; block M = MT*32 (MT=4 -> BM128, MT=2 -> BM64).
#define BN 128
#define BKT 32
#define BSTG (BN*BKT*2)

template<int OP, int MT>
__global__ void __launch_bounds__(256, 2)
gemm_async(const __half* __restrict__ A, const __half* __restrict__ Wh,
           const float* __restrict__ Sc, void* __restrict__ Cv,
           int M, int N, int K)
{
    constexpr int BM   = MT * 32;
    constexpr int ASTG = BM * BKT * 2;
    __shared__ __align__(16) __half As[3][BM*BKT];
    __shared__ __align__(16) __half Bs[3][BN*BKT];

    const int tid  = threadIdx.x;
    const int lane = tid & 31;
    const int wid  = tid >> 5;
    const int warp_m = wid >> 2;            // 0..1
    const int warp_n = wid & 3;             // 0..3 (32 cols)
    const int m0 = blockIdx.x * BM;
    const int n0 = blockIdx.y * BN;
    const int ngroups = K >> 7;
    const int gid = lane >> 2, tig = lane & 3;

    const uint32_t sa = smem_u32(&As[0][0]);
    const uint32_t sb = smem_u32(&Bs[0][0]);

    const int a_row  = lane & 15;
    const int a_sel  = lane >> 4;
    const int a_xor  = ((lane & 15) >> 1) & 3;
    const int b_roff = ((lane >> 4) << 3) + (lane & 7);
    const int b_sel  = (lane >> 3) & 1;
    const int b_xor  = (b_roff >> 1) & 3;

    float acc[MT][4][4] = {};
    float s_cur[4][2];
    float s_nxt[4][2];

    const int iters = K / BKT;

    auto issue = [&](int stage, int k0) {
        uint32_t ab = sa + stage * ASTG;
        uint32_t bb = sb + stage * BSTG;
#pragma unroll
        for (int j = 0; j < MT/2; j++) {
            int c = tid + j*256;
            int row = c >> 2, ch = c & 3;
            int pch = ch ^ ((row >> 1) & 3);
            cp16(ab + row*64 + pch*16, A  + (size_t)(m0+row)*K + k0 + ch*8);
        }
#pragma unroll
        for (int j = 0; j < 2; j++) {
            int c = tid + j*256;
            int row = c >> 2, ch = c & 3;
            int pch = ch ^ ((row >> 1) & 3);
            cp16(bb + row*64 + pch*16, Wh + (size_t)(n0+row)*K + k0 + ch*8);
        }
        asm volatile("cp.async.commit_group;\n");
    };

    issue(0, 0);
    issue(1, BKT);

    int stage = 0;
    for (int it = 0; it < iters; it++) {
        if (it + 1 < iters) asm volatile("cp.async.wait_group 1;\n");
        else                asm volatile("cp.async.wait_group 0;\n");
        __syncthreads();

        if ((it & 3) == 0) {
            int g = it >> 2;
#pragma unroll
            for (int nt = 0; nt < 4; nt++) {
                int nc = warp_n*32 + nt*8 + 2*tig;
                float ns0, ns1;
                if (g == 0) {
                    ns0 = Sc[(size_t)(n0 + nc)    *ngroups];
                    ns1 = Sc[(size_t)(n0 + nc + 1)*ngroups];
                } else {
                    ns0 = s_nxt[nt][0]; ns1 = s_nxt[nt][1];
                }
                if (it) {
                    float r0 = __fdividef(s_cur[nt][0], ns0);
                    float r1 = __fdividef(s_cur[nt][1], ns1);
#pragma unroll
                    for (int mt = 0; mt < MT; mt++) {
                        acc[mt][nt][0] *= r0; acc[mt][nt][1] *= r1;
                        acc[mt][nt][2] *= r0; acc[mt][nt][3] *= r1;
                    }
                }
                s_cur[nt][0] = ns0; s_cur[nt][1] = ns1;
            }
            if (g + 1 < ngroups) {
#pragma unroll
                for (int nt = 0; nt < 4; nt++) {
                    int nc = warp_n*32 + nt*8 + 2*tig;
                    s_nxt[nt][0] = Sc[(size_t)(n0 + nc)    *ngroups + g + 1];
                    s_nxt[nt][1] = Sc[(size_t)(n0 + nc + 1)*ngroups + g + 1];
                }
            }
        }

        const uint32_t ab = sa + stage * ASTG;
        const uint32_t bb = sb + stage * BSTG;
#pragma unroll
        for (int kk = 0; kk < 2; kk++) {
            uint32_t af[MT][4];
#pragma unroll
            for (int mt = 0; mt < MT; mt++) {
                int row = warp_m*(16*MT) + mt*16 + a_row;
                int pch = (kk*2 + a_sel) ^ a_xor;
                ldm_x4(af[mt][0], af[mt][1], af[mt][2], af[mt][3],
                       ab + row*64 + pch*16);
            }
            uint32_t bf[4][2];
#pragma unroll
            for (int p = 0; p < 2; p++) {
                int row = warp_n*32 + p*16 + b_roff;
                int pch = (kk*2 + b_sel) ^ b_xor;
                uint32_t r0, r1, r2, r3;
                ldm_x4(r0, r1, r2, r3, bb + row*64 + pch*16);
                bf[2*p  ][0] = r0; bf[2*p  ][1] = r1;
                bf[2*p+1][0] = r2; bf[2*p+1][1] = r3;
            }
#pragma unroll
            for (int mt = 0; mt < MT; mt++)
#pragma unroll
                for (int nt = 0; nt < 4; nt++)
                    mma16816(acc[mt][nt], af[mt], bf[nt]);
        }

        if (it + 2 < iters) issue((stage + 2 >= 3) ? stage - 1 : stage + 2, (it + 2) * BKT);
        stage = (stage + 1 == 3) ? 0 : stage + 1;
    }

    // ---- epilogue ----
#pragma unroll
    for (int mt = 0; mt < MT; mt++) {
        int r = m0 + warp_m*(16*MT) + mt*16 + gid;
#pragma unroll
        for (int nt = 0; nt < 4; nt++) {
            int c = n0 + warp_n*32 + nt*8 + 2*tig;
            float s0 = s_cur[nt][0], s1 = s_cur[nt][1];
            float v00 = acc[mt][nt][0]*s0, v01 = acc[mt][nt][1]*s1;
            float v10 = acc[mt][nt][2]*s0, v11 = acc[mt][nt][3]*s1;
            if (OP == 0 || OP == 1) {
                float* C = (float*)Cv;
                float* p0 = C + (size_t)r*N + c;
                float* p1 = C + (size_t)(r+8)*N + c;
                float2 v0 = make_float2(v00, v01);
                float2 v1 = make_float2(v10, v11);
                if (OP == 1) {
                    float2 o0 = *(float2*)p0, o1 = *(float2*)p1;
                    v0.x += o0.x; v0.y += o0.y; v1.x += o1.x; v1.y += o1.y;
                }
                *(float2*)p0 = v0;
                *(float2*)p1 = v1;
            } else if (OP == 2) {
                __half* C = (__half*)Cv;
                *(__half2*)(C + (size_t)r*N + c)     = __floats2half2_rn(v00, v01);
                *(__half2*)(C + (size_t)(r+8)*N + c) = __floats2half2_rn(v10, v11);
            } else {
                __half* C = (__half*)Cv;
                int oN = N >> 1, oc = c >> 1;
                float o0 = v00 / (1.f + __expf(-v00)) * v01;
                float o1 = v10 / (1.f + __expf(-v10)) * v11;
                C[(size_t)r*oN + oc]     = __float2half(o0);
                C[(size_t)(r+8)*oN + oc] = __float2half(o1);
            }
        }
    }
}

// ---------------- mma flash attention + per-head residual ----------------
#define AQ 64
#define QKVS (3*D_)
__global__ void __launch_bounds__(128)
attn_mma(const __half* __restrict__ QKV, const __half* __restrict__ Hn,
         const float* __restrict__ alpha, __half* __restrict__ O, int layer)
{
    __shared__ __align__(16) __half Qs[AQ][72];
    __shared__ __align__(16) __half Ks[AQ][72];
    __shared__ __align__(16) __half Vt[AQ][72];   // Vt[dh][key]

    const int tid = threadIdx.x, lane = tid & 31, wid = tid >> 5;
    const int qt = blockIdx.x, hh = blockIdx.y, b = blockIdx.z;
    const int q0 = qt * AQ;

    for (int t = tid; t < AQ*8; t += 128) {
        int r = t >> 3, c8 = t & 7;
        *(uint4*)&Qs[r][c8*8] =
            *(const uint4*)(QKV + ((size_t)(b*S_ + q0 + r))*QKVS + hh*DH_ + c8*8);
    }
    __syncthreads();

    uint32_t qf[4][4];
    {
        int rr = wid*16 + (lane & 15);
        int cc = ((lane >> 4) & 1) * 8;
#pragma unroll
        for (int ks = 0; ks < 4; ks++)
            ldm_x4(qf[ks][0], qf[ks][1], qf[ks][2], qf[ks][3],
                   smem_u32(&Qs[rr][ks*16 + cc]));
    }

    float o[8][4] = {};
    float m_lo = -1e30f, m_hi = -1e30f, l_lo = 0.f, l_hi = 0.f;
    const int qi_lo = q0 + wid*16 + (lane >> 2);
    const int qi_hi = qi_lo + 8;
    const int row_off = ((lane >> 4) << 3) + (lane & 7);
    const int col_sel = ((lane >> 3) & 1) * 8;

    for (int t0 = 0; t0 < q0 + AQ; t0 += AQ) {
        __syncthreads();
        for (int t = tid; t < AQ*8; t += 128) {
            int r = t >> 3, c8 = t & 7;
            const __half* base = QKV + ((size_t)(b*S_ + t0 + r))*QKVS + hh*DH_ + c8*8;
            *(uint4*)&Ks[r][c8*8] = *(const uint4*)(base + D_);
            uint4 raw = *(const uint4*)(base + 2*D_);
            const __half* hp = (const __half*)&raw;
#pragma unroll
            for (int d = 0; d < 8; d++) Vt[c8*8 + d][r] = hp[d];
        }
        __syncthreads();

        float sacc[8][4] = {};
#pragma unroll
        for (int ks = 0; ks < 4; ks++) {
#pragma unroll
            for (int jp = 0; jp < 4; jp++) {
                uint32_t r0, r1, r2, r3;
                ldm_x4(r0, r1, r2, r3, smem_u32(&Ks[jp*16 + row_off][ks*16 + col_sel]));
                uint32_t bA[2] = {r0, r1};
                uint32_t bB[2] = {r2, r3};
                mma16816(sacc[2*jp  ], qf[ks], bA);
                mma16816(sacc[2*jp+1], qf[ks], bB);
            }
        }

        float mx_lo = -1e30f, mx_hi = -1e30f;
#pragma unroll
        for (int j = 0; j < 8; j++) {
            int kb = t0 + j*8 + 2*(lane & 3);
            sacc[j][0] = (kb     <= qi_lo) ? sacc[j][0]*0.125f : -1e30f;
            sacc[j][1] = (kb + 1 <= qi_lo) ? sacc[j][1]*0.125f : -1e30f;
            sacc[j][2] = (kb     <= qi_hi) ? sacc[j][2]*0.125f : -1e30f;
            sacc[j][3] = (kb + 1 <= qi_hi) ? sacc[j][3]*0.125f : -1e30f;
            mx_lo = fmaxf(mx_lo, fmaxf(sacc[j][0], sacc[j][1]));
            mx_hi = fmaxf(mx_hi, fmaxf(sacc[j][2], sacc[j][3]));
        }
        mx_lo = fmaxf(mx_lo, __shfl_xor_sync(0xffffffffu, mx_lo, 1));
        mx_lo = fmaxf(mx_lo, __shfl_xor_sync(0xffffffffu, mx_lo, 2));
        mx_hi = fmaxf(mx_hi, __shfl_xor_sync(0xffffffffu, mx_hi, 1));
        mx_hi = fmaxf(mx_hi, __shfl_xor_sync(0xffffffffu, mx_hi, 2));

        float mn_lo = fmaxf(m_lo, mx_lo), mn_hi = fmaxf(m_hi, mx_hi);
        float c_lo = __expf(m_lo - mn_lo), c_hi = __expf(m_hi - mn_hi);
        m_lo = mn_lo; m_hi = mn_hi;
        l_lo *= c_lo; l_hi *= c_hi;
#pragma unroll
        for (int j = 0; j < 8; j++) {
            o[j][0] *= c_lo; o[j][1] *= c_lo;
            o[j][2] *= c_hi; o[j][3] *= c_hi;
        }

        uint32_t pa[8], pb[8];
        float ps_lo = 0.f, ps_hi = 0.f;
#pragma unroll
        for (int j = 0; j < 8; j++) {
            float e0 = __expf(sacc[j][0] - mn_lo);
            float e1 = __expf(sacc[j][1] - mn_lo);
            float e2 = __expf(sacc[j][2] - mn_hi);
            float e3 = __expf(sacc[j][3] - mn_hi);
            ps_lo += e0 + e1; ps_hi += e2 + e3;
            __half2 hl = __floats2half2_rn(e0, e1);
            __half2 hb = __floats2half2_rn(e2, e3);
            pa[j] = *(uint32_t*)&hl;
            pb[j] = *(uint32_t*)&hb;
        }
        ps_lo += __shfl_xor_sync(0xffffffffu, ps_lo, 1);
        ps_lo += __shfl_xor_sync(0xffffffffu, ps_lo, 2);
        ps_hi += __shfl_xor_sync(0xffffffffu, ps_hi, 1);
        ps_hi += __shfl_xor_sync(0xffffffffu, ps_hi, 2);
        l_lo += ps_lo; l_hi += ps_hi;

#pragma unroll
        for (int kk = 0; kk < 4; kk++) {
            uint32_t af[4] = {pa[2*kk], pb[2*kk], pa[2*kk+1], pb[2*kk+1]};
#pragma unroll
            for (int dp = 0; dp < 4; dp++) {
                uint32_t r0, r1, r2, r3;
                ldm_x4(r0, r1, r2, r3, smem_u32(&Vt[dp*16 + row_off][kk*16 + col_sel]));
                uint32_t bA[2] = {r0, r1};
                uint32_t bB[2] = {r2, r3};
                mma16816(o[2*dp  ], af, bA);
                mma16816(o[2*dp+1], af, bB);
            }
        }
    }

    float i_lo = 1.f / l_lo, i_hi = 1.f / l_hi;
    float a = alpha[layer*H_ + hh];
    size_t tok_lo = (size_t)(b*S_ + qi_lo);
#pragma unroll
    for (int j = 0; j < 8; j++) {
        int col = hh*DH_ + j*8 + 2*(lane & 3);
        float2 fh_lo = __half22float2(*(const __half2*)(Hn + tok_lo*D_ + col));
        float2 fh_hi = __half22float2(*(const __half2*)(Hn + (tok_lo+8)*D_ + col));
        __half2 o_lo = __floats2half2_rn(o[j][0]*i_lo + a*fh_lo.x,
                                         o[j][1]*i_lo + a*fh_lo.y);
        __half2 o_hi = __floats2half2_rn(o[j][2]*i_hi + a*fh_hi.x,
                                         o[j][3]*i_hi + a*fh_hi.y);
        *(__half2*)(O + tok_lo*D_ + col)     = o_lo;
        *(__half2*)(O + (tok_lo+8)*D_ + col) = o_hi;
    }
}

// ---------------- launch ----------------
extern "C" void kernel_launch(void* const* d_in, const int* in_sizes, int n_in,
                              void* d_out, int out_size)
{
    const int*   ids    = (const int*)  d_in[0];
    const void*  emb_t  = d_in[1];
    const float* emb_s  = (const float*)d_in[2];
    const void*  qt_    = d_in[3];
    const float* qs_    = (const float*)d_in[4];
    const void*  kt_    = d_in[5];
    const float* ks_    = (const float*)d_in[6];
    const void*  vt_    = d_in[7];
    const float* vs_    = (const float*)d_in[8];
    const void*  ot_    = d_in[9];
    const float* os_    = (const float*)d_in[10];
    const void*  gatet  = d_in[11];
    const float* gates  = (const float*)d_in[12];
    const void*  upt    = d_in[13];
    const float* ups    = (const float*)d_in[14];
    const void*  downt  = d_in[15];
    const float* downs  = (const float*)d_in[16];
    const float* wa     = (const float*)d_in[17];
    const float* wm     = (const float*)d_in[18];
    const float* alpha  = (const float*)d_in[19];
    const float* wf     = (const float*)d_in[20];
    const void*  headt  = d_in[21];
    const float* heads  = (const float*)d_in[22];
    float* out = (float*)d_out;

    float *x, *scqkv, *scgu;
    __half *qkv, *hh, *oh, *gh, *wh;
    cudaGetSymbolAddress((void**)&x,    g_x);
    cudaGetSymbolAddress((void**)&qkv,  g_qkv);
    cudaGetSymbolAddress((void**)&hh,   g_hh);
    cudaGetSymbolAddress((void**)&oh,   g_oh);
    cudaGetSymbolAddress((void**)&gh,   g_gh);
    cudaGetSymbolAddress((void**)&wh,   g_wh);
    cudaGetSymbolAddress((void**)&scqkv,g_scqkv);
    cudaGetSymbolAddress((void**)&scgu, g_scgu);

    // side stream for overlapping head-weight conversion with layer compute
    static cudaStream_t s2 = nullptr;
    static cudaEvent_t evFork = nullptr, evJoin = nullptr;
    if (!s2) {
        cudaStreamCreate(&s2);
        cudaEventCreateWithFlags(&evFork, cudaEventDisableTiming);
        cudaEventCreateWithFlags(&evJoin, cudaEventDisableTiming);
    }

    const size_t wDD = (size_t)D_*D_;          // 1M
    const size_t wFD = (size_t)DFF_*D_;        // 4M
    const size_t sDD = wDD/GS_;                // 8192
    const size_t sFD = wFD/GS_;                // 32768

    detect_fmt_kernel<<<1, 1>>>(emb_t);

    // fork: head conversion on s2 (depends only on detect_fmt)
    cudaEventRecord(evFork, 0);
    cudaStreamWaitEvent(s2, evFork, 0);
    {
        ConvSegs PH;
        for (int s = 0; s < NSEG; s++) PH.chunkEnd[s] = (int)((V_*(size_t)D_)/16);
        PH.src[0] = headt; PH.srcOff[0] = 0; PH.dstOff[0] = OFF_HD; PH.mode[0] = 0;
        PH.total = (int)((V_*(size_t)D_)/16);
        convert_all<<<(PH.total + 255)/256, 256, 0, s2>>>(PH, wh);
        cudaEventRecord(evJoin, s2);
    }

    // layer weights conversion on main stream
    ConvSegs P;
    {
        int c = 0, seg = 0;
        auto add = [&](const void* src, size_t soff, size_t doff, int nelems, int mode) {
            P.src[seg] = src; P.srcOff[seg] = soff; P.dstOff[seg] = doff;
            P.mode[seg] = mode; c += nelems / 16; P.chunkEnd[seg] = c; seg++;
        };
        for (int l = 0; l < L_; l++) {
            add(qt_,   l*wDD, OFF_QKV + l*3*wDD,         (int)wDD, 0);
            add(kt_,   l*wDD, OFF_QKV + l*3*wDD + wDD,   (int)wDD, 0);
            add(vt_,   l*wDD, OFF_QKV + l*3*wDD + 2*wDD, (int)wDD, 0);
            add(ot_,   l*wDD, OFF_O   + l*wDD,           (int)wDD, 0);
            add(gatet, l*wFD, OFF_GU  + l*2*wFD,         (int)wFD, 1);
            add(upt,   l*wFD, OFF_GU  + l*2*wFD,         (int)wFD, 2);
            add(downt, l*wFD, OFF_DN  + l*wFD,           (int)wFD, 0);
        }
        P.total = c;
    }
    convert_all<<<(P.total + 255)/256, 256>>>(P, wh);

    pack_scales<<<(180224 + 255)/256, 256>>>(qs_, ks_, vs_, gates, ups, scqkv, scgu);
    embed_kernel<<<NT_, 256>>>(ids, emb_t, emb_s, x);

    dim3 g_qkvp(NT_/128, 3*D_/BN);   // 16 x 24
    dim3 g_op  (NT_/64,  D_/BN);     // 32 x 8  (BM=64)
    dim3 g_gup (NT_/128, 2*DFF_/BN); // 16 x 64
    dim3 g_hd  (NT_/128, V_/BN);     // 16 x 250

    for (int l = 0; l < L_; l++) {
        rmsnorm_kernel<<<NT_, 256>>>(x, wa + (size_t)l*D_, hh);
        gemm_async<2,4><<<g_qkvp, 256>>>(hh, wh + OFF_QKV + l*3*wDD, scqkv + l*3*sDD,
                                         qkv, NT_, 3*D_, D_);
        attn_mma<<<dim3(S_/AQ, H_, B_), 128>>>(qkv, hh, alpha, oh, l);
        gemm_async<1,2><<<g_op, 256>>>(oh, wh + OFF_O + l*wDD, os_ + l*sDD,
                                       x, NT_, D_, D_);

        rmsnorm_kernel<<<NT_, 256>>>(x, wm + (size_t)l*D_, hh);
        gemm_async<3,4><<<g_gup, 256>>>(hh, wh + OFF_GU + l*2*wFD, scgu + l*2*sFD,
                                        gh, NT_, 2*DFF_, D_);
        gemm_async<1,2><<<g_op, 256>>>(gh, wh + OFF_DN + l*wFD, downs + l*sFD,
                                       x, NT_, D_, DFF_);
    }
    rmsnorm_kernel<<<NT_, 256>>>(x, wf, hh);

    // join: head weights must be converted before the head GEMM
    cudaStreamWaitEvent(0, evJoin, 0);
    gemm_async<0,4><<<g_hd, 256>>>(hh, wh + OFF_HD, heads, out, NT_, V_, D_);
}

// round 14
// speedup vs baseline: 10.6218x; 1.0038x over previous
#include <cuda_runtime.h>
#include <cuda_fp16.h>
#include <cuda_bf16.h>
#include <cstdint>

// ---------------- dims ----------------
#define B_  2
#define S_  1024
#define D_  1024
#define H_  16
#define DH_ 64
#define DFF_ 4096
#define L_  2
#define V_  32000
#define GS_ 128
#define NT_ (B_*S_)   // 2048 tokens

// weight regions in g_wh (element offsets, halves)
#define OFF_QKV 0ull                       // 2 layers x 3M
#define OFF_O   (6ull*1024*1024)           // 2 x 1M
#define OFF_GU  (8ull*1024*1024)           // 2 x 8M (interleaved gate/up)
#define OFF_DN  (24ull*1024*1024)          // 2 x 4M
#define OFF_HD  (32ull*1024*1024)          // 32.77M
#define WH_TOT  (66ull*1024*1024)

// ---------------- scratch ----------------
__device__ __align__(16) float  g_x  [NT_*D_];
__device__ __align__(16) __half g_qkv[NT_*3*D_];
__device__ __align__(16) __half g_hh [NT_*D_];
__device__ __align__(16) __half g_oh [NT_*D_];
__device__ __align__(16) __half g_gh [NT_*DFF_];
__device__ __align__(16) __half g_wh [WH_TOT];
__device__ float g_scqkv[2*3*8192];
__device__ float g_scgu [2*2*32768];       // interleaved gate/up scales
__device__ int   g_wfmt;   // 0=int8, 1=int32, 2=bf16

// ---------------- weight format detector ----------------
__global__ void detect_fmt_kernel(const void* __restrict__ w)
{
    const unsigned* u = (const unsigned*)w;
    bool i32 = true, b16 = true;
    for (int i = 0; i < 64; i++) {
        unsigned x = u[i];
        if (!(x == 0u || x == 1u || x == 0xFFFFFFFFu)) i32 = false;
        unsigned lo = x & 0xFFFFu, hi = x >> 16;
        bool lok = (lo == 0u || lo == 0x3F80u || lo == 0xBF80u);
        bool hok = (hi == 0u || hi == 0x3F80u || hi == 0xBF80u);
        if (!(lok && hok)) b16 = false;
    }
    g_wfmt = i32 ? 1 : (b16 ? 2 : 0);
}

__device__ __forceinline__ void load_w4(const void* W, size_t idx, int fmt,
                                        float& w0, float& w1, float& w2, float& w3)
{
    if (fmt == 1) {
        int4 wv = *(const int4*)((const int*)W + idx);
        w0 = (float)wv.x; w1 = (float)wv.y; w2 = (float)wv.z; w3 = (float)wv.w;
    } else if (fmt == 2) {
        uint2 v = *(const uint2*)((const __nv_bfloat16*)W + idx);
        w0 = __bfloat162float(__ushort_as_bfloat16((unsigned short)( v.x        & 0xFFFFu)));
        w1 = __bfloat162float(__ushort_as_bfloat16((unsigned short)( v.x >> 16          )));
        w2 = __bfloat162float(__ushort_as_bfloat16((unsigned short)( v.y        & 0xFFFFu)));
        w3 = __bfloat162float(__ushort_as_bfloat16((unsigned short)( v.y >> 16          )));
    } else {
        int wv = *(const int*)((const int8_t*)W + idx);
        w0 = (float)(int8_t)( wv         & 0xff);
        w1 = (float)(int8_t)((wv >> 8 )  & 0xff);
        w2 = (float)(int8_t)((wv >> 16)  & 0xff);
        w3 = (float)(int8_t)( wv >> 24         );
    }
}

// ---------------- fused weight conversion ----------------
#define NSEG 7
struct ConvSegs {
    const void*        src[NSEG];
    unsigned long long srcOff[NSEG];   // element offset in source tensor
    unsigned long long dstOff[NSEG];   // half offset in g_wh
    int                mode[NSEG];     // 0 plain, 1 interleave-even, 2 interleave-odd
    int                chunkEnd[NSEG]; // exclusive prefix in 16-elem chunks
    int                total;          // total chunks
};

__global__ void convert_all(ConvSegs P, __half* __restrict__ dst)
{
    const int fmt = g_wfmt;
    for (int chunk = blockIdx.x * blockDim.x + threadIdx.x; chunk < P.total;
         chunk += gridDim.x * blockDim.x) {
        int s = 0;
        while (chunk >= P.chunkEnd[s]) s++;
        int start = (s == 0) ? 0 : P.chunkEnd[s - 1];
        size_t i = (size_t)(chunk - start) * 16;

        float w[16];
#pragma unroll
        for (int j = 0; j < 4; j++)
            load_w4(P.src[s], P.srcOff[s] + i + j*4, fmt,
                    w[j*4], w[j*4+1], w[j*4+2], w[j*4+3]);
        uint32_t h[8];
#pragma unroll
        for (int j = 0; j < 8; j++) {
            __half2 p = __floats2half2_rn(w[2*j], w[2*j+1]);
            h[j] = *(uint32_t*)&p;
        }
        size_t di;
        int mode = P.mode[s];
        if (mode == 0) {
            di = (size_t)P.dstOff[s] + i;
        } else {
            size_t row = i >> 10, col = i & 1023;
            di = (size_t)P.dstOff[s] + ((2*row + (mode - 1)) << 10) + col;
        }
        *(uint4*)&dst[di]     = make_uint4(h[0], h[1], h[2], h[3]);
        *(uint4*)&dst[di + 8] = make_uint4(h[4], h[5], h[6], h[7]);
    }
}

// ---------------- scale packing ----------------
__global__ void pack_scales(const float* __restrict__ qs, const float* __restrict__ ks,
                            const float* __restrict__ vs, const float* __restrict__ gs,
                            const float* __restrict__ us,
                            float* __restrict__ scqkv, float* __restrict__ scgu)
{
    int i = blockIdx.x * 256 + threadIdx.x;
    if (i < 49152) {
        int l = i / 24576, r = i % 24576;
        int which = r / 8192, j = r % 8192;
        const float* sp = (which == 0) ? qs : ((which == 1) ? ks : vs);
        scqkv[i] = sp[l*8192 + j];
    } else if (i < 180224) {
        int k = i - 49152;
        int l = k / 65536, r = k % 65536;
        int which = r / 32768, j = r % 32768;
        int row = j >> 3, g = j & 7;
        scgu[l*65536 + ((2*row + which) << 3) + g] = (which ? us : gs)[l*32768 + j];
    }
}

// ---------------- embedding gather + dequant ----------------
__global__ void embed_kernel(const int* __restrict__ ids,
                             const void* __restrict__ et,
                             const float* __restrict__ es,
                             float* __restrict__ X)
{
    int token = blockIdx.x;
    int id = ids[token];
    int d0 = threadIdx.x * 4;
    int fmt = g_wfmt;
    float w0, w1, w2, w3;
    load_w4(et, (size_t)id * D_ + d0, fmt, w0, w1, w2, w3);
    float s = es[id * (D_/GS_) + (d0 >> 7)];
    *(float4*)(X + (size_t)token * D_ + d0) = make_float4(w0*s, w1*s, w2*s, w3*s);
}

// ---------------- rmsnorm (f32 in, f16 out) ----------------
__global__ void rmsnorm_kernel(const float* __restrict__ X,
                               const float* __restrict__ w,
                               __half* __restrict__ Y)
{
    int row = blockIdx.x;
    const float* x = X + (size_t)row * D_;
    float ss = 0.f;
    float vals[4];
#pragma unroll
    for (int j = 0; j < 4; j++) {
        vals[j] = x[threadIdx.x + j*256];
        ss += vals[j]*vals[j];
    }
    __shared__ float red[256];
    red[threadIdx.x] = ss;
    __syncthreads();
    for (int s = 128; s > 0; s >>= 1) {
        if (threadIdx.x < s) red[threadIdx.x] += red[threadIdx.x + s];
        __syncthreads();
    }
    float rs = rsqrtf(red[0] * (1.0f/(float)D_) + 1e-6f);
#pragma unroll
    for (int j = 0; j < 4; j++) {
        int d = threadIdx.x + j*256;
        Y[(size_t)row * D_ + d] = __float2half(vals[j] * rs * w[d]);
    }
}

// ---------------- mma helpers ----------------
__device__ __forceinline__ void mma16816(float* c, const uint32_t* a, const uint32_t* b)
{
    asm volatile(
        "mma.sync.aligned.m16n8k16.row.col.f32.f16.f16.f32 "
        "{%0,%1,%2,%3}, {%4,%5,%6,%7}, {%8,%9}, {%0,%1,%2,%3};\n"
        : "+f"(c[0]), "+f"(c[1]), "+f"(c[2]), "+f"(c[3])
        : "r"(a[0]), "r"(a[1]), "r"(a[2]), "r"(a[3]), "r"(b[0]), "r"(b[1]));
}
__device__ __forceinline__ void cp16(uint32_t dst, const void* src)
{
    asm volatile("cp.async.cg.shared.global [%0], [%1], 16;\n" :: "r"(dst), "l"(src));
}
__device__ __forceinline__ void ldm_x4(uint32_t& r0, uint32_t& r1, uint32_t& r2, uint32_t& r3,
                                       uint32_t addr)
{
    asm volatile("ldmatrix.sync.aligned.m8n8.x4.shared.b16 {%0,%1,%2,%3}, [%4];"
                 : "=r"(r0), "=r"(r1), "=r"(r2), "=r"(r3) : "r"(addr));
}
__device__ __forceinline__ uint32_t smem_u32(const void* p) {
    return (uint32_t)__cvta_generic_to_shared(p);
}

// ---------------- async HMMA GEMM (4 warps, 64-wide warp tiles) ----------------
// OP=0: f32 store.  OP=1: f32 accumulate.  OP=2: f16 store.
// OP=3: fused silu(gate)*up -> f16 [M, N/2] (weights interleaved gate/up).
// MT: m16-tiles per warp; block = (MT*32) x 128; warp tile (MT*16) x 64.
#define BN 128
#define BKT 32
#define BSTG (BN*BKT*2)

template<int OP, int MT>
__global__ void __launch_bounds__(128, 2)
gemm_async(const __half* __restrict__ A, const __half* __restrict__ Wh,
           const float* __restrict__ Sc, void* __restrict__ Cv,
           int M, int N, int K)
{
    constexpr int BM   = MT * 32;
    constexpr int ASTG = BM * BKT * 2;
    __shared__ __align__(16) __half As[3][BM*BKT];
    __shared__ __align__(16) __half Bs[3][BN*BKT];

    const int tid  = threadIdx.x;
    const int lane = tid & 31;
    const int wid  = tid >> 5;            // 0..3
    const int warp_m = wid >> 1;          // 0..1
    const int warp_n = wid & 1;           // 0..1 (64 cols each)
    const int m0 = blockIdx.x * BM;
    const int n0 = blockIdx.y * BN;
    const int ngroups = K >> 7;
    const int gid = lane >> 2, tig = lane & 3;

    const uint32_t sa = smem_u32(&As[0][0]);
    const uint32_t sb = smem_u32(&Bs[0][0]);

    const int a_row  = lane & 15;
    const int a_sel  = lane >> 4;
    const int a_xor  = ((lane & 15) >> 1) & 3;
    const int b_roff = ((lane >> 4) << 3) + (lane & 7);
    const int b_sel  = (lane >> 3) & 1;
    const int b_xor  = (b_roff >> 1) & 3;

    float acc[MT][8][4] = {};
    float s_cur[8][2];
    float s_nxt[8][2];

    const int iters = K / BKT;

    auto issue = [&](int stage, int k0) {
        uint32_t ab = sa + stage * ASTG;
        uint32_t bb = sb + stage * BSTG;
#pragma unroll
        for (int j = 0; j < MT; j++) {            // BM*4 items / 128 threads
            int c = tid + j*128;
            int row = c >> 2, ch = c & 3;
            int pch = ch ^ ((row >> 1) & 3);
            cp16(ab + row*64 + pch*16, A  + (size_t)(m0+row)*K + k0 + ch*8);
        }
#pragma unroll
        for (int j = 0; j < 4; j++) {             // 512 items / 128 threads
            int c = tid + j*128;
            int row = c >> 2, ch = c & 3;
            int pch = ch ^ ((row >> 1) & 3);
            cp16(bb + row*64 + pch*16, Wh + (size_t)(n0+row)*K + k0 + ch*8);
        }
        asm volatile("cp.async.commit_group;\n");
    };

    issue(0, 0);
    issue(1, BKT);

    int stage = 0;
    for (int it = 0; it < iters; it++) {
        if (it + 1 < iters) asm volatile("cp.async.wait_group 1;\n");
        else                asm volatile("cp.async.wait_group 0;\n");
        __syncthreads();

        if ((it & 3) == 0) {
            int g = it >> 2;
#pragma unroll
            for (int nt = 0; nt < 8; nt++) {
                int nc = warp_n*64 + nt*8 + 2*tig;
                float ns0, ns1;
                if (g == 0) {
                    ns0 = Sc[(size_t)(n0 + nc)    *ngroups];
                    ns1 = Sc[(size_t)(n0 + nc + 1)*ngroups];
                } else {
                    ns0 = s_nxt[nt][0]; ns1 = s_nxt[nt][1];
                }
                if (it) {
                    float r0 = __fdividef(s_cur[nt][0], ns0);
                    float r1 = __fdividef(s_cur[nt][1], ns1);
#pragma unroll
                    for (int mt = 0; mt < MT; mt++) {
                        acc[mt][nt][0] *= r0; acc[mt][nt][1] *= r1;
                        acc[mt][nt][2] *= r0; acc[mt][nt][3] *= r1;
                    }
                }
                s_cur[nt][0] = ns0; s_cur[nt][1] = ns1;
            }
            if (g + 1 < ngroups) {
#pragma unroll
                for (int nt = 0; nt < 8; nt++) {
                    int nc = warp_n*64 + nt*8 + 2*tig;
                    s_nxt[nt][0] = Sc[(size_t)(n0 + nc)    *ngroups + g + 1];
                    s_nxt[nt][1] = Sc[(size_t)(n0 + nc + 1)*ngroups + g + 1];
                }
            }
        }

        const uint32_t ab = sa + stage * ASTG;
        const uint32_t bb = sb + stage * BSTG;
#pragma unroll
        for (int kk = 0; kk < 2; kk++) {
            uint32_t af[MT][4];
#pragma unroll
            for (int mt = 0; mt < MT; mt++) {
                int row = warp_m*(16*MT) + mt*16 + a_row;
                int pch = (kk*2 + a_sel) ^ a_xor;
                ldm_x4(af[mt][0], af[mt][1], af[mt][2], af[mt][3],
                       ab + row*64 + pch*16);
            }
            uint32_t bf[8][2];
#pragma unroll
            for (int p = 0; p < 4; p++) {
                int row = warp_n*64 + p*16 + b_roff;
                int pch = (kk*2 + b_sel) ^ b_xor;
                uint32_t r0, r1, r2, r3;
                ldm_x4(r0, r1, r2, r3, bb + row*64 + pch*16);
                bf[2*p  ][0] = r0; bf[2*p  ][1] = r1;
                bf[2*p+1][0] = r2; bf[2*p+1][1] = r3;
            }
#pragma unroll
            for (int mt = 0; mt < MT; mt++)
#pragma unroll
                for (int nt = 0; nt < 8; nt++)
                    mma16816(acc[mt][nt], af[mt], bf[nt]);
        }

        if (it + 2 < iters) issue((stage + 2 >= 3) ? stage - 1 : stage + 2, (it + 2) * BKT);
        stage = (stage + 1 == 3) ? 0 : stage + 1;
    }

    // ---- epilogue ----
#pragma unroll
    for (int mt = 0; mt < MT; mt++) {
        int r = m0 + warp_m*(16*MT) + mt*16 + gid;
#pragma unroll
        for (int nt = 0; nt < 8; nt++) {
            int c = n0 + warp_n*64 + nt*8 + 2*tig;
            float s0 = s_cur[nt][0], s1 = s_cur[nt][1];
            float v00 = acc[mt][nt][0]*s0, v01 = acc[mt][nt][1]*s1;
            float v10 = acc[mt][nt][2]*s0, v11 = acc[mt][nt][3]*s1;
            if (OP == 0 || OP == 1) {
                float* C = (float*)Cv;
                float* p0 = C + (size_t)r*N + c;
                float* p1 = C + (size_t)(r+8)*N + c;
                float2 v0 = make_float2(v00, v01);
                float2 v1 = make_float2(v10, v11);
                if (OP == 1) {
                    float2 o0 = *(float2*)p0, o1 = *(float2*)p1;
                    v0.x += o0.x; v0.y += o0.y; v1.x += o1.x; v1.y += o1.y;
                }
                *(float2*)p0 = v0;
                *(float2*)p1 = v1;
            } else if (OP == 2) {
                __half* C = (__half*)Cv;
                *(__half2*)(C + (size_t)r*N + c)     = __floats2half2_rn(v00, v01);
                *(__half2*)(C + (size_t)(r+8)*N + c) = __floats2half2_rn(v10, v11);
            } else {
                __half* C = (__half*)Cv;
                int oN = N >> 1, oc = c >> 1;
                float o0 = v00 / (1.f + __expf(-v00)) * v01;
                float o1 = v10 / (1.f + __expf(-v10)) * v11;
                C[(size_t)r*oN + oc]     = __float2half(o0);
                C[(size_t)(r+8)*oN + oc] = __float2half(o1);
            }
        }
    }
}

// ---------------- mma flash attention + per-head residual ----------------
#define AQ 64
#define QKVS (3*D_)
__global__ void __launch_bounds__(128)
attn_mma(const __half* __restrict__ QKV, const __half* __restrict__ Hn,
         const float* __restrict__ alpha, __half* __restrict__ O, int layer)
{
    __shared__ __align__(16) __half Qs[AQ][72];
    __shared__ __align__(16) __half Ks[AQ][72];
    __shared__ __align__(16) __half Vt[AQ][72];   // Vt[dh][key]

    const int tid = threadIdx.x, lane = tid & 31, wid = tid >> 5;
    const int qt = blockIdx.x, hh = blockIdx.y, b = blockIdx.z;
    const int q0 = qt * AQ;

    for (int t = tid; t < AQ*8; t += 128) {
        int r = t >> 3, c8 = t & 7;
        *(uint4*)&Qs[r][c8*8] =
            *(const uint4*)(QKV + ((size_t)(b*S_ + q0 + r))*QKVS + hh*DH_ + c8*8);
    }
    __syncthreads();

    uint32_t qf[4][4];
    {
        int rr = wid*16 + (lane & 15);
        int cc = ((lane >> 4) & 1) * 8;
#pragma unroll
        for (int ks = 0; ks < 4; ks++)
            ldm_x4(qf[ks][0], qf[ks][1], qf[ks][2], qf[ks][3],
                   smem_u32(&Qs[rr][ks*16 + cc]));
    }

    float o[8][4] = {};
    float m_lo = -1e30f, m_hi = -1e30f, l_lo = 0.f, l_hi = 0.f;
    const int qi_lo = q0 + wid*16 + (lane >> 2);
    const int qi_hi = qi_lo + 8;
    const int row_off = ((lane >> 4) << 3) + (lane & 7);
    const int col_sel = ((lane >> 3) & 1) * 8;

    for (int t0 = 0; t0 < q0 + AQ; t0 += AQ) {
        __syncthreads();
        for (int t = tid; t < AQ*8; t += 128) {
            int r = t >> 3, c8 = t & 7;
            const __half* base = QKV + ((size_t)(b*S_ + t0 + r))*QKVS + hh*DH_ + c8*8;
            *(uint4*)&Ks[r][c8*8] = *(const uint4*)(base + D_);
            uint4 raw = *(const uint4*)(base + 2*D_);
            const __half* hp = (const __half*)&raw;
#pragma unroll
            for (int d = 0; d < 8; d++) Vt[c8*8 + d][r] = hp[d];
        }
        __syncthreads();

        float sacc[8][4] = {};
#pragma unroll
        for (int ks = 0; ks < 4; ks++) {
#pragma unroll
            for (int jp = 0; jp < 4; jp++) {
                uint32_t r0, r1, r2, r3;
                ldm_x4(r0, r1, r2, r3, smem_u32(&Ks[jp*16 + row_off][ks*16 + col_sel]));
                uint32_t bA[2] = {r0, r1};
                uint32_t bB[2] = {r2, r3};
                mma16816(sacc[2*jp  ], qf[ks], bA);
                mma16816(sacc[2*jp+1], qf[ks], bB);
            }
        }

        float mx_lo = -1e30f, mx_hi = -1e30f;
#pragma unroll
        for (int j = 0; j < 8; j++) {
            int kb = t0 + j*8 + 2*(lane & 3);
            sacc[j][0] = (kb     <= qi_lo) ? sacc[j][0]*0.125f : -1e30f;
            sacc[j][1] = (kb + 1 <= qi_lo) ? sacc[j][1]*0.125f : -1e30f;
            sacc[j][2] = (kb     <= qi_hi) ? sacc[j][2]*0.125f : -1e30f;
            sacc[j][3] = (kb + 1 <= qi_hi) ? sacc[j][3]*0.125f : -1e30f;
            mx_lo = fmaxf(mx_lo, fmaxf(sacc[j][0], sacc[j][1]));
            mx_hi = fmaxf(mx_hi, fmaxf(sacc[j][2], sacc[j][3]));
        }
        mx_lo = fmaxf(mx_lo, __shfl_xor_sync(0xffffffffu, mx_lo, 1));
        mx_lo = fmaxf(mx_lo, __shfl_xor_sync(0xffffffffu, mx_lo, 2));
        mx_hi = fmaxf(mx_hi, __shfl_xor_sync(0xffffffffu, mx_hi, 1));
        mx_hi = fmaxf(mx_hi, __shfl_xor_sync(0xffffffffu, mx_hi, 2));

        float mn_lo = fmaxf(m_lo, mx_lo), mn_hi = fmaxf(m_hi, mx_hi);
        float c_lo = __expf(m_lo - mn_lo), c_hi = __expf(m_hi - mn_hi);
        m_lo = mn_lo; m_hi = mn_hi;
        l_lo *= c_lo; l_hi *= c_hi;
#pragma unroll
        for (int j = 0; j < 8; j++) {
            o[j][0] *= c_lo; o[j][1] *= c_lo;
            o[j][2] *= c_hi; o[j][3] *= c_hi;
        }

        uint32_t pa[8], pb[8];
        float ps_lo = 0.f, ps_hi = 0.f;
#pragma unroll
        for (int j = 0; j < 8; j++) {
            float e0 = __expf(sacc[j][0] - mn_lo);
            float e1 = __expf(sacc[j][1] - mn_lo);
            float e2 = __expf(sacc[j][2] - mn_hi);
            float e3 = __expf(sacc[j][3] - mn_hi);
            ps_lo += e0 + e1; ps_hi += e2 + e3;
            __half2 hl = __floats2half2_rn(e0, e1);
            __half2 hb = __floats2half2_rn(e2, e3);
            pa[j] = *(uint32_t*)&hl;
            pb[j] = *(uint32_t*)&hb;
        }
        ps_lo += __shfl_xor_sync(0xffffffffu, ps_lo, 1);
        ps_lo += __shfl_xor_sync(0xffffffffu, ps_lo, 2);
        ps_hi += __shfl_xor_sync(0xffffffffu, ps_hi, 1);
        ps_hi += __shfl_xor_sync(0xffffffffu, ps_hi, 2);
        l_lo += ps_lo; l_hi += ps_hi;

#pragma unroll
        for (int kk = 0; kk < 4; kk++) {
            uint32_t af[4] = {pa[2*kk], pb[2*kk], pa[2*kk+1], pb[2*kk+1]};
#pragma unroll
            for (int dp = 0; dp < 4; dp++) {
                uint32_t r0, r1, r2, r3;
                ldm_x4(r0, r1, r2, r3, smem_u32(&Vt[dp*16 + row_off][kk*16 + col_sel]));
                uint32_t bA[2] = {r0, r1};
                uint32_t bB[2] = {r2, r3};
                mma16816(o[2*dp  ], af, bA);
                mma16816(o[2*dp+1], af, bB);
            }
        }
    }

    float i_lo = 1.f / l_lo, i_hi = 1.f / l_hi;
    float a = alpha[layer*H_ + hh];
    size_t tok_lo = (size_t)(b*S_ + qi_lo);
#pragma unroll
    for (int j = 0; j < 8; j++) {
        int col = hh*DH_ + j*8 + 2*(lane & 3);
        float2 fh_lo = __half22float2(*(const __half2*)(Hn + tok_lo*D_ + col));
        float2 fh_hi = __half22float2(*(const __half2*)(Hn + (tok_lo+8)*D_ + col));
        __half2 o_lo = __floats2half2_rn(o[j][0]*i_lo + a*fh_lo.x,
                                         o[j][1]*i_lo + a*fh_lo.y);
        __half2 o_hi = __floats2half2_rn(o[j][2]*i_hi + a*fh_hi.x,
                                         o[j][3]*i_hi + a*fh_hi.y);
        *(__half2*)(O + tok_lo*D_ + col)     = o_lo;
        *(__half2*)(O + (tok_lo+8)*D_ + col) = o_hi;
    }
}

// ---------------- launch ----------------
extern "C" void kernel_launch(void* const* d_in, const int* in_sizes, int n_in,
                              void* d_out, int out_size)
{
    const int*   ids    = (const int*)  d_in[0];
    const void*  emb_t  = d_in[1];
    const float* emb_s  = (const float*)d_in[2];
    const void*  qt_    = d_in[3];
    const float* qs_    = (const float*)d_in[4];
    const void*  kt_    = d_in[5];
    const float* ks_    = (const float*)d_in[6];
    const void*  vt_    = d_in[7];
    const float* vs_    = (const float*)d_in[8];
    const void*  ot_    = d_in[9];
    const float* os_    = (const float*)d_in[10];
    const void*  gatet  = d_in[11];
    const float* gates  = (const float*)d_in[12];
    const void*  upt    = d_in[13];
    const float* ups    = (const float*)d_in[14];
    const void*  downt  = d_in[15];
    const float* downs  = (const float*)d_in[16];
    const float* wa     = (const float*)d_in[17];
    const float* wm     = (const float*)d_in[18];
    const float* alpha  = (const float*)d_in[19];
    const float* wf     = (const float*)d_in[20];
    const void*  headt  = d_in[21];
    const float* heads  = (const float*)d_in[22];
    float* out = (float*)d_out;

    float *x, *scqkv, *scgu;
    __half *qkv, *hh, *oh, *gh, *wh;
    cudaGetSymbolAddress((void**)&x,    g_x);
    cudaGetSymbolAddress((void**)&qkv,  g_qkv);
    cudaGetSymbolAddress((void**)&hh,   g_hh);
    cudaGetSymbolAddress((void**)&oh,   g_oh);
    cudaGetSymbolAddress((void**)&gh,   g_gh);
    cudaGetSymbolAddress((void**)&wh,   g_wh);
    cudaGetSymbolAddress((void**)&scqkv,g_scqkv);
    cudaGetSymbolAddress((void**)&scgu, g_scgu);

    // side stream: weight conversion overlapped with compute
    static cudaStream_t s2 = nullptr;
    static cudaEvent_t evFork = nullptr, evL[2] = {nullptr, nullptr}, evH = nullptr;
    if (!s2) {
        cudaStreamCreate(&s2);
        cudaEventCreateWithFlags(&evFork, cudaEventDisableTiming);
        cudaEventCreateWithFlags(&evL[0], cudaEventDisableTiming);
        cudaEventCreateWithFlags(&evL[1], cudaEventDisableTiming);
        cudaEventCreateWithFlags(&evH,    cudaEventDisableTiming);
    }

    const size_t wDD = (size_t)D_*D_;          // 1M
    const size_t wFD = (size_t)DFF_*D_;        // 4M
    const size_t sDD = wDD/GS_;                // 8192
    const size_t sFD = wFD/GS_;                // 32768

    detect_fmt_kernel<<<1, 1>>>(emb_t);
    cudaEventRecord(evFork, 0);
    cudaStreamWaitEvent(s2, evFork, 0);

    // per-layer weight conversion + head, all on s2 with per-stage events
    for (int l = 0; l < L_; l++) {
        ConvSegs P;
        int c = 0, seg = 0;
        auto add = [&](const void* src, size_t soff, size_t doff, int nelems, int mode) {
            P.src[seg] = src; P.srcOff[seg] = soff; P.dstOff[seg] = doff;
            P.mode[seg] = mode; c += nelems / 16; P.chunkEnd[seg] = c; seg++;
        };
        add(qt_,   l*wDD, OFF_QKV + l*3*wDD,         (int)wDD, 0);
        add(kt_,   l*wDD, OFF_QKV + l*3*wDD + wDD,   (int)wDD, 0);
        add(vt_,   l*wDD, OFF_QKV + l*3*wDD + 2*wDD, (int)wDD, 0);
        add(ot_,   l*wDD, OFF_O   + l*wDD,           (int)wDD, 0);
        add(gatet, l*wFD, OFF_GU  + l*2*wFD,         (int)wFD, 1);
        add(upt,   l*wFD, OFF_GU  + l*2*wFD,         (int)wFD, 2);
        add(downt, l*wFD, OFF_DN  + l*wFD,           (int)wFD, 0);
        P.total = c;
        convert_all<<<(P.total + 255)/256, 256, 0, s2>>>(P, wh);
        cudaEventRecord(evL[l], s2);
    }
    {
        ConvSegs PH;
        int c = (int)((V_*(size_t)D_)/16);
        for (int s = 0; s < NSEG; s++) PH.chunkEnd[s] = c;
        PH.src[0] = headt; PH.srcOff[0] = 0; PH.dstOff[0] = OFF_HD; PH.mode[0] = 0;
        PH.total = c;
        convert_all<<<(PH.total + 255)/256, 256, 0, s2>>>(PH, wh);
        cudaEventRecord(evH, s2);
    }

    pack_scales<<<(180224 + 255)/256, 256>>>(qs_, ks_, vs_, gates, ups, scqkv, scgu);
    embed_kernel<<<NT_, 256>>>(ids, emb_t, emb_s, x);

    dim3 g_qkvp(NT_/128, 3*D_/BN);   // 16 x 24
    dim3 g_op  (NT_/64,  D_/BN);     // 32 x 8  (BM=64)
    dim3 g_gup (NT_/128, 2*DFF_/BN); // 16 x 64
    dim3 g_hd  (NT_/128, V_/BN);     // 16 x 250

    for (int l = 0; l < L_; l++) {
        rmsnorm_kernel<<<NT_, 256>>>(x, wa + (size_t)l*D_, hh);
        cudaStreamWaitEvent(0, evL[l], 0);
        gemm_async<2,4><<<g_qkvp, 128>>>(hh, wh + OFF_QKV + l*3*wDD, scqkv + l*3*sDD,
                                         qkv, NT_, 3*D_, D_);
        attn_mma<<<dim3(S_/AQ, H_, B_), 128>>>(qkv, hh, alpha, oh, l);
        gemm_async<1,2><<<g_op, 128>>>(oh, wh + OFF_O + l*wDD, os_ + l*sDD,
                                       x, NT_, D_, D_);

        rmsnorm_kernel<<<NT_, 256>>>(x, wm + (size_t)l*D_, hh);
        gemm_async<3,4><<<g_gup, 128>>>(hh, wh + OFF_GU + l*2*wFD, scgu + l*2*sFD,
                                        gh, NT_, 2*DFF_, D_);
        gemm_async<1,2><<<g_op, 128>>>(gh, wh + OFF_DN + l*wFD, downs + l*sFD,
                                       x, NT_, D_, DFF_);
    }
    rmsnorm_kernel<<<NT_, 256>>>(x, wf, hh);

    cudaStreamWaitEvent(0, evH, 0);
    gemm_async<0,4><<<g_hd, 128>>>(hh, wh + OFF_HD, heads, out, NT_, V_, D_);
}